// round 11
// baseline (speedup 1.0000x reference)
#include <cuda_runtime.h>
#include <cuda_fp16.h>
#include <cstdint>
#include <math.h>

// ---------------- problem constants ----------------
#define BSZ   16
#define Hh    64
#define Ww    64
#define Cc    512
#define HEADS 16
#define WS    8
#define SHIFT 4
#define Ll    (Hh*Ww)
#define Tt    (BSZ*Ll)     // 65536 tokens
#define HID   2048

// ---------------- scratch (device globals) ----------------
__device__ __half g_qkvh [(size_t)Tt * 1536]; // fp16, GLOBAL token order
__device__ __half g_xh   [(size_t)Tt * Cc];
__device__ __half g_attnh[(size_t)Tt * Cc];   // window order
__device__ float  g_proj [(size_t)Tt * Cc];   // window order
__device__ float  g_x1   [(size_t)Tt * Cc];   // global order
__device__ __half g_x1h  [(size_t)Tt * Cc];
__device__ __half g_hid  [(size_t)Tt * HID];
__device__ float  g_mlp  [(size_t)Tt * Cc];
__device__ float  g_tbl  [225 * HEADS];
__device__ float  g_cmb  [64 * 16 * 4096];    // combined bias+mask fp32 [w][h][i*64+j], 16MB
__device__ __half g_wqkv [1536 * 512];
__device__ __half g_wproj[512 * 512];
__device__ __half g_wfc1 [2048 * 512];
__device__ __half g_wfc2 [512 * 2048];

// ---------------- helpers ----------------
__device__ __forceinline__ void mma16(float* d, const uint32_t* a, uint32_t b0, uint32_t b1) {
    asm volatile(
        "mma.sync.aligned.m16n8k16.row.col.f32.f16.f16.f32 "
        "{%0,%1,%2,%3}, {%4,%5,%6,%7}, {%8,%9}, {%0,%1,%2,%3};\n"
        : "+f"(d[0]), "+f"(d[1]), "+f"(d[2]), "+f"(d[3])
        : "r"(a[0]), "r"(a[1]), "r"(a[2]), "r"(a[3]), "r"(b0), "r"(b1));
}
__device__ __forceinline__ void ldsm4(uint32_t* r, uint32_t addr) {
    asm volatile("ldmatrix.sync.aligned.m8n8.x4.shared.b16 {%0,%1,%2,%3}, [%4];"
                 : "=r"(r[0]), "=r"(r[1]), "=r"(r[2]), "=r"(r[3]) : "r"(addr));
}
__device__ __forceinline__ void ldsm4t(uint32_t* r, uint32_t addr) {
    asm volatile("ldmatrix.sync.aligned.m8n8.x4.trans.shared.b16 {%0,%1,%2,%3}, [%4];"
                 : "=r"(r[0]), "=r"(r[1]), "=r"(r[2]), "=r"(r[3]) : "r"(addr));
}
__device__ __forceinline__ void cpasync16(uint32_t dst, const void* src) {
    asm volatile("cp.async.cg.shared.global [%0], [%1], 16;" :: "r"(dst), "l"(src) : "memory");
}
__device__ __forceinline__ uint32_t smem_u32(const void* p) {
    uint32_t a;
    asm("{ .reg .u64 t; cvta.to.shared.u64 t, %1; cvt.u32.u64 %0, t; }" : "=r"(a) : "l"(p));
    return a;
}
__device__ __forceinline__ uint32_t packh2(float a, float b) {
    __half2 h = __floats2half2_rn(a, b);
    return *(uint32_t*)&h;
}

// window-token index -> global token index
__device__ __forceinline__ int win2glob(int m) {
    int bw = m >> 6, n = m & 63;
    int b = bw >> 6, w = bw & 63;
    int y = (((w >> 3) << 3) + (n >> 3) + SHIFT) & 63;
    int x = (((w & 7) << 3) + (n & 7) + SHIFT) & 63;
    return (b << 12) | (y << 6) | x;
}

// ---------------- epilogue functors: pair interface, vectorized stores ----------------
struct EpiQKVh {
    __half* out; const float* qb; const float* vb; int cbase;
    __device__ __forceinline__ void operator()(int m, int c, float v0, float v1) const {
        int cc = c + cbase;
        if (cc < 512)       { v0 += qb[cc]; v1 += qb[cc + 1]; }
        else if (cc >= 1024){ v0 += vb[cc - 1024]; v1 += vb[cc - 1023]; }
        *(__half2*)(out + (size_t)m * 1536 + cc) = __floats2half2_rn(v0, v1);
    }
};
struct EpiBias {
    float* out; const float* b; int ldc;
    __device__ __forceinline__ void operator()(int m, int c, float v0, float v1) const {
        float2 r; r.x = v0 + b[c]; r.y = v1 + b[c + 1];
        *(float2*)(out + (size_t)m * ldc + c) = r;
    }
};
struct EpiGelu {
    __half* out; const float* b;
    __device__ __forceinline__ void operator()(int m, int c, float v0, float v1) const {
        v0 += b[c];     v0 = 0.5f * v0 * (1.0f + erff(v0 * 0.70710678118654752f));
        v1 += b[c + 1]; v1 = 0.5f * v1 * (1.0f + erff(v1 * 0.70710678118654752f));
        *(__half2*)(out + (size_t)m * HID + c) = __floats2half2_rn(v0, v1);
    }
};

// ---------------- fp16 mma.sync GEMM: 128x256 tile, 512 threads, 3-stage cp.async,
// ---------------- register-fragment double buffering ----------------
#define BKk     64
#define STG_A   (128 * BKk * 2)            // 16384 B
#define STG_B   (256 * BKk * 2)            // 32768 B
#define STG     (STG_A + STG_B)            // 49152 B
#define GSMEM   (3 * STG)                  // 147456 B

template <int K, class Epi>
__global__ __launch_bounds__(512, 1)
void gemm_ca(const __half* __restrict__ A, const __half* __restrict__ B, Epi epi) {
    extern __shared__ __align__(16) char sm[];
    const uint32_t smBase = smem_u32(sm);

    const int tid  = threadIdx.x;
    const int lane = tid & 31, warp = tid >> 5;      // 16 warps
    const int gid  = lane >> 2, tig = lane & 3;
    const int lrow = lane & 15, lk = lane >> 4;
    const int wm   = warp >> 2, wn = warp & 3;        // 4 x 4
    const int m0   = blockIdx.y << 7;                 // 128-row tile
    const int n0   = blockIdx.x << 8;                 // 256-col tile
    const int NT   = K / BKk;

    // cp.async descriptors: A 1024 units -> 2/thread; B 2048 units -> 4/thread
    uint32_t aOff[2], sDstA[2];
#pragma unroll
    for (int i = 0; i < 2; i++) {
        int u = tid * 2 + i, r = u >> 3, c = u & 7;
        aOff[i]  = (uint32_t)(m0 + r) * (uint32_t)K + (uint32_t)(c * 8);
        sDstA[i] = (uint32_t)((r * 8 + (c ^ (r & 7))) * 16);
    }
    uint32_t bOff[4], sDstB[4];
#pragma unroll
    for (int i = 0; i < 4; i++) {
        int u = tid * 4 + i, r = u >> 3, c = u & 7;
        bOff[i]  = (uint32_t)(n0 + r) * (uint32_t)K + (uint32_t)(c * 8);
        sDstB[i] = (uint32_t)(STG_A + (r * 8 + (c ^ (r & 7))) * 16);
    }

    int aR8[2], aSW[2], bR8[4], bSW[4];
#pragma unroll
    for (int t = 0; t < 2; t++) {
        int r = wm * 32 + t * 16 + lrow;
        aR8[t] = r * 8; aSW[t] = r & 7;
    }
#pragma unroll
    for (int t = 0; t < 4; t++) {
        int r = wn * 64 + t * 16 + lrow;
        bR8[t] = r * 8; bSW[t] = r & 7;
    }

    float acc[2][8][4];
#pragma unroll
    for (int i = 0; i < 2; i++)
#pragma unroll
        for (int j = 0; j < 8; j++)
#pragma unroll
            for (int k = 0; k < 4; k++) acc[i][j][k] = 0.f;

    auto load_tile = [&](int s, int kt) {
        uint32_t base = smBase + s * STG;
        uint32_t ko = (uint32_t)(kt * BKk);
#pragma unroll
        for (int i = 0; i < 2; i++) cpasync16(base + sDstA[i], A + aOff[i] + ko);
#pragma unroll
        for (int i = 0; i < 4; i++) cpasync16(base + sDstB[i], B + bOff[i] + ko);
    };

    load_tile(0, 0);
    asm volatile("cp.async.commit_group;" ::: "memory");
    load_tile(1, 1);
    asm volatile("cp.async.commit_group;" ::: "memory");

    // double-buffered register fragments
    uint32_t af[2][2][4], bf[2][4][4];

    for (int kt = 0; kt < NT; kt++) {
        const int s = kt % 3;
        asm volatile("cp.async.wait_group 1;" ::: "memory");
        __syncthreads();
        if (kt + 2 < NT) load_tile((kt + 2) % 3, kt + 2);
        asm volatile("cp.async.commit_group;" ::: "memory");

        uint32_t sA = smBase + s * STG;
        uint32_t sB = sA + STG_A;

        // prime ks=0 fragments
#pragma unroll
        for (int mt = 0; mt < 2; mt++)
            ldsm4(af[0][mt], sA + (uint32_t)((aR8[mt] + (lk ^ aSW[mt])) * 16));
#pragma unroll
        for (int nt = 0; nt < 4; nt++)
            ldsm4(bf[0][nt], sB + (uint32_t)((bR8[nt] + (lk ^ bSW[nt])) * 16));

#pragma unroll
        for (int ks = 0; ks < 4; ks++) {
            const int cur = ks & 1, nxt = cur ^ 1;
            if (ks < 3) {   // prefetch ks+1 fragments before issuing MMAs of ks
#pragma unroll
                for (int mt = 0; mt < 2; mt++)
                    ldsm4(af[nxt][mt], sA + (uint32_t)((aR8[mt] + (((ks + 1) * 2 + lk) ^ aSW[mt])) * 16));
#pragma unroll
                for (int nt = 0; nt < 4; nt++)
                    ldsm4(bf[nxt][nt], sB + (uint32_t)((bR8[nt] + (((ks + 1) * 2 + lk) ^ bSW[nt])) * 16));
            }
#pragma unroll
            for (int mt = 0; mt < 2; mt++)
#pragma unroll
                for (int n8 = 0; n8 < 8; n8++)
                    mma16(acc[mt][n8], af[cur][mt],
                          bf[cur][n8 >> 1][n8 & 1], bf[cur][n8 >> 1][(n8 & 1) + 2]);
        }
    }

    // epilogue: vectorized pair stores
#pragma unroll
    for (int mt = 0; mt < 2; mt++)
#pragma unroll
        for (int n8 = 0; n8 < 8; n8++) {
            int r = m0 + wm * 32 + mt * 16 + gid;
            int c = n0 + wn * 64 + n8 * 8 + tig * 2;
            epi(r,     c, acc[mt][n8][0], acc[mt][n8][1]);
            epi(r + 8, c, acc[mt][n8][2], acc[mt][n8][3]);
        }
}

// ---------------- fp32 -> fp16 convert ----------------
__global__ __launch_bounds__(256)
void cvt_f2h(const float* __restrict__ src, __half* __restrict__ dst, int n) {
    int i = (blockIdx.x * 256 + threadIdx.x) * 4;
    if (i < n) {
        float4 v = *(const float4*)(src + i);
        __half2 a = __floats2half2_rn(v.x, v.y);
        __half2 b = __floats2half2_rn(v.z, v.w);
        uint2 u; u.x = *(uint32_t*)&a; u.y = *(uint32_t*)&b;
        *(uint2*)(dst + i) = u;
    }
}

// ---------------- CPB MLP ----------------
__global__ __launch_bounds__(512) void cpb_kernel(const float* __restrict__ ct,
                                                  const float* __restrict__ w1,
                                                  const float* __restrict__ b1,
                                                  const float* __restrict__ w2) {
    __shared__ float hid[512];
    int p = blockIdx.x;
    float c0 = ct[p * 2 + 0], c1 = ct[p * 2 + 1];
    int t = threadIdx.x;
    hid[t] = fmaxf(c0 * w1[t * 2 + 0] + c1 * w1[t * 2 + 1] + b1[t], 0.f);
    __syncthreads();
    int lane = t & 31, h = t >> 5;
    float s = 0.f;
    for (int k = lane; k < 512; k += 32) s += w2[h * 512 + k] * hid[k];
#pragma unroll
    for (int o = 16; o; o >>= 1) s += __shfl_xor_sync(0xffffffffu, s, o);
    if (lane == 0) g_tbl[p * 16 + h] = 16.0f / (1.0f + __expf(-s));
}

// ---------------- combined bias+mask table: cmb[w][h][ij] (fp32) ----------------
__global__ __launch_bounds__(256)
void cmb_kernel(const int* __restrict__ rpi, const float* __restrict__ am) {
    int wh = blockIdx.x;          // w*16 + h
    int w = wh >> 4, h = wh & 15;
#pragma unroll
    for (int e = 0; e < 16; e++) {
        int ij = threadIdx.x + e * 256;
        g_cmb[((size_t)wh << 12) + ij] = g_tbl[rpi[ij] * 16 + h] + am[(size_t)w * 4096 + ij];
    }
}

// ---------------- attention: tensor-core, one CTA per (window-batch, head) ----------------
__global__ __launch_bounds__(128)
void attn_mma(const __half* __restrict__ qkv, const float* __restrict__ ls,
              __half* __restrict__ outp) {
    __shared__ __align__(16) __half sQ[64][40];
    __shared__ __align__(16) __half sK[64][40];
    __shared__ __align__(16) __half sV[64][40];
    __shared__ float sRq[64];
    __shared__ float sRk[64];

    const int bw = blockIdx.x, h = blockIdx.y;
    const int tid = threadIdx.x;
    const int lane = tid & 31, warp = tid >> 5;
    const int gid = lane >> 2, tig = lane & 3;
    const int lrow = lane & 15, lk = lane >> 4;

#pragma unroll
    for (int i = 0; i < 2; i++) {
        int u = tid * 2 + i;
        int r = u >> 2, c = u & 3;
        int g = win2glob(bw * 64 + r);
        const __half* src = qkv + (size_t)g * 1536 + h * 32 + c * 8;
        *(uint4*)&sQ[r][c * 8] = *(const uint4*)(src);
        *(uint4*)&sK[r][c * 8] = *(const uint4*)(src + 512);
        *(uint4*)&sV[r][c * 8] = *(const uint4*)(src + 1024);
    }
    __syncthreads();

    const float scale = __expf(fminf(ls[h], 4.6051701859880914f));

    {
        int r = tid >> 1, seg = (tid & 1) * 16;
        float sq = 0.f, sk = 0.f;
#pragma unroll
        for (int d = 0; d < 16; d++) {
            float qv = __half2float(sQ[r][seg + d]);
            float kv = __half2float(sK[r][seg + d]);
            sq += qv * qv;
            sk += kv * kv;
        }
        sq += __shfl_xor_sync(0xffffffffu, sq, 1);
        sk += __shfl_xor_sync(0xffffffffu, sk, 1);
        if ((tid & 1) == 0) {
            sRq[r] = scale / fmaxf(sqrtf(sq), 1e-12f);
            sRk[r] = 1.0f  / fmaxf(sqrtf(sk), 1e-12f);
        }
    }
    __syncthreads();

    const uint32_t qB = smem_u32(&sQ[0][0]);
    const uint32_t kB = smem_u32(&sK[0][0]);
    const uint32_t vB = smem_u32(&sV[0][0]);

    float accS[8][4];
#pragma unroll
    for (int j = 0; j < 8; j++)
#pragma unroll
        for (int k = 0; k < 4; k++) accS[j][k] = 0.f;

#pragma unroll
    for (int ks = 0; ks < 2; ks++) {
        uint32_t a[4], b[4][4];
        ldsm4(a, qB + (uint32_t)(((warp * 16 + lrow) * 40 + ks * 16 + lk * 8) * 2));
#pragma unroll
        for (int nt = 0; nt < 4; nt++)
            ldsm4(b[nt], kB + (uint32_t)(((nt * 16 + lrow) * 40 + ks * 16 + lk * 8) * 2));
#pragma unroll
        for (int n8 = 0; n8 < 8; n8++)
            mma16(accS[n8], a, b[n8 >> 1][n8 & 1], b[n8 >> 1][(n8 & 1) + 2]);
    }

    const int w = bw & 63;
    const float* cmbF = g_cmb + (((size_t)w * 16 + h) << 12);
    const int i0 = warp * 16 + gid;
    const float rq0 = sRq[i0], rq1 = sRq[i0 + 8];
#pragma unroll
    for (int n8 = 0; n8 < 8; n8++) {
        int j = n8 * 8 + tig * 2;
        float rk0 = sRk[j], rk1 = sRk[j + 1];
        float2 b0 = *(const float2*)(cmbF + i0 * 64 + j);
        float2 b1 = *(const float2*)(cmbF + (i0 + 8) * 64 + j);
        accS[n8][0] = accS[n8][0] * rq0 * rk0 + b0.x;
        accS[n8][1] = accS[n8][1] * rq0 * rk1 + b0.y;
        accS[n8][2] = accS[n8][2] * rq1 * rk0 + b1.x;
        accS[n8][3] = accS[n8][3] * rq1 * rk1 + b1.y;
    }

    float m0 = -1e30f, m1 = -1e30f;
#pragma unroll
    for (int n8 = 0; n8 < 8; n8++) {
        m0 = fmaxf(m0, fmaxf(accS[n8][0], accS[n8][1]));
        m1 = fmaxf(m1, fmaxf(accS[n8][2], accS[n8][3]));
    }
    m0 = fmaxf(m0, __shfl_xor_sync(0xffffffffu, m0, 1));
    m0 = fmaxf(m0, __shfl_xor_sync(0xffffffffu, m0, 2));
    m1 = fmaxf(m1, __shfl_xor_sync(0xffffffffu, m1, 1));
    m1 = fmaxf(m1, __shfl_xor_sync(0xffffffffu, m1, 2));
    float s0 = 0.f, s1 = 0.f;
#pragma unroll
    for (int n8 = 0; n8 < 8; n8++) {
        accS[n8][0] = __expf(accS[n8][0] - m0); s0 += accS[n8][0];
        accS[n8][1] = __expf(accS[n8][1] - m0); s0 += accS[n8][1];
        accS[n8][2] = __expf(accS[n8][2] - m1); s1 += accS[n8][2];
        accS[n8][3] = __expf(accS[n8][3] - m1); s1 += accS[n8][3];
    }
    s0 += __shfl_xor_sync(0xffffffffu, s0, 1);
    s0 += __shfl_xor_sync(0xffffffffu, s0, 2);
    s1 += __shfl_xor_sync(0xffffffffu, s1, 1);
    s1 += __shfl_xor_sync(0xffffffffu, s1, 2);
    float r0 = 1.0f / s0, r1 = 1.0f / s1;

    uint32_t pk0[8], pk1[8];
#pragma unroll
    for (int n8 = 0; n8 < 8; n8++) {
        pk0[n8] = packh2(accS[n8][0] * r0, accS[n8][1] * r0);
        pk1[n8] = packh2(accS[n8][2] * r1, accS[n8][3] * r1);
    }

    float accO[4][4];
#pragma unroll
    for (int j = 0; j < 4; j++)
#pragma unroll
        for (int k = 0; k < 4; k++) accO[j][k] = 0.f;

#pragma unroll
    for (int kb = 0; kb < 4; kb++) {
        uint32_t aP[4] = { pk0[2 * kb], pk1[2 * kb], pk0[2 * kb + 1], pk1[2 * kb + 1] };
#pragma unroll
        for (int dt = 0; dt < 2; dt++) {
            uint32_t vb[4];
            int vr = kb * 16 + ((lane >> 4) << 3) + (lane & 7);
            int vc = dt * 16 + ((lane >> 3) & 1) * 8;
            ldsm4t(vb, vB + (uint32_t)((vr * 40 + vc) * 2));
            mma16(accO[2 * dt],     aP, vb[0], vb[2]);
            mma16(accO[2 * dt + 1], aP, vb[1], vb[3]);
        }
    }

#pragma unroll
    for (int n8 = 0; n8 < 4; n8++) {
        int d = n8 * 8 + tig * 2;
        size_t o0 = (size_t)(bw * 64 + i0) * 512 + h * 32 + d;
        __half2 h0 = __floats2half2_rn(accO[n8][0], accO[n8][1]);
        __half2 h1 = __floats2half2_rn(accO[n8][2], accO[n8][3]);
        *(__half2*)(outp + o0)            = h0;
        *(__half2*)(outp + o0 + 8 * 512)  = h1;
    }
}

// ---------------- LayerNorm: warp-per-token, no barriers ----------------
__global__ __launch_bounds__(256)
void ln1_kernel(const float4* __restrict__ proj, const float4* __restrict__ x,
                const float4* __restrict__ gma, const float4* __restrict__ bta,
                float4* __restrict__ x1o, uint2* __restrict__ x1h) {
    const int m = blockIdx.x * 8 + (threadIdx.x >> 5);
    const int lane = threadIdx.x & 31;
    const size_t pb = (size_t)m * 128 + lane;

    float4 v[4];
    float sum = 0.f;
#pragma unroll
    for (int j = 0; j < 4; j++) {
        v[j] = proj[pb + j * 32];
        sum += (v[j].x + v[j].y) + (v[j].z + v[j].w);
    }
#pragma unroll
    for (int o = 16; o; o >>= 1) sum += __shfl_xor_sync(0xffffffffu, sum, o);
    const float mean = sum * (1.0f / 512.0f);

    float vs = 0.f;
#pragma unroll
    for (int j = 0; j < 4; j++) {
        v[j].x -= mean; v[j].y -= mean; v[j].z -= mean; v[j].w -= mean;
        vs += (v[j].x * v[j].x + v[j].y * v[j].y) + (v[j].z * v[j].z + v[j].w * v[j].w);
    }
#pragma unroll
    for (int o = 16; o; o >>= 1) vs += __shfl_xor_sync(0xffffffffu, vs, o);
    const float inv = rsqrtf(vs * (1.0f / 512.0f) + 1e-5f);

    const int g = win2glob(m);
    const size_t gb = (size_t)g * 128 + lane;
#pragma unroll
    for (int j = 0; j < 4; j++) {
        float4 xm = x[gb + j * 32];
        float4 gm = gma[lane + j * 32];
        float4 bt = bta[lane + j * 32];
        float4 r;
        r.x = xm.x + v[j].x * inv * gm.x + bt.x;
        r.y = xm.y + v[j].y * inv * gm.y + bt.y;
        r.z = xm.z + v[j].z * inv * gm.z + bt.z;
        r.w = xm.w + v[j].w * inv * gm.w + bt.w;
        x1o[gb + j * 32] = r;
        uint2 u; u.x = packh2(r.x, r.y); u.y = packh2(r.z, r.w);
        x1h[gb + j * 32] = u;
    }
}

__global__ __launch_bounds__(256)
void ln2_kernel(const float4* __restrict__ mlp, const float4* __restrict__ x1,
                const float4* __restrict__ gma, const float4* __restrict__ bta,
                float4* __restrict__ outp) {
    const int m = blockIdx.x * 8 + (threadIdx.x >> 5);
    const int lane = threadIdx.x & 31;
    const size_t pb = (size_t)m * 128 + lane;

    float4 v[4];
    float sum = 0.f;
#pragma unroll
    for (int j = 0; j < 4; j++) {
        v[j] = mlp[pb + j * 32];
        sum += (v[j].x + v[j].y) + (v[j].z + v[j].w);
    }
#pragma unroll
    for (int o = 16; o; o >>= 1) sum += __shfl_xor_sync(0xffffffffu, sum, o);
    const float mean = sum * (1.0f / 512.0f);

    float vs = 0.f;
#pragma unroll
    for (int j = 0; j < 4; j++) {
        v[j].x -= mean; v[j].y -= mean; v[j].z -= mean; v[j].w -= mean;
        vs += (v[j].x * v[j].x + v[j].y * v[j].y) + (v[j].z * v[j].z + v[j].w * v[j].w);
    }
#pragma unroll
    for (int o = 16; o; o >>= 1) vs += __shfl_xor_sync(0xffffffffu, vs, o);
    const float inv = rsqrtf(vs * (1.0f / 512.0f) + 1e-5f);

#pragma unroll
    for (int j = 0; j < 4; j++) {
        float4 xm = x1[pb + j * 32];
        float4 gm = gma[lane + j * 32];
        float4 bt = bta[lane + j * 32];
        float4 r;
        r.x = xm.x + v[j].x * inv * gm.x + bt.x;
        r.y = xm.y + v[j].y * inv * gm.y + bt.y;
        r.z = xm.z + v[j].z * inv * gm.z + bt.z;
        r.w = xm.w + v[j].w * inv * gm.w + bt.w;
        outp[pb + j * 32] = r;
    }
}

// ---------------- host launcher ----------------
extern "C" void kernel_launch(void* const* d_in, const int* in_sizes, int n_in,
                              void* d_out, int out_size) {
    (void)in_sizes; (void)n_in; (void)out_size;
    const float* x      = (const float*)d_in[0];
    const float* qkv_w  = (const float*)d_in[1];
    const float* q_bias = (const float*)d_in[2];
    const float* v_bias = (const float*)d_in[3];
    const float* lscale = (const float*)d_in[4];
    const float* cpb_w1 = (const float*)d_in[5];
    const float* cpb_b1 = (const float*)d_in[6];
    const float* cpb_w2 = (const float*)d_in[7];
    const float* proj_w = (const float*)d_in[8];
    const float* proj_b = (const float*)d_in[9];
    const float* n1g    = (const float*)d_in[10];
    const float* n1b    = (const float*)d_in[11];
    const float* n2g    = (const float*)d_in[12];
    const float* n2b    = (const float*)d_in[13];
    const float* fc1_w  = (const float*)d_in[14];
    const float* fc1_b  = (const float*)d_in[15];
    const float* fc2_w  = (const float*)d_in[16];
    const float* fc2_b  = (const float*)d_in[17];
    const float* coords = (const float*)d_in[18];
    const float* amask  = (const float*)d_in[19];
    const int*   rpi    = (const int*)d_in[20];
    float*       out    = (float*)d_out;

    float  *p_proj, *p_x1, *p_mlp;
    __half *p_qkv, *p_xh, *p_attnh, *p_x1h, *p_hid, *p_wqkv, *p_wproj, *p_wfc1, *p_wfc2;
    cudaGetSymbolAddress((void**)&p_qkv,   g_qkvh);
    cudaGetSymbolAddress((void**)&p_proj,  g_proj);
    cudaGetSymbolAddress((void**)&p_x1,    g_x1);
    cudaGetSymbolAddress((void**)&p_mlp,   g_mlp);
    cudaGetSymbolAddress((void**)&p_xh,    g_xh);
    cudaGetSymbolAddress((void**)&p_attnh, g_attnh);
    cudaGetSymbolAddress((void**)&p_x1h,   g_x1h);
    cudaGetSymbolAddress((void**)&p_hid,   g_hid);
    cudaGetSymbolAddress((void**)&p_wqkv,  g_wqkv);
    cudaGetSymbolAddress((void**)&p_wproj, g_wproj);
    cudaGetSymbolAddress((void**)&p_wfc1,  g_wfc1);
    cudaGetSymbolAddress((void**)&p_wfc2,  g_wfc2);

    cudaFuncSetAttribute(gemm_ca<512,  EpiQKVh>, cudaFuncAttributeMaxDynamicSharedMemorySize, GSMEM);
    cudaFuncSetAttribute(gemm_ca<512,  EpiBias>, cudaFuncAttributeMaxDynamicSharedMemorySize, GSMEM);
    cudaFuncSetAttribute(gemm_ca<512,  EpiGelu>, cudaFuncAttributeMaxDynamicSharedMemorySize, GSMEM);
    cudaFuncSetAttribute(gemm_ca<2048, EpiBias>, cudaFuncAttributeMaxDynamicSharedMemorySize, GSMEM);

    // 0,1: deps of the QKV GEMM; 2,3: QKV GEMM split so ncu lands on a GEMM.
    cvt_f2h<<<(Tt * 512 / 4 + 255) / 256, 256>>>(x, p_xh, Tt * 512);                 // 0
    cvt_f2h<<<(1536 * 512 / 4 + 255) / 256, 256>>>(qkv_w, p_wqkv, 1536 * 512);       // 1
    gemm_ca<512><<<dim3(3, 512), 512, GSMEM>>>(p_xh, p_wqkv,
        EpiQKVh{p_qkv, q_bias, v_bias, 0});                                          // 2
    gemm_ca<512><<<dim3(3, 512), 512, GSMEM>>>(p_xh, p_wqkv + 768 * 512,
        EpiQKVh{p_qkv, q_bias, v_bias, 768});                                        // 3
    cpb_kernel<<<225, 512>>>(coords, cpb_w1, cpb_b1, cpb_w2);                        // 4
    cmb_kernel<<<1024, 256>>>(rpi, amask);                                           // 5
    attn_mma<<<dim3(1024, 16), 128>>>(p_qkv, lscale, p_attnh);                       // 6
    cvt_f2h<<<(512 * 512 / 4 + 255) / 256, 256>>>(proj_w, p_wproj, 512 * 512);       // 7
    gemm_ca<512><<<dim3(2, 512), 512, GSMEM>>>(p_attnh, p_wproj,
        EpiBias{p_proj, proj_b, 512});                                               // 8
    ln1_kernel<<<Tt / 8, 256>>>((const float4*)p_proj, (const float4*)x,
                                (const float4*)n1g, (const float4*)n1b,
                                (float4*)p_x1, (uint2*)p_x1h);                       // 9
    cvt_f2h<<<(2048 * 512 / 4 + 255) / 256, 256>>>(fc1_w, p_wfc1, 2048 * 512);       // 10
    gemm_ca<512><<<dim3(8, 512), 512, GSMEM>>>(p_x1h, p_wfc1, EpiGelu{p_hid, fc1_b}); // 11
    cvt_f2h<<<(512 * 2048 / 4 + 255) / 256, 256>>>(fc2_w, p_wfc2, 512 * 2048);       // 12
    gemm_ca<2048><<<dim3(2, 512), 512, GSMEM>>>(p_hid, p_wfc2, EpiBias{p_mlp, fc2_b, 512}); // 13
    ln2_kernel<<<Tt / 8, 256>>>((const float4*)p_mlp, (const float4*)p_x1,
                                (const float4*)n2g, (const float4*)n2b,
                                (float4*)out);                                       // 14
}

// round 12
// speedup vs baseline: 1.0180x; 1.0180x over previous
#include <cuda_runtime.h>
#include <cuda_fp16.h>
#include <cstdint>
#include <math.h>

// ---------------- problem constants ----------------
#define BSZ   16
#define Hh    64
#define Ww    64
#define Cc    512
#define HEADS 16
#define WS    8
#define SHIFT 4
#define Ll    (Hh*Ww)
#define Tt    (BSZ*Ll)     // 65536 tokens
#define HID   2048

// ---------------- scratch (device globals) ----------------
__device__ __half g_qkvh [(size_t)Tt * 1536]; // fp16, GLOBAL token order
__device__ __half g_xh   [(size_t)Tt * Cc];
__device__ __half g_attnh[(size_t)Tt * Cc];   // window order
__device__ float  g_proj [(size_t)Tt * Cc];   // window order
__device__ float  g_x1   [(size_t)Tt * Cc];   // global order
__device__ __half g_x1h  [(size_t)Tt * Cc];
__device__ __half g_hid  [(size_t)Tt * HID];
__device__ float  g_mlp  [(size_t)Tt * Cc];
__device__ float  g_tbl  [225 * HEADS];
__device__ float  g_cmb  [64 * 16 * 4096];    // combined bias+mask fp32 [w][h][i*64+j], 16MB
__device__ __half g_wqkv [1536 * 512];
__device__ __half g_wproj[512 * 512];
__device__ __half g_wfc1 [2048 * 512];
__device__ __half g_wfc2 [512 * 2048];

// ---------------- helpers ----------------
__device__ __forceinline__ void mma16(float* d, const uint32_t* a, uint32_t b0, uint32_t b1) {
    asm volatile(
        "mma.sync.aligned.m16n8k16.row.col.f32.f16.f16.f32 "
        "{%0,%1,%2,%3}, {%4,%5,%6,%7}, {%8,%9}, {%0,%1,%2,%3};\n"
        : "+f"(d[0]), "+f"(d[1]), "+f"(d[2]), "+f"(d[3])
        : "r"(a[0]), "r"(a[1]), "r"(a[2]), "r"(a[3]), "r"(b0), "r"(b1));
}
__device__ __forceinline__ void ldsm4(uint32_t* r, uint32_t addr) {
    asm volatile("ldmatrix.sync.aligned.m8n8.x4.shared.b16 {%0,%1,%2,%3}, [%4];"
                 : "=r"(r[0]), "=r"(r[1]), "=r"(r[2]), "=r"(r[3]) : "r"(addr));
}
__device__ __forceinline__ void ldsm4t(uint32_t* r, uint32_t addr) {
    asm volatile("ldmatrix.sync.aligned.m8n8.x4.trans.shared.b16 {%0,%1,%2,%3}, [%4];"
                 : "=r"(r[0]), "=r"(r[1]), "=r"(r[2]), "=r"(r[3]) : "r"(addr));
}
__device__ __forceinline__ void cpasync16(uint32_t dst, const void* src) {
    asm volatile("cp.async.cg.shared.global [%0], [%1], 16;" :: "r"(dst), "l"(src) : "memory");
}
__device__ __forceinline__ uint32_t smem_u32(const void* p) {
    uint32_t a;
    asm("{ .reg .u64 t; cvta.to.shared.u64 t, %1; cvt.u32.u64 %0, t; }" : "=r"(a) : "l"(p));
    return a;
}
__device__ __forceinline__ uint32_t packh2(float a, float b) {
    __half2 h = __floats2half2_rn(a, b);
    return *(uint32_t*)&h;
}

// window-token index -> global token index
__device__ __forceinline__ int win2glob(int m) {
    int bw = m >> 6, n = m & 63;
    int b = bw >> 6, w = bw & 63;
    int y = (((w >> 3) << 3) + (n >> 3) + SHIFT) & 63;
    int x = (((w & 7) << 3) + (n & 7) + SHIFT) & 63;
    return (b << 12) | (y << 6) | x;
}

// ---------------- epilogue functors: pair interface, vectorized stores ----------------
struct EpiQKVh {
    __half* out; const float* qb; const float* vb; int cbase;
    __device__ __forceinline__ void operator()(int m, int c, float v0, float v1) const {
        int cc = c + cbase;
        if (cc < 512)       { v0 += qb[cc]; v1 += qb[cc + 1]; }
        else if (cc >= 1024){ v0 += vb[cc - 1024]; v1 += vb[cc - 1023]; }
        *(__half2*)(out + (size_t)m * 1536 + cc) = __floats2half2_rn(v0, v1);
    }
};
struct EpiBias {
    float* out; const float* b; int ldc;
    __device__ __forceinline__ void operator()(int m, int c, float v0, float v1) const {
        float2 r; r.x = v0 + b[c]; r.y = v1 + b[c + 1];
        *(float2*)(out + (size_t)m * ldc + c) = r;
    }
};
struct EpiGelu {
    __half* out; const float* b;
    __device__ __forceinline__ void operator()(int m, int c, float v0, float v1) const {
        v0 += b[c];     v0 = 0.5f * v0 * (1.0f + erff(v0 * 0.70710678118654752f));
        v1 += b[c + 1]; v1 = 0.5f * v1 * (1.0f + erff(v1 * 0.70710678118654752f));
        *(__half2*)(out + (size_t)m * HID + c) = __floats2half2_rn(v0, v1);
    }
};

// ---------------- fp16 mma.sync GEMM: 128x256 tile, 512 threads, 4-stage cp.async ----------------
#define BKk     64
#define STG_A   (128 * BKk * 2)            // 16384 B
#define STG_B   (256 * BKk * 2)            // 32768 B
#define STG     (STG_A + STG_B)            // 49152 B
#define NSTAGE  4
#define GSMEM   (NSTAGE * STG)             // 196608 B

template <int K, class Epi>
__global__ __launch_bounds__(512, 1)
void gemm_ca(const __half* __restrict__ A, const __half* __restrict__ B, Epi epi) {
    extern __shared__ __align__(16) char sm[];
    const uint32_t smBase = smem_u32(sm);

    const int tid  = threadIdx.x;
    const int lane = tid & 31, warp = tid >> 5;      // 16 warps
    const int gid  = lane >> 2, tig = lane & 3;
    const int lrow = lane & 15, lk = lane >> 4;
    const int wm   = warp >> 2, wn = warp & 3;        // 4 x 4
    const int m0   = blockIdx.y << 7;                 // 128-row tile
    const int n0   = blockIdx.x << 8;                 // 256-col tile
    const int NT   = K / BKk;

    // cp.async descriptors: A 1024 units -> 2/thread; B 2048 units -> 4/thread
    uint32_t aOff[2], sDstA[2];
#pragma unroll
    for (int i = 0; i < 2; i++) {
        int u = tid * 2 + i, r = u >> 3, c = u & 7;
        aOff[i]  = (uint32_t)(m0 + r) * (uint32_t)K + (uint32_t)(c * 8);
        sDstA[i] = (uint32_t)((r * 8 + (c ^ (r & 7))) * 16);
    }
    uint32_t bOff[4], sDstB[4];
#pragma unroll
    for (int i = 0; i < 4; i++) {
        int u = tid * 4 + i, r = u >> 3, c = u & 7;
        bOff[i]  = (uint32_t)(n0 + r) * (uint32_t)K + (uint32_t)(c * 8);
        sDstB[i] = (uint32_t)(STG_A + (r * 8 + (c ^ (r & 7))) * 16);
    }

    int aR8[2], aSW[2], bR8[4], bSW[4];
#pragma unroll
    for (int t = 0; t < 2; t++) {
        int r = wm * 32 + t * 16 + lrow;
        aR8[t] = r * 8; aSW[t] = r & 7;
    }
#pragma unroll
    for (int t = 0; t < 4; t++) {
        int r = wn * 64 + t * 16 + lrow;
        bR8[t] = r * 8; bSW[t] = r & 7;
    }

    float acc[2][8][4];
#pragma unroll
    for (int i = 0; i < 2; i++)
#pragma unroll
        for (int j = 0; j < 8; j++)
#pragma unroll
            for (int k = 0; k < 4; k++) acc[i][j][k] = 0.f;

    auto load_tile = [&](int s, int kt) {
        uint32_t base = smBase + s * STG;
        uint32_t ko = (uint32_t)(kt * BKk);
#pragma unroll
        for (int i = 0; i < 2; i++) cpasync16(base + sDstA[i], A + aOff[i] + ko);
#pragma unroll
        for (int i = 0; i < 4; i++) cpasync16(base + sDstB[i], B + bOff[i] + ko);
    };

    // prologue: 3 tiles in flight
    load_tile(0, 0);
    asm volatile("cp.async.commit_group;" ::: "memory");
    load_tile(1, 1);
    asm volatile("cp.async.commit_group;" ::: "memory");
    load_tile(2, 2);
    asm volatile("cp.async.commit_group;" ::: "memory");

    for (int kt = 0; kt < NT; kt++) {
        const int s = kt % NSTAGE;
        asm volatile("cp.async.wait_group 2;" ::: "memory");
        __syncthreads();
        if (kt + 3 < NT) load_tile((kt + 3) % NSTAGE, kt + 3);
        asm volatile("cp.async.commit_group;" ::: "memory");

        uint32_t sA = smBase + s * STG;
        uint32_t sB = sA + STG_A;
#pragma unroll
        for (int ks = 0; ks < 4; ks++) {
            uint32_t a[2][4], b[4][4];
#pragma unroll
            for (int mt = 0; mt < 2; mt++)
                ldsm4(a[mt], sA + (uint32_t)((aR8[mt] + ((ks * 2 + lk) ^ aSW[mt])) * 16));
#pragma unroll
            for (int nt = 0; nt < 4; nt++)
                ldsm4(b[nt], sB + (uint32_t)((bR8[nt] + ((ks * 2 + lk) ^ bSW[nt])) * 16));
#pragma unroll
            for (int mt = 0; mt < 2; mt++)
#pragma unroll
                for (int n8 = 0; n8 < 8; n8++)
                    mma16(acc[mt][n8], a[mt], b[n8 >> 1][n8 & 1], b[n8 >> 1][(n8 & 1) + 2]);
        }
    }

    // epilogue: vectorized pair stores
#pragma unroll
    for (int mt = 0; mt < 2; mt++)
#pragma unroll
        for (int n8 = 0; n8 < 8; n8++) {
            int r = m0 + wm * 32 + mt * 16 + gid;
            int c = n0 + wn * 64 + n8 * 8 + tig * 2;
            epi(r,     c, acc[mt][n8][0], acc[mt][n8][1]);
            epi(r + 8, c, acc[mt][n8][2], acc[mt][n8][3]);
        }
}

// ---------------- fp32 -> fp16 convert ----------------
__global__ __launch_bounds__(256)
void cvt_f2h(const float* __restrict__ src, __half* __restrict__ dst, int n) {
    int i = (blockIdx.x * 256 + threadIdx.x) * 4;
    if (i < n) {
        float4 v = *(const float4*)(src + i);
        __half2 a = __floats2half2_rn(v.x, v.y);
        __half2 b = __floats2half2_rn(v.z, v.w);
        uint2 u; u.x = *(uint32_t*)&a; u.y = *(uint32_t*)&b;
        *(uint2*)(dst + i) = u;
    }
}

// ---------------- CPB MLP ----------------
__global__ __launch_bounds__(512) void cpb_kernel(const float* __restrict__ ct,
                                                  const float* __restrict__ w1,
                                                  const float* __restrict__ b1,
                                                  const float* __restrict__ w2) {
    __shared__ float hid[512];
    int p = blockIdx.x;
    float c0 = ct[p * 2 + 0], c1 = ct[p * 2 + 1];
    int t = threadIdx.x;
    hid[t] = fmaxf(c0 * w1[t * 2 + 0] + c1 * w1[t * 2 + 1] + b1[t], 0.f);
    __syncthreads();
    int lane = t & 31, h = t >> 5;
    float s = 0.f;
    for (int k = lane; k < 512; k += 32) s += w2[h * 512 + k] * hid[k];
#pragma unroll
    for (int o = 16; o; o >>= 1) s += __shfl_xor_sync(0xffffffffu, s, o);
    if (lane == 0) g_tbl[p * 16 + h] = 16.0f / (1.0f + __expf(-s));
}

// ---------------- combined bias+mask table: cmb[w][h][ij] (fp32) ----------------
__global__ __launch_bounds__(256)
void cmb_kernel(const int* __restrict__ rpi, const float* __restrict__ am) {
    int wh = blockIdx.x;          // w*16 + h
    int w = wh >> 4, h = wh & 15;
#pragma unroll
    for (int e = 0; e < 16; e++) {
        int ij = threadIdx.x + e * 256;
        g_cmb[((size_t)wh << 12) + ij] = g_tbl[rpi[ij] * 16 + h] + am[(size_t)w * 4096 + ij];
    }
}

// ---------------- attention: tensor-core, one CTA per (window-batch, head) ----------------
__global__ __launch_bounds__(128)
void attn_mma(const __half* __restrict__ qkv, const float* __restrict__ ls,
              __half* __restrict__ outp) {
    __shared__ __align__(16) __half sQ[64][40];
    __shared__ __align__(16) __half sK[64][40];
    __shared__ __align__(16) __half sV[64][40];
    __shared__ float sRq[64];
    __shared__ float sRk[64];

    const int bw = blockIdx.x, h = blockIdx.y;
    const int tid = threadIdx.x;
    const int lane = tid & 31, warp = tid >> 5;
    const int gid = lane >> 2, tig = lane & 3;
    const int lrow = lane & 15, lk = lane >> 4;

#pragma unroll
    for (int i = 0; i < 2; i++) {
        int u = tid * 2 + i;
        int r = u >> 2, c = u & 3;
        int g = win2glob(bw * 64 + r);
        const __half* src = qkv + (size_t)g * 1536 + h * 32 + c * 8;
        *(uint4*)&sQ[r][c * 8] = *(const uint4*)(src);
        *(uint4*)&sK[r][c * 8] = *(const uint4*)(src + 512);
        *(uint4*)&sV[r][c * 8] = *(const uint4*)(src + 1024);
    }
    __syncthreads();

    const float scale = __expf(fminf(ls[h], 4.6051701859880914f));

    {
        int r = tid >> 1, seg = (tid & 1) * 16;
        float sq = 0.f, sk = 0.f;
#pragma unroll
        for (int d = 0; d < 16; d++) {
            float qv = __half2float(sQ[r][seg + d]);
            float kv = __half2float(sK[r][seg + d]);
            sq += qv * qv;
            sk += kv * kv;
        }
        sq += __shfl_xor_sync(0xffffffffu, sq, 1);
        sk += __shfl_xor_sync(0xffffffffu, sk, 1);
        if ((tid & 1) == 0) {
            sRq[r] = scale / fmaxf(sqrtf(sq), 1e-12f);
            sRk[r] = 1.0f  / fmaxf(sqrtf(sk), 1e-12f);
        }
    }
    __syncthreads();

    const uint32_t qB = smem_u32(&sQ[0][0]);
    const uint32_t kB = smem_u32(&sK[0][0]);
    const uint32_t vB = smem_u32(&sV[0][0]);

    float accS[8][4];
#pragma unroll
    for (int j = 0; j < 8; j++)
#pragma unroll
        for (int k = 0; k < 4; k++) accS[j][k] = 0.f;

#pragma unroll
    for (int ks = 0; ks < 2; ks++) {
        uint32_t a[4], b[4][4];
        ldsm4(a, qB + (uint32_t)(((warp * 16 + lrow) * 40 + ks * 16 + lk * 8) * 2));
#pragma unroll
        for (int nt = 0; nt < 4; nt++)
            ldsm4(b[nt], kB + (uint32_t)(((nt * 16 + lrow) * 40 + ks * 16 + lk * 8) * 2));
#pragma unroll
        for (int n8 = 0; n8 < 8; n8++)
            mma16(accS[n8], a, b[n8 >> 1][n8 & 1], b[n8 >> 1][(n8 & 1) + 2]);
    }

    const int w = bw & 63;
    const float* cmbF = g_cmb + (((size_t)w * 16 + h) << 12);
    const int i0 = warp * 16 + gid;
    const float rq0 = sRq[i0], rq1 = sRq[i0 + 8];
#pragma unroll
    for (int n8 = 0; n8 < 8; n8++) {
        int j = n8 * 8 + tig * 2;
        float rk0 = sRk[j], rk1 = sRk[j + 1];
        float2 b0 = *(const float2*)(cmbF + i0 * 64 + j);
        float2 b1 = *(const float2*)(cmbF + (i0 + 8) * 64 + j);
        accS[n8][0] = accS[n8][0] * rq0 * rk0 + b0.x;
        accS[n8][1] = accS[n8][1] * rq0 * rk1 + b0.y;
        accS[n8][2] = accS[n8][2] * rq1 * rk0 + b1.x;
        accS[n8][3] = accS[n8][3] * rq1 * rk1 + b1.y;
    }

    float m0 = -1e30f, m1 = -1e30f;
#pragma unroll
    for (int n8 = 0; n8 < 8; n8++) {
        m0 = fmaxf(m0, fmaxf(accS[n8][0], accS[n8][1]));
        m1 = fmaxf(m1, fmaxf(accS[n8][2], accS[n8][3]));
    }
    m0 = fmaxf(m0, __shfl_xor_sync(0xffffffffu, m0, 1));
    m0 = fmaxf(m0, __shfl_xor_sync(0xffffffffu, m0, 2));
    m1 = fmaxf(m1, __shfl_xor_sync(0xffffffffu, m1, 1));
    m1 = fmaxf(m1, __shfl_xor_sync(0xffffffffu, m1, 2));
    float s0 = 0.f, s1 = 0.f;
#pragma unroll
    for (int n8 = 0; n8 < 8; n8++) {
        accS[n8][0] = __expf(accS[n8][0] - m0); s0 += accS[n8][0];
        accS[n8][1] = __expf(accS[n8][1] - m0); s0 += accS[n8][1];
        accS[n8][2] = __expf(accS[n8][2] - m1); s1 += accS[n8][2];
        accS[n8][3] = __expf(accS[n8][3] - m1); s1 += accS[n8][3];
    }
    s0 += __shfl_xor_sync(0xffffffffu, s0, 1);
    s0 += __shfl_xor_sync(0xffffffffu, s0, 2);
    s1 += __shfl_xor_sync(0xffffffffu, s1, 1);
    s1 += __shfl_xor_sync(0xffffffffu, s1, 2);
    float r0 = 1.0f / s0, r1 = 1.0f / s1;

    uint32_t pk0[8], pk1[8];
#pragma unroll
    for (int n8 = 0; n8 < 8; n8++) {
        pk0[n8] = packh2(accS[n8][0] * r0, accS[n8][1] * r0);
        pk1[n8] = packh2(accS[n8][2] * r1, accS[n8][3] * r1);
    }

    float accO[4][4];
#pragma unroll
    for (int j = 0; j < 4; j++)
#pragma unroll
        for (int k = 0; k < 4; k++) accO[j][k] = 0.f;

#pragma unroll
    for (int kb = 0; kb < 4; kb++) {
        uint32_t aP[4] = { pk0[2 * kb], pk1[2 * kb], pk0[2 * kb + 1], pk1[2 * kb + 1] };
#pragma unroll
        for (int dt = 0; dt < 2; dt++) {
            uint32_t vb[4];
            int vr = kb * 16 + ((lane >> 4) << 3) + (lane & 7);
            int vc = dt * 16 + ((lane >> 3) & 1) * 8;
            ldsm4t(vb, vB + (uint32_t)((vr * 40 + vc) * 2));
            mma16(accO[2 * dt],     aP, vb[0], vb[2]);
            mma16(accO[2 * dt + 1], aP, vb[1], vb[3]);
        }
    }

#pragma unroll
    for (int n8 = 0; n8 < 4; n8++) {
        int d = n8 * 8 + tig * 2;
        size_t o0 = (size_t)(bw * 64 + i0) * 512 + h * 32 + d;
        __half2 h0 = __floats2half2_rn(accO[n8][0], accO[n8][1]);
        __half2 h1 = __floats2half2_rn(accO[n8][2], accO[n8][3]);
        *(__half2*)(outp + o0)            = h0;
        *(__half2*)(outp + o0 + 8 * 512)  = h1;
    }
}

// ---------------- LayerNorm: warp-per-token, no barriers ----------------
__global__ __launch_bounds__(256)
void ln1_kernel(const float4* __restrict__ proj, const float4* __restrict__ x,
                const float4* __restrict__ gma, const float4* __restrict__ bta,
                float4* __restrict__ x1o, uint2* __restrict__ x1h) {
    const int m = blockIdx.x * 8 + (threadIdx.x >> 5);
    const int lane = threadIdx.x & 31;
    const size_t pb = (size_t)m * 128 + lane;

    float4 v[4];
    float sum = 0.f;
#pragma unroll
    for (int j = 0; j < 4; j++) {
        v[j] = proj[pb + j * 32];
        sum += (v[j].x + v[j].y) + (v[j].z + v[j].w);
    }
#pragma unroll
    for (int o = 16; o; o >>= 1) sum += __shfl_xor_sync(0xffffffffu, sum, o);
    const float mean = sum * (1.0f / 512.0f);

    float vs = 0.f;
#pragma unroll
    for (int j = 0; j < 4; j++) {
        v[j].x -= mean; v[j].y -= mean; v[j].z -= mean; v[j].w -= mean;
        vs += (v[j].x * v[j].x + v[j].y * v[j].y) + (v[j].z * v[j].z + v[j].w * v[j].w);
    }
#pragma unroll
    for (int o = 16; o; o >>= 1) vs += __shfl_xor_sync(0xffffffffu, vs, o);
    const float inv = rsqrtf(vs * (1.0f / 512.0f) + 1e-5f);

    const int g = win2glob(m);
    const size_t gb = (size_t)g * 128 + lane;
#pragma unroll
    for (int j = 0; j < 4; j++) {
        float4 xm = x[gb + j * 32];
        float4 gm = gma[lane + j * 32];
        float4 bt = bta[lane + j * 32];
        float4 r;
        r.x = xm.x + v[j].x * inv * gm.x + bt.x;
        r.y = xm.y + v[j].y * inv * gm.y + bt.y;
        r.z = xm.z + v[j].z * inv * gm.z + bt.z;
        r.w = xm.w + v[j].w * inv * gm.w + bt.w;
        x1o[gb + j * 32] = r;
        uint2 u; u.x = packh2(r.x, r.y); u.y = packh2(r.z, r.w);
        x1h[gb + j * 32] = u;
    }
}

__global__ __launch_bounds__(256)
void ln2_kernel(const float4* __restrict__ mlp, const float4* __restrict__ x1,
                const float4* __restrict__ gma, const float4* __restrict__ bta,
                float4* __restrict__ outp) {
    const int m = blockIdx.x * 8 + (threadIdx.x >> 5);
    const int lane = threadIdx.x & 31;
    const size_t pb = (size_t)m * 128 + lane;

    float4 v[4];
    float sum = 0.f;
#pragma unroll
    for (int j = 0; j < 4; j++) {
        v[j] = mlp[pb + j * 32];
        sum += (v[j].x + v[j].y) + (v[j].z + v[j].w);
    }
#pragma unroll
    for (int o = 16; o; o >>= 1) sum += __shfl_xor_sync(0xffffffffu, sum, o);
    const float mean = sum * (1.0f / 512.0f);

    float vs = 0.f;
#pragma unroll
    for (int j = 0; j < 4; j++) {
        v[j].x -= mean; v[j].y -= mean; v[j].z -= mean; v[j].w -= mean;
        vs += (v[j].x * v[j].x + v[j].y * v[j].y) + (v[j].z * v[j].z + v[j].w * v[j].w);
    }
#pragma unroll
    for (int o = 16; o; o >>= 1) vs += __shfl_xor_sync(0xffffffffu, vs, o);
    const float inv = rsqrtf(vs * (1.0f / 512.0f) + 1e-5f);

#pragma unroll
    for (int j = 0; j < 4; j++) {
        float4 xm = x1[pb + j * 32];
        float4 gm = gma[lane + j * 32];
        float4 bt = bta[lane + j * 32];
        float4 r;
        r.x = xm.x + v[j].x * inv * gm.x + bt.x;
        r.y = xm.y + v[j].y * inv * gm.y + bt.y;
        r.z = xm.z + v[j].z * inv * gm.z + bt.z;
        r.w = xm.w + v[j].w * inv * gm.w + bt.w;
        outp[pb + j * 32] = r;
    }
}

// ---------------- host launcher ----------------
extern "C" void kernel_launch(void* const* d_in, const int* in_sizes, int n_in,
                              void* d_out, int out_size) {
    (void)in_sizes; (void)n_in; (void)out_size;
    const float* x      = (const float*)d_in[0];
    const float* qkv_w  = (const float*)d_in[1];
    const float* q_bias = (const float*)d_in[2];
    const float* v_bias = (const float*)d_in[3];
    const float* lscale = (const float*)d_in[4];
    const float* cpb_w1 = (const float*)d_in[5];
    const float* cpb_b1 = (const float*)d_in[6];
    const float* cpb_w2 = (const float*)d_in[7];
    const float* proj_w = (const float*)d_in[8];
    const float* proj_b = (const float*)d_in[9];
    const float* n1g    = (const float*)d_in[10];
    const float* n1b    = (const float*)d_in[11];
    const float* n2g    = (const float*)d_in[12];
    const float* n2b    = (const float*)d_in[13];
    const float* fc1_w  = (const float*)d_in[14];
    const float* fc1_b  = (const float*)d_in[15];
    const float* fc2_w  = (const float*)d_in[16];
    const float* fc2_b  = (const float*)d_in[17];
    const float* coords = (const float*)d_in[18];
    const float* amask  = (const float*)d_in[19];
    const int*   rpi    = (const int*)d_in[20];
    float*       out    = (float*)d_out;

    float  *p_proj, *p_x1, *p_mlp;
    __half *p_qkv, *p_xh, *p_attnh, *p_x1h, *p_hid, *p_wqkv, *p_wproj, *p_wfc1, *p_wfc2;
    cudaGetSymbolAddress((void**)&p_qkv,   g_qkvh);
    cudaGetSymbolAddress((void**)&p_proj,  g_proj);
    cudaGetSymbolAddress((void**)&p_x1,    g_x1);
    cudaGetSymbolAddress((void**)&p_mlp,   g_mlp);
    cudaGetSymbolAddress((void**)&p_xh,    g_xh);
    cudaGetSymbolAddress((void**)&p_attnh, g_attnh);
    cudaGetSymbolAddress((void**)&p_x1h,   g_x1h);
    cudaGetSymbolAddress((void**)&p_hid,   g_hid);
    cudaGetSymbolAddress((void**)&p_wqkv,  g_wqkv);
    cudaGetSymbolAddress((void**)&p_wproj, g_wproj);
    cudaGetSymbolAddress((void**)&p_wfc1,  g_wfc1);
    cudaGetSymbolAddress((void**)&p_wfc2,  g_wfc2);

    cudaFuncSetAttribute(gemm_ca<512,  EpiQKVh>, cudaFuncAttributeMaxDynamicSharedMemorySize, GSMEM);
    cudaFuncSetAttribute(gemm_ca<512,  EpiBias>, cudaFuncAttributeMaxDynamicSharedMemorySize, GSMEM);
    cudaFuncSetAttribute(gemm_ca<512,  EpiGelu>, cudaFuncAttributeMaxDynamicSharedMemorySize, GSMEM);
    cudaFuncSetAttribute(gemm_ca<2048, EpiBias>, cudaFuncAttributeMaxDynamicSharedMemorySize, GSMEM);

    // 0,1: deps of the QKV GEMM; 2,3: QKV GEMM split so ncu lands on a GEMM.
    cvt_f2h<<<(Tt * 512 / 4 + 255) / 256, 256>>>(x, p_xh, Tt * 512);                 // 0
    cvt_f2h<<<(1536 * 512 / 4 + 255) / 256, 256>>>(qkv_w, p_wqkv, 1536 * 512);       // 1
    gemm_ca<512><<<dim3(3, 512), 512, GSMEM>>>(p_xh, p_wqkv,
        EpiQKVh{p_qkv, q_bias, v_bias, 0});                                          // 2
    gemm_ca<512><<<dim3(3, 512), 512, GSMEM>>>(p_xh, p_wqkv + 768 * 512,
        EpiQKVh{p_qkv, q_bias, v_bias, 768});                                        // 3
    cpb_kernel<<<225, 512>>>(coords, cpb_w1, cpb_b1, cpb_w2);                        // 4
    cmb_kernel<<<1024, 256>>>(rpi, amask);                                           // 5
    attn_mma<<<dim3(1024, 16), 128>>>(p_qkv, lscale, p_attnh);                       // 6
    cvt_f2h<<<(512 * 512 / 4 + 255) / 256, 256>>>(proj_w, p_wproj, 512 * 512);       // 7
    gemm_ca<512><<<dim3(2, 512), 512, GSMEM>>>(p_attnh, p_wproj,
        EpiBias{p_proj, proj_b, 512});                                               // 8
    ln1_kernel<<<Tt / 8, 256>>>((const float4*)p_proj, (const float4*)x,
                                (const float4*)n1g, (const float4*)n1b,
                                (float4*)p_x1, (uint2*)p_x1h);                       // 9
    cvt_f2h<<<(2048 * 512 / 4 + 255) / 256, 256>>>(fc1_w, p_wfc1, 2048 * 512);       // 10
    gemm_ca<512><<<dim3(8, 512), 512, GSMEM>>>(p_x1h, p_wfc1, EpiGelu{p_hid, fc1_b}); // 11
    cvt_f2h<<<(512 * 2048 / 4 + 255) / 256, 256>>>(fc2_w, p_wfc2, 512 * 2048);       // 12
    gemm_ca<2048><<<dim3(2, 512), 512, GSMEM>>>(p_hid, p_wfc2, EpiBias{p_mlp, fc2_b, 512}); // 13
    ln2_kernel<<<Tt / 8, 256>>>((const float4*)p_mlp, (const float4*)p_x1,
                                (const float4*)n2g, (const float4*)n2b,
                                (float4*)out);                                       // 14
}

// round 13
// speedup vs baseline: 1.0931x; 1.0738x over previous
#include <cuda_runtime.h>
#include <cuda_fp16.h>
#include <cstdint>
#include <math.h>

// ---------------- problem constants ----------------
#define BSZ   16
#define Hh    64
#define Ww    64
#define Cc    512
#define HEADS 16
#define WS    8
#define SHIFT 4
#define Ll    (Hh*Ww)
#define Tt    (BSZ*Ll)     // 65536 tokens
#define HID   2048

// ---------------- scratch (device globals) ----------------
__device__ __half g_qkvh [(size_t)Tt * 1536]; // fp16, GLOBAL token order
__device__ __half g_xh   [(size_t)Tt * Cc];
__device__ __half g_attnh[(size_t)Tt * Cc];   // window order
__device__ float  g_proj [(size_t)Tt * Cc];   // window order
__device__ float  g_x1   [(size_t)Tt * Cc];   // global order
__device__ __half g_x1h  [(size_t)Tt * Cc];
__device__ __half g_hid  [(size_t)Tt * HID];
__device__ float  g_mlp  [(size_t)Tt * Cc];
__device__ float  g_tbl  [225 * HEADS];
__device__ float  g_cmb  [64 * 16 * 4096];    // combined bias+mask fp32 [w][h][i*64+j], 16MB
__device__ __half g_wqkv [1536 * 512];
__device__ __half g_wproj[512 * 512];
__device__ __half g_wfc1 [2048 * 512];
__device__ __half g_wfc2 [512 * 2048];

// ---------------- helpers ----------------
__device__ __forceinline__ void mma16(float* d, const uint32_t* a, uint32_t b0, uint32_t b1) {
    asm volatile(
        "mma.sync.aligned.m16n8k16.row.col.f32.f16.f16.f32 "
        "{%0,%1,%2,%3}, {%4,%5,%6,%7}, {%8,%9}, {%0,%1,%2,%3};\n"
        : "+f"(d[0]), "+f"(d[1]), "+f"(d[2]), "+f"(d[3])
        : "r"(a[0]), "r"(a[1]), "r"(a[2]), "r"(a[3]), "r"(b0), "r"(b1));
}
__device__ __forceinline__ void ldsm4(uint32_t* r, uint32_t addr) {
    asm volatile("ldmatrix.sync.aligned.m8n8.x4.shared.b16 {%0,%1,%2,%3}, [%4];"
                 : "=r"(r[0]), "=r"(r[1]), "=r"(r[2]), "=r"(r[3]) : "r"(addr));
}
__device__ __forceinline__ void ldsm4t(uint32_t* r, uint32_t addr) {
    asm volatile("ldmatrix.sync.aligned.m8n8.x4.trans.shared.b16 {%0,%1,%2,%3}, [%4];"
                 : "=r"(r[0]), "=r"(r[1]), "=r"(r[2]), "=r"(r[3]) : "r"(addr));
}
__device__ __forceinline__ void cpasync16(uint32_t dst, const void* src) {
    asm volatile("cp.async.cg.shared.global [%0], [%1], 16;" :: "r"(dst), "l"(src) : "memory");
}
__device__ __forceinline__ uint32_t smem_u32(const void* p) {
    uint32_t a;
    asm("{ .reg .u64 t; cvta.to.shared.u64 t, %1; cvt.u32.u64 %0, t; }" : "=r"(a) : "l"(p));
    return a;
}
__device__ __forceinline__ uint32_t packh2(float a, float b) {
    __half2 h = __floats2half2_rn(a, b);
    return *(uint32_t*)&h;
}

// window-token index -> global token index
__device__ __forceinline__ int win2glob(int m) {
    int bw = m >> 6, n = m & 63;
    int b = bw >> 6, w = bw & 63;
    int y = (((w >> 3) << 3) + (n >> 3) + SHIFT) & 63;
    int x = (((w & 7) << 3) + (n & 7) + SHIFT) & 63;
    return (b << 12) | (y << 6) | x;
}

// ---------------- epilogue functors: pair interface, vectorized stores ----------------
struct EpiQKVh {
    __half* out; const float* qb; const float* vb;
    __device__ __forceinline__ void operator()(int m, int c, float v0, float v1) const {
        if (c < 512)       { v0 += qb[c]; v1 += qb[c + 1]; }
        else if (c >= 1024){ v0 += vb[c - 1024]; v1 += vb[c - 1023]; }
        *(__half2*)(out + (size_t)m * 1536 + c) = __floats2half2_rn(v0, v1);
    }
};
struct EpiBias {
    float* out; const float* b; int ldc;
    __device__ __forceinline__ void operator()(int m, int c, float v0, float v1) const {
        float2 r; r.x = v0 + b[c]; r.y = v1 + b[c + 1];
        *(float2*)(out + (size_t)m * ldc + c) = r;
    }
};
struct EpiGelu {
    __half* out; const float* b;
    __device__ __forceinline__ void operator()(int m, int c, float v0, float v1) const {
        v0 += b[c];     v0 = 0.5f * v0 * (1.0f + erff(v0 * 0.70710678118654752f));
        v1 += b[c + 1]; v1 = 0.5f * v1 * (1.0f + erff(v1 * 0.70710678118654752f));
        *(__half2*)(out + (size_t)m * HID + c) = __floats2half2_rn(v0, v1);
    }
};

// ---------------- fp16 mma.sync GEMM: 128x256 tile, 512 threads, 3-stage cp.async ----------------
// (round-10 configuration — local optimum; do not re-pipeline, see R11/R12 post-mortems)
#define BKk     64
#define STG_A   (128 * BKk * 2)            // 16384 B
#define STG_B   (256 * BKk * 2)            // 32768 B
#define STG     (STG_A + STG_B)            // 49152 B
#define GSMEM   (3 * STG)                  // 147456 B

template <int K, class Epi>
__global__ __launch_bounds__(512, 1)
void gemm_ca(const __half* __restrict__ A, const __half* __restrict__ B, Epi epi) {
    extern __shared__ __align__(16) char sm[];
    const uint32_t smBase = smem_u32(sm);

    const int tid  = threadIdx.x;
    const int lane = tid & 31, warp = tid >> 5;      // 16 warps
    const int gid  = lane >> 2, tig = lane & 3;
    const int lrow = lane & 15, lk = lane >> 4;
    const int wm   = warp >> 2, wn = warp & 3;        // 4 x 4
    const int m0   = blockIdx.y << 7;                 // 128-row tile
    const int n0   = blockIdx.x << 8;                 // 256-col tile
    const int NT   = K / BKk;

    // cp.async descriptors: A 1024 units -> 2/thread; B 2048 units -> 4/thread
    uint32_t aOff[2], sDstA[2];
#pragma unroll
    for (int i = 0; i < 2; i++) {
        int u = tid * 2 + i, r = u >> 3, c = u & 7;
        aOff[i]  = (uint32_t)(m0 + r) * (uint32_t)K + (uint32_t)(c * 8);
        sDstA[i] = (uint32_t)((r * 8 + (c ^ (r & 7))) * 16);
    }
    uint32_t bOff[4], sDstB[4];
#pragma unroll
    for (int i = 0; i < 4; i++) {
        int u = tid * 4 + i, r = u >> 3, c = u & 7;
        bOff[i]  = (uint32_t)(n0 + r) * (uint32_t)K + (uint32_t)(c * 8);
        sDstB[i] = (uint32_t)(STG_A + (r * 8 + (c ^ (r & 7))) * 16);
    }

    int aR8[2], aSW[2], bR8[4], bSW[4];
#pragma unroll
    for (int t = 0; t < 2; t++) {
        int r = wm * 32 + t * 16 + lrow;
        aR8[t] = r * 8; aSW[t] = r & 7;
    }
#pragma unroll
    for (int t = 0; t < 4; t++) {
        int r = wn * 64 + t * 16 + lrow;
        bR8[t] = r * 8; bSW[t] = r & 7;
    }

    float acc[2][8][4];
#pragma unroll
    for (int i = 0; i < 2; i++)
#pragma unroll
        for (int j = 0; j < 8; j++)
#pragma unroll
            for (int k = 0; k < 4; k++) acc[i][j][k] = 0.f;

    auto load_tile = [&](int s, int kt) {
        uint32_t base = smBase + s * STG;
        uint32_t ko = (uint32_t)(kt * BKk);
#pragma unroll
        for (int i = 0; i < 2; i++) cpasync16(base + sDstA[i], A + aOff[i] + ko);
#pragma unroll
        for (int i = 0; i < 4; i++) cpasync16(base + sDstB[i], B + bOff[i] + ko);
    };

    load_tile(0, 0);
    asm volatile("cp.async.commit_group;" ::: "memory");
    load_tile(1, 1);
    asm volatile("cp.async.commit_group;" ::: "memory");

    for (int kt = 0; kt < NT; kt++) {
        const int s = kt % 3;
        asm volatile("cp.async.wait_group 1;" ::: "memory");
        __syncthreads();
        if (kt + 2 < NT) load_tile((kt + 2) % 3, kt + 2);
        asm volatile("cp.async.commit_group;" ::: "memory");

        uint32_t sA = smBase + s * STG;
        uint32_t sB = sA + STG_A;
#pragma unroll
        for (int ks = 0; ks < 4; ks++) {
            uint32_t a[2][4], b[4][4];
#pragma unroll
            for (int mt = 0; mt < 2; mt++)
                ldsm4(a[mt], sA + (uint32_t)((aR8[mt] + ((ks * 2 + lk) ^ aSW[mt])) * 16));
#pragma unroll
            for (int nt = 0; nt < 4; nt++)
                ldsm4(b[nt], sB + (uint32_t)((bR8[nt] + ((ks * 2 + lk) ^ bSW[nt])) * 16));
#pragma unroll
            for (int mt = 0; mt < 2; mt++)
#pragma unroll
                for (int n8 = 0; n8 < 8; n8++)
                    mma16(acc[mt][n8], a[mt], b[n8 >> 1][n8 & 1], b[n8 >> 1][(n8 & 1) + 2]);
        }
    }

    // epilogue: vectorized pair stores
#pragma unroll
    for (int mt = 0; mt < 2; mt++)
#pragma unroll
        for (int n8 = 0; n8 < 8; n8++) {
            int r = m0 + wm * 32 + mt * 16 + gid;
            int c = n0 + wn * 64 + n8 * 8 + tig * 2;
            epi(r,     c, acc[mt][n8][0], acc[mt][n8][1]);
            epi(r + 8, c, acc[mt][n8][2], acc[mt][n8][3]);
        }
}

// ---------------- batched fp32 -> fp16 convert (all weights + x in one launch) ----------------
// segment table passed by value
struct CvtSeg { const float* src; __half* dst; int n4; };   // n4 = float4 count

__global__ __launch_bounds__(256)
void cvt_batch(CvtSeg s0, CvtSeg s1, CvtSeg s2, CvtSeg s3, CvtSeg s4,
               int c0, int c1, int c2, int c3) {
    int blk = blockIdx.x;
    CvtSeg s;
    int base;
    if      (blk < c0) { s = s0; base = blk; }
    else if (blk < c1) { s = s1; base = blk - c0; }
    else if (blk < c2) { s = s2; base = blk - c1; }
    else if (blk < c3) { s = s3; base = blk - c2; }
    else               { s = s4; base = blk - c3; }
    int i = base * 256 + threadIdx.x;
    if (i < s.n4) {
        float4 v = ((const float4*)s.src)[i];
        uint2 u;
        u.x = packh2(v.x, v.y);
        u.y = packh2(v.z, v.w);
        ((uint2*)s.dst)[i] = u;
    }
}

// ---------------- CPB MLP ----------------
__global__ __launch_bounds__(512) void cpb_kernel(const float* __restrict__ ct,
                                                  const float* __restrict__ w1,
                                                  const float* __restrict__ b1,
                                                  const float* __restrict__ w2) {
    __shared__ float hid[512];
    int p = blockIdx.x;
    float c0 = ct[p * 2 + 0], c1 = ct[p * 2 + 1];
    int t = threadIdx.x;
    hid[t] = fmaxf(c0 * w1[t * 2 + 0] + c1 * w1[t * 2 + 1] + b1[t], 0.f);
    __syncthreads();
    int lane = t & 31, h = t >> 5;
    float s = 0.f;
    for (int k = lane; k < 512; k += 32) s += w2[h * 512 + k] * hid[k];
#pragma unroll
    for (int o = 16; o; o >>= 1) s += __shfl_xor_sync(0xffffffffu, s, o);
    if (lane == 0) g_tbl[p * 16 + h] = 16.0f / (1.0f + __expf(-s));
}

// ---------------- combined bias+mask table: cmb[w][h][ij] (fp32) ----------------
__global__ __launch_bounds__(256)
void cmb_kernel(const int* __restrict__ rpi, const float* __restrict__ am) {
    int wh = blockIdx.x;          // w*16 + h
    int w = wh >> 4, h = wh & 15;
#pragma unroll
    for (int e = 0; e < 16; e++) {
        int ij = threadIdx.x + e * 256;
        g_cmb[((size_t)wh << 12) + ij] = g_tbl[rpi[ij] * 16 + h] + am[(size_t)w * 4096 + ij];
    }
}

// ---------------- attention: tensor-core, one CTA per (window-batch, head) ----------------
__global__ __launch_bounds__(128)
void attn_mma(const __half* __restrict__ qkv, const float* __restrict__ ls,
              __half* __restrict__ outp) {
    __shared__ __align__(16) __half sQ[64][40];
    __shared__ __align__(16) __half sK[64][40];
    __shared__ __align__(16) __half sV[64][40];
    __shared__ float sRq[64];
    __shared__ float sRk[64];

    const int bw = blockIdx.x, h = blockIdx.y;
    const int tid = threadIdx.x;
    const int lane = tid & 31, warp = tid >> 5;
    const int gid = lane >> 2, tig = lane & 3;
    const int lrow = lane & 15, lk = lane >> 4;

#pragma unroll
    for (int i = 0; i < 2; i++) {
        int u = tid * 2 + i;
        int r = u >> 2, c = u & 3;
        int g = win2glob(bw * 64 + r);
        const __half* src = qkv + (size_t)g * 1536 + h * 32 + c * 8;
        *(uint4*)&sQ[r][c * 8] = *(const uint4*)(src);
        *(uint4*)&sK[r][c * 8] = *(const uint4*)(src + 512);
        *(uint4*)&sV[r][c * 8] = *(const uint4*)(src + 1024);
    }
    __syncthreads();

    const float scale = __expf(fminf(ls[h], 4.6051701859880914f));

    {
        int r = tid >> 1, seg = (tid & 1) * 16;
        float sq = 0.f, sk = 0.f;
#pragma unroll
        for (int d = 0; d < 16; d++) {
            float qv = __half2float(sQ[r][seg + d]);
            float kv = __half2float(sK[r][seg + d]);
            sq += qv * qv;
            sk += kv * kv;
        }
        sq += __shfl_xor_sync(0xffffffffu, sq, 1);
        sk += __shfl_xor_sync(0xffffffffu, sk, 1);
        if ((tid & 1) == 0) {
            sRq[r] = scale / fmaxf(sqrtf(sq), 1e-12f);
            sRk[r] = 1.0f  / fmaxf(sqrtf(sk), 1e-12f);
        }
    }
    __syncthreads();

    const uint32_t qB = smem_u32(&sQ[0][0]);
    const uint32_t kB = smem_u32(&sK[0][0]);
    const uint32_t vB = smem_u32(&sV[0][0]);

    float accS[8][4];
#pragma unroll
    for (int j = 0; j < 8; j++)
#pragma unroll
        for (int k = 0; k < 4; k++) accS[j][k] = 0.f;

#pragma unroll
    for (int ks = 0; ks < 2; ks++) {
        uint32_t a[4], b[4][4];
        ldsm4(a, qB + (uint32_t)(((warp * 16 + lrow) * 40 + ks * 16 + lk * 8) * 2));
#pragma unroll
        for (int nt = 0; nt < 4; nt++)
            ldsm4(b[nt], kB + (uint32_t)(((nt * 16 + lrow) * 40 + ks * 16 + lk * 8) * 2));
#pragma unroll
        for (int n8 = 0; n8 < 8; n8++)
            mma16(accS[n8], a, b[n8 >> 1][n8 & 1], b[n8 >> 1][(n8 & 1) + 2]);
    }

    const int w = bw & 63;
    const float* cmbF = g_cmb + (((size_t)w * 16 + h) << 12);
    const int i0 = warp * 16 + gid;
    const float rq0 = sRq[i0], rq1 = sRq[i0 + 8];
#pragma unroll
    for (int n8 = 0; n8 < 8; n8++) {
        int j = n8 * 8 + tig * 2;
        float rk0 = sRk[j], rk1 = sRk[j + 1];
        float2 b0 = *(const float2*)(cmbF + i0 * 64 + j);
        float2 b1 = *(const float2*)(cmbF + (i0 + 8) * 64 + j);
        accS[n8][0] = accS[n8][0] * rq0 * rk0 + b0.x;
        accS[n8][1] = accS[n8][1] * rq0 * rk1 + b0.y;
        accS[n8][2] = accS[n8][2] * rq1 * rk0 + b1.x;
        accS[n8][3] = accS[n8][3] * rq1 * rk1 + b1.y;
    }

    float m0 = -1e30f, m1 = -1e30f;
#pragma unroll
    for (int n8 = 0; n8 < 8; n8++) {
        m0 = fmaxf(m0, fmaxf(accS[n8][0], accS[n8][1]));
        m1 = fmaxf(m1, fmaxf(accS[n8][2], accS[n8][3]));
    }
    m0 = fmaxf(m0, __shfl_xor_sync(0xffffffffu, m0, 1));
    m0 = fmaxf(m0, __shfl_xor_sync(0xffffffffu, m0, 2));
    m1 = fmaxf(m1, __shfl_xor_sync(0xffffffffu, m1, 1));
    m1 = fmaxf(m1, __shfl_xor_sync(0xffffffffu, m1, 2));
    float s0 = 0.f, s1 = 0.f;
#pragma unroll
    for (int n8 = 0; n8 < 8; n8++) {
        accS[n8][0] = __expf(accS[n8][0] - m0); s0 += accS[n8][0];
        accS[n8][1] = __expf(accS[n8][1] - m0); s0 += accS[n8][1];
        accS[n8][2] = __expf(accS[n8][2] - m1); s1 += accS[n8][2];
        accS[n8][3] = __expf(accS[n8][3] - m1); s1 += accS[n8][3];
    }
    s0 += __shfl_xor_sync(0xffffffffu, s0, 1);
    s0 += __shfl_xor_sync(0xffffffffu, s0, 2);
    s1 += __shfl_xor_sync(0xffffffffu, s1, 1);
    s1 += __shfl_xor_sync(0xffffffffu, s1, 2);
    float r0 = 1.0f / s0, r1 = 1.0f / s1;

    uint32_t pk0[8], pk1[8];
#pragma unroll
    for (int n8 = 0; n8 < 8; n8++) {
        pk0[n8] = packh2(accS[n8][0] * r0, accS[n8][1] * r0);
        pk1[n8] = packh2(accS[n8][2] * r1, accS[n8][3] * r1);
    }

    float accO[4][4];
#pragma unroll
    for (int j = 0; j < 4; j++)
#pragma unroll
        for (int k = 0; k < 4; k++) accO[j][k] = 0.f;

#pragma unroll
    for (int kb = 0; kb < 4; kb++) {
        uint32_t aP[4] = { pk0[2 * kb], pk1[2 * kb], pk0[2 * kb + 1], pk1[2 * kb + 1] };
#pragma unroll
        for (int dt = 0; dt < 2; dt++) {
            uint32_t vb[4];
            int vr = kb * 16 + ((lane >> 4) << 3) + (lane & 7);
            int vc = dt * 16 + ((lane >> 3) & 1) * 8;
            ldsm4t(vb, vB + (uint32_t)((vr * 40 + vc) * 2));
            mma16(accO[2 * dt],     aP, vb[0], vb[2]);
            mma16(accO[2 * dt + 1], aP, vb[1], vb[3]);
        }
    }

#pragma unroll
    for (int n8 = 0; n8 < 4; n8++) {
        int d = n8 * 8 + tig * 2;
        size_t o0 = (size_t)(bw * 64 + i0) * 512 + h * 32 + d;
        __half2 h0 = __floats2half2_rn(accO[n8][0], accO[n8][1]);
        __half2 h1 = __floats2half2_rn(accO[n8][2], accO[n8][3]);
        *(__half2*)(outp + o0)            = h0;
        *(__half2*)(outp + o0 + 8 * 512)  = h1;
    }
}

// ---------------- LayerNorm: warp-per-token, no barriers ----------------
__global__ __launch_bounds__(256)
void ln1_kernel(const float4* __restrict__ proj, const float4* __restrict__ x,
                const float4* __restrict__ gma, const float4* __restrict__ bta,
                float4* __restrict__ x1o, uint2* __restrict__ x1h) {
    const int m = blockIdx.x * 8 + (threadIdx.x >> 5);
    const int lane = threadIdx.x & 31;
    const size_t pb = (size_t)m * 128 + lane;

    float4 v[4];
    float sum = 0.f;
#pragma unroll
    for (int j = 0; j < 4; j++) {
        v[j] = proj[pb + j * 32];
        sum += (v[j].x + v[j].y) + (v[j].z + v[j].w);
    }
#pragma unroll
    for (int o = 16; o; o >>= 1) sum += __shfl_xor_sync(0xffffffffu, sum, o);
    const float mean = sum * (1.0f / 512.0f);

    float vs = 0.f;
#pragma unroll
    for (int j = 0; j < 4; j++) {
        v[j].x -= mean; v[j].y -= mean; v[j].z -= mean; v[j].w -= mean;
        vs += (v[j].x * v[j].x + v[j].y * v[j].y) + (v[j].z * v[j].z + v[j].w * v[j].w);
    }
#pragma unroll
    for (int o = 16; o; o >>= 1) vs += __shfl_xor_sync(0xffffffffu, vs, o);
    const float inv = rsqrtf(vs * (1.0f / 512.0f) + 1e-5f);

    const int g = win2glob(m);
    const size_t gb = (size_t)g * 128 + lane;
#pragma unroll
    for (int j = 0; j < 4; j++) {
        float4 xm = x[gb + j * 32];
        float4 gm = gma[lane + j * 32];
        float4 bt = bta[lane + j * 32];
        float4 r;
        r.x = xm.x + v[j].x * inv * gm.x + bt.x;
        r.y = xm.y + v[j].y * inv * gm.y + bt.y;
        r.z = xm.z + v[j].z * inv * gm.z + bt.z;
        r.w = xm.w + v[j].w * inv * gm.w + bt.w;
        x1o[gb + j * 32] = r;
        uint2 u; u.x = packh2(r.x, r.y); u.y = packh2(r.z, r.w);
        x1h[gb + j * 32] = u;
    }
}

__global__ __launch_bounds__(256)
void ln2_kernel(const float4* __restrict__ mlp, const float4* __restrict__ x1,
                const float4* __restrict__ gma, const float4* __restrict__ bta,
                float4* __restrict__ outp) {
    const int m = blockIdx.x * 8 + (threadIdx.x >> 5);
    const int lane = threadIdx.x & 31;
    const size_t pb = (size_t)m * 128 + lane;

    float4 v[4];
    float sum = 0.f;
#pragma unroll
    for (int j = 0; j < 4; j++) {
        v[j] = mlp[pb + j * 32];
        sum += (v[j].x + v[j].y) + (v[j].z + v[j].w);
    }
#pragma unroll
    for (int o = 16; o; o >>= 1) sum += __shfl_xor_sync(0xffffffffu, sum, o);
    const float mean = sum * (1.0f / 512.0f);

    float vs = 0.f;
#pragma unroll
    for (int j = 0; j < 4; j++) {
        v[j].x -= mean; v[j].y -= mean; v[j].z -= mean; v[j].w -= mean;
        vs += (v[j].x * v[j].x + v[j].y * v[j].y) + (v[j].z * v[j].z + v[j].w * v[j].w);
    }
#pragma unroll
    for (int o = 16; o; o >>= 1) vs += __shfl_xor_sync(0xffffffffu, vs, o);
    const float inv = rsqrtf(vs * (1.0f / 512.0f) + 1e-5f);

#pragma unroll
    for (int j = 0; j < 4; j++) {
        float4 xm = x1[pb + j * 32];
        float4 gm = gma[lane + j * 32];
        float4 bt = bta[lane + j * 32];
        float4 r;
        r.x = xm.x + v[j].x * inv * gm.x + bt.x;
        r.y = xm.y + v[j].y * inv * gm.y + bt.y;
        r.z = xm.z + v[j].z * inv * gm.z + bt.z;
        r.w = xm.w + v[j].w * inv * gm.w + bt.w;
        outp[pb + j * 32] = r;
    }
}

// ---------------- host launcher ----------------
extern "C" void kernel_launch(void* const* d_in, const int* in_sizes, int n_in,
                              void* d_out, int out_size) {
    (void)in_sizes; (void)n_in; (void)out_size;
    const float* x      = (const float*)d_in[0];
    const float* qkv_w  = (const float*)d_in[1];
    const float* q_bias = (const float*)d_in[2];
    const float* v_bias = (const float*)d_in[3];
    const float* lscale = (const float*)d_in[4];
    const float* cpb_w1 = (const float*)d_in[5];
    const float* cpb_b1 = (const float*)d_in[6];
    const float* cpb_w2 = (const float*)d_in[7];
    const float* proj_w = (const float*)d_in[8];
    const float* proj_b = (const float*)d_in[9];
    const float* n1g    = (const float*)d_in[10];
    const float* n1b    = (const float*)d_in[11];
    const float* n2g    = (const float*)d_in[12];
    const float* n2b    = (const float*)d_in[13];
    const float* fc1_w  = (const float*)d_in[14];
    const float* fc1_b  = (const float*)d_in[15];
    const float* fc2_w  = (const float*)d_in[16];
    const float* fc2_b  = (const float*)d_in[17];
    const float* coords = (const float*)d_in[18];
    const float* amask  = (const float*)d_in[19];
    const int*   rpi    = (const int*)d_in[20];
    float*       out    = (float*)d_out;

    float  *p_proj, *p_x1, *p_mlp;
    __half *p_qkv, *p_xh, *p_attnh, *p_x1h, *p_hid, *p_wqkv, *p_wproj, *p_wfc1, *p_wfc2;
    cudaGetSymbolAddress((void**)&p_qkv,   g_qkvh);
    cudaGetSymbolAddress((void**)&p_proj,  g_proj);
    cudaGetSymbolAddress((void**)&p_x1,    g_x1);
    cudaGetSymbolAddress((void**)&p_mlp,   g_mlp);
    cudaGetSymbolAddress((void**)&p_xh,    g_xh);
    cudaGetSymbolAddress((void**)&p_attnh, g_attnh);
    cudaGetSymbolAddress((void**)&p_x1h,   g_x1h);
    cudaGetSymbolAddress((void**)&p_hid,   g_hid);
    cudaGetSymbolAddress((void**)&p_wqkv,  g_wqkv);
    cudaGetSymbolAddress((void**)&p_wproj, g_wproj);
    cudaGetSymbolAddress((void**)&p_wfc1,  g_wfc1);
    cudaGetSymbolAddress((void**)&p_wfc2,  g_wfc2);

    cudaFuncSetAttribute(gemm_ca<512,  EpiQKVh>, cudaFuncAttributeMaxDynamicSharedMemorySize, GSMEM);
    cudaFuncSetAttribute(gemm_ca<512,  EpiBias>, cudaFuncAttributeMaxDynamicSharedMemorySize, GSMEM);
    cudaFuncSetAttribute(gemm_ca<512,  EpiGelu>, cudaFuncAttributeMaxDynamicSharedMemorySize, GSMEM);
    cudaFuncSetAttribute(gemm_ca<2048, EpiBias>, cudaFuncAttributeMaxDynamicSharedMemorySize, GSMEM);

    // segment block counts for batched convert (float4 granularity, 256 thr/blk)
    const int n4_x    = Tt * 512 / 4;        // 8388608
    const int n4_qkvw = 1536 * 512 / 4;      // 196608
    const int n4_proj = 512 * 512 / 4;       // 65536
    const int n4_fc1  = 2048 * 512 / 4;      // 262144
    const int n4_fc2  = 512 * 2048 / 4;      // 262144
    const int b0 = (n4_x + 255) / 256;
    const int b1 = b0 + (n4_qkvw + 255) / 256;
    const int b2 = b1 + (n4_proj + 255) / 256;
    const int b3 = b2 + (n4_fc1 + 255) / 256;
    const int b4 = b3 + (n4_fc2 + 255) / 256;

    // 0: all fp32->fp16 conversions in one launch
    cvt_batch<<<b4, 256>>>(
        CvtSeg{x, p_xh, n4_x}, CvtSeg{qkv_w, p_wqkv, n4_qkvw},
        CvtSeg{proj_w, p_wproj, n4_proj}, CvtSeg{fc1_w, p_wfc1, n4_fc1},
        CvtSeg{fc2_w, p_wfc2, n4_fc2}, b0, b1, b2, b3);
    // 1: QKV GEMM (single launch, N=1536 -> 6 col tiles)
    gemm_ca<512><<<dim3(6, 512), 512, GSMEM>>>(p_xh, p_wqkv, EpiQKVh{p_qkv, q_bias, v_bias});
    cpb_kernel<<<225, 512>>>(coords, cpb_w1, cpb_b1, cpb_w2);                        // 2
    cmb_kernel<<<1024, 256>>>(rpi, amask);                                           // 3
    attn_mma<<<dim3(1024, 16), 128>>>(p_qkv, lscale, p_attnh);                       // 4
    gemm_ca<512><<<dim3(2, 512), 512, GSMEM>>>(p_attnh, p_wproj,
        EpiBias{p_proj, proj_b, 512});                                               // 5
    ln1_kernel<<<Tt / 8, 256>>>((const float4*)p_proj, (const float4*)x,
                                (const float4*)n1g, (const float4*)n1b,
                                (float4*)p_x1, (uint2*)p_x1h);                       // 6
    gemm_ca<512><<<dim3(8, 512), 512, GSMEM>>>(p_x1h, p_wfc1, EpiGelu{p_hid, fc1_b}); // 7
    gemm_ca<2048><<<dim3(2, 512), 512, GSMEM>>>(p_hid, p_wfc2, EpiBias{p_mlp, fc2_b, 512}); // 8
    ln2_kernel<<<Tt / 8, 256>>>((const float4*)p_mlp, (const float4*)p_x1,
                                (const float4*)n2g, (const float4*)n2b,
                                (float4*)out);                                       // 9
}

// round 14
// speedup vs baseline: 1.0976x; 1.0040x over previous
#include <cuda_runtime.h>
#include <cuda_fp16.h>
#include <cstdint>
#include <math.h>

// ---------------- problem constants ----------------
#define BSZ   16
#define Hh    64
#define Ww    64
#define Cc    512
#define HEADS 16
#define WS    8
#define SHIFT 4
#define Ll    (Hh*Ww)
#define Tt    (BSZ*Ll)     // 65536 tokens
#define HID   2048

// ---------------- scratch (device globals) ----------------
__device__ __half g_qkvh [(size_t)Tt * 1536];
__device__ __half g_xh   [(size_t)Tt * Cc];
__device__ __half g_attnh[(size_t)Tt * Cc];
__device__ float  g_proj [(size_t)Tt * Cc];
__device__ float  g_x1   [(size_t)Tt * Cc];
__device__ __half g_x1h  [(size_t)Tt * Cc];
__device__ __half g_hid  [(size_t)Tt * HID];
__device__ float  g_mlp  [(size_t)Tt * Cc];
__device__ float  g_tbl  [225 * HEADS];
__device__ float  g_cmb  [64 * 16 * 4096];
__device__ __half g_wqkv [1536 * 512];
__device__ __half g_wproj[512 * 512];
__device__ __half g_wfc1 [2048 * 512];
__device__ __half g_wfc2 [512 * 2048];

// ---------------- helpers ----------------
__device__ __forceinline__ void mma16(float* d, const uint32_t* a, uint32_t b0, uint32_t b1) {
    asm volatile(
        "mma.sync.aligned.m16n8k16.row.col.f32.f16.f16.f32 "
        "{%0,%1,%2,%3}, {%4,%5,%6,%7}, {%8,%9}, {%0,%1,%2,%3};\n"
        : "+f"(d[0]), "+f"(d[1]), "+f"(d[2]), "+f"(d[3])
        : "r"(a[0]), "r"(a[1]), "r"(a[2]), "r"(a[3]), "r"(b0), "r"(b1));
}
__device__ __forceinline__ void ldsm4(uint32_t* r, uint32_t addr) {
    asm volatile("ldmatrix.sync.aligned.m8n8.x4.shared.b16 {%0,%1,%2,%3}, [%4];"
                 : "=r"(r[0]), "=r"(r[1]), "=r"(r[2]), "=r"(r[3]) : "r"(addr));
}
__device__ __forceinline__ void ldsm4t(uint32_t* r, uint32_t addr) {
    asm volatile("ldmatrix.sync.aligned.m8n8.x4.trans.shared.b16 {%0,%1,%2,%3}, [%4];"
                 : "=r"(r[0]), "=r"(r[1]), "=r"(r[2]), "=r"(r[3]) : "r"(addr));
}
__device__ __forceinline__ void cpasync16(uint32_t dst, const void* src) {
    asm volatile("cp.async.cg.shared.global [%0], [%1], 16;" :: "r"(dst), "l"(src) : "memory");
}
__device__ __forceinline__ uint32_t smem_u32(const void* p) {
    uint32_t a;
    asm("{ .reg .u64 t; cvta.to.shared.u64 t, %1; cvt.u32.u64 %0, t; }" : "=r"(a) : "l"(p));
    return a;
}
__device__ __forceinline__ uint32_t packh2(float a, float b) {
    __half2 h = __floats2half2_rn(a, b);
    return *(uint32_t*)&h;
}

__device__ __forceinline__ int win2glob(int m) {
    int bw = m >> 6, n = m & 63;
    int b = bw >> 6, w = bw & 63;
    int y = (((w >> 3) << 3) + (n >> 3) + SHIFT) & 63;
    int x = (((w & 7) << 3) + (n & 7) + SHIFT) & 63;
    return (b << 12) | (y << 6) | x;
}

// ---------------- epilogue functors ----------------
struct EpiQKVh {
    __half* out; const float* qb; const float* vb;
    __device__ __forceinline__ void operator()(int m, int c, float v0, float v1) const {
        if (c < 512)       { v0 += qb[c]; v1 += qb[c + 1]; }
        else if (c >= 1024){ v0 += vb[c - 1024]; v1 += vb[c - 1023]; }
        *(__half2*)(out + (size_t)m * 1536 + c) = __floats2half2_rn(v0, v1);
    }
};
struct EpiBias {
    float* out; const float* b; int ldc;
    __device__ __forceinline__ void operator()(int m, int c, float v0, float v1) const {
        float2 r; r.x = v0 + b[c]; r.y = v1 + b[c + 1];
        *(float2*)(out + (size_t)m * ldc + c) = r;
    }
};
struct EpiGelu {
    __half* out; const float* b;
    __device__ __forceinline__ void operator()(int m, int c, float v0, float v1) const {
        v0 += b[c];     v0 = 0.5f * v0 * (1.0f + erff(v0 * 0.70710678118654752f));
        v1 += b[c + 1]; v1 = 0.5f * v1 * (1.0f + erff(v1 * 0.70710678118654752f));
        *(__half2*)(out + (size_t)m * HID + c) = __floats2half2_rn(v0, v1);
    }
};

// ---------------- fp16 mma.sync GEMM: 128x256, 512 thr, 3-stage (round-10 optimum) ----------------
#define BKk     64
#define STG_A   (128 * BKk * 2)
#define STG_B   (256 * BKk * 2)
#define STG     (STG_A + STG_B)
#define GSMEM   (3 * STG)

template <int K, class Epi>
__global__ __launch_bounds__(512, 1)
void gemm_ca(const __half* __restrict__ A, const __half* __restrict__ B, Epi epi) {
    extern __shared__ __align__(16) char sm[];
    const uint32_t smBase = smem_u32(sm);

    const int tid  = threadIdx.x;
    const int lane = tid & 31, warp = tid >> 5;
    const int gid  = lane >> 2, tig = lane & 3;
    const int lrow = lane & 15, lk = lane >> 4;
    const int wm   = warp >> 2, wn = warp & 3;
    const int m0   = blockIdx.y << 7;
    const int n0   = blockIdx.x << 8;
    const int NT   = K / BKk;

    uint32_t aOff[2], sDstA[2];
#pragma unroll
    for (int i = 0; i < 2; i++) {
        int u = tid * 2 + i, r = u >> 3, c = u & 7;
        aOff[i]  = (uint32_t)(m0 + r) * (uint32_t)K + (uint32_t)(c * 8);
        sDstA[i] = (uint32_t)((r * 8 + (c ^ (r & 7))) * 16);
    }
    uint32_t bOff[4], sDstB[4];
#pragma unroll
    for (int i = 0; i < 4; i++) {
        int u = tid * 4 + i, r = u >> 3, c = u & 7;
        bOff[i]  = (uint32_t)(n0 + r) * (uint32_t)K + (uint32_t)(c * 8);
        sDstB[i] = (uint32_t)(STG_A + (r * 8 + (c ^ (r & 7))) * 16);
    }

    int aR8[2], aSW[2], bR8[4], bSW[4];
#pragma unroll
    for (int t = 0; t < 2; t++) {
        int r = wm * 32 + t * 16 + lrow;
        aR8[t] = r * 8; aSW[t] = r & 7;
    }
#pragma unroll
    for (int t = 0; t < 4; t++) {
        int r = wn * 64 + t * 16 + lrow;
        bR8[t] = r * 8; bSW[t] = r & 7;
    }

    float acc[2][8][4];
#pragma unroll
    for (int i = 0; i < 2; i++)
#pragma unroll
        for (int j = 0; j < 8; j++)
#pragma unroll
            for (int k = 0; k < 4; k++) acc[i][j][k] = 0.f;

    auto load_tile = [&](int s, int kt) {
        uint32_t base = smBase + s * STG;
        uint32_t ko = (uint32_t)(kt * BKk);
#pragma unroll
        for (int i = 0; i < 2; i++) cpasync16(base + sDstA[i], A + aOff[i] + ko);
#pragma unroll
        for (int i = 0; i < 4; i++) cpasync16(base + sDstB[i], B + bOff[i] + ko);
    };

    load_tile(0, 0);
    asm volatile("cp.async.commit_group;" ::: "memory");
    load_tile(1, 1);
    asm volatile("cp.async.commit_group;" ::: "memory");

    for (int kt = 0; kt < NT; kt++) {
        const int s = kt % 3;
        asm volatile("cp.async.wait_group 1;" ::: "memory");
        __syncthreads();
        if (kt + 2 < NT) load_tile((kt + 2) % 3, kt + 2);
        asm volatile("cp.async.commit_group;" ::: "memory");

        uint32_t sA = smBase + s * STG;
        uint32_t sB = sA + STG_A;
#pragma unroll
        for (int ks = 0; ks < 4; ks++) {
            uint32_t a[2][4], b[4][4];
#pragma unroll
            for (int mt = 0; mt < 2; mt++)
                ldsm4(a[mt], sA + (uint32_t)((aR8[mt] + ((ks * 2 + lk) ^ aSW[mt])) * 16));
#pragma unroll
            for (int nt = 0; nt < 4; nt++)
                ldsm4(b[nt], sB + (uint32_t)((bR8[nt] + ((ks * 2 + lk) ^ bSW[nt])) * 16));
#pragma unroll
            for (int mt = 0; mt < 2; mt++)
#pragma unroll
                for (int n8 = 0; n8 < 8; n8++)
                    mma16(acc[mt][n8], a[mt], b[n8 >> 1][n8 & 1], b[n8 >> 1][(n8 & 1) + 2]);
        }
    }

#pragma unroll
    for (int mt = 0; mt < 2; mt++)
#pragma unroll
        for (int n8 = 0; n8 < 8; n8++) {
            int r = m0 + wm * 32 + mt * 16 + gid;
            int c = n0 + wn * 64 + n8 * 8 + tig * 2;
            epi(r,     c, acc[mt][n8][0], acc[mt][n8][1]);
            epi(r + 8, c, acc[mt][n8][2], acc[mt][n8][3]);
        }
}

// ---------------- batched fp32 -> fp16 convert (3 segments) ----------------
struct CvtSeg { const float* src; __half* dst; int n4; };

__global__ __launch_bounds__(256)
void cvt_batch3(CvtSeg s0, CvtSeg s1, CvtSeg s2, int c0, int c1) {
    int blk = blockIdx.x;
    CvtSeg s;
    int base;
    if      (blk < c0) { s = s0; base = blk; }
    else if (blk < c1) { s = s1; base = blk - c0; }
    else               { s = s2; base = blk - c1; }
    int i = base * 256 + threadIdx.x;
    if (i < s.n4) {
        float4 v = ((const float4*)s.src)[i];
        uint2 u;
        u.x = packh2(v.x, v.y);
        u.y = packh2(v.z, v.w);
        ((uint2*)s.dst)[i] = u;
    }
}

// ---------------- CPB MLP ----------------
__global__ __launch_bounds__(512) void cpb_kernel(const float* __restrict__ ct,
                                                  const float* __restrict__ w1,
                                                  const float* __restrict__ b1,
                                                  const float* __restrict__ w2) {
    __shared__ float hid[512];
    int p = blockIdx.x;
    float c0 = ct[p * 2 + 0], c1 = ct[p * 2 + 1];
    int t = threadIdx.x;
    hid[t] = fmaxf(c0 * w1[t * 2 + 0] + c1 * w1[t * 2 + 1] + b1[t], 0.f);
    __syncthreads();
    int lane = t & 31, h = t >> 5;
    float s = 0.f;
    for (int k = lane; k < 512; k += 32) s += w2[h * 512 + k] * hid[k];
#pragma unroll
    for (int o = 16; o; o >>= 1) s += __shfl_xor_sync(0xffffffffu, s, o);
    if (lane == 0) g_tbl[p * 16 + h] = 16.0f / (1.0f + __expf(-s));
}

// ---------------- combined bias+mask table ----------------
__global__ __launch_bounds__(256)
void cmb_kernel(const int* __restrict__ rpi, const float* __restrict__ am) {
    int wh = blockIdx.x;
    int w = wh >> 4, h = wh & 15;
#pragma unroll
    for (int e = 0; e < 16; e++) {
        int ij = threadIdx.x + e * 256;
        g_cmb[((size_t)wh << 12) + ij] = g_tbl[rpi[ij] * 16 + h] + am[(size_t)w * 4096 + ij];
    }
}

// ---------------- attention ----------------
__global__ __launch_bounds__(128)
void attn_mma(const __half* __restrict__ qkv, const float* __restrict__ ls,
              __half* __restrict__ outp) {
    __shared__ __align__(16) __half sQ[64][40];
    __shared__ __align__(16) __half sK[64][40];
    __shared__ __align__(16) __half sV[64][40];
    __shared__ float sRq[64];
    __shared__ float sRk[64];

    const int bw = blockIdx.x, h = blockIdx.y;
    const int tid = threadIdx.x;
    const int lane = tid & 31, warp = tid >> 5;
    const int gid = lane >> 2, tig = lane & 3;
    const int lrow = lane & 15, lk = lane >> 4;

#pragma unroll
    for (int i = 0; i < 2; i++) {
        int u = tid * 2 + i;
        int r = u >> 2, c = u & 3;
        int g = win2glob(bw * 64 + r);
        const __half* src = qkv + (size_t)g * 1536 + h * 32 + c * 8;
        *(uint4*)&sQ[r][c * 8] = *(const uint4*)(src);
        *(uint4*)&sK[r][c * 8] = *(const uint4*)(src + 512);
        *(uint4*)&sV[r][c * 8] = *(const uint4*)(src + 1024);
    }
    __syncthreads();

    const float scale = __expf(fminf(ls[h], 4.6051701859880914f));

    {
        int r = tid >> 1, seg = (tid & 1) * 16;
        float sq = 0.f, sk = 0.f;
#pragma unroll
        for (int d = 0; d < 16; d++) {
            float qv = __half2float(sQ[r][seg + d]);
            float kv = __half2float(sK[r][seg + d]);
            sq += qv * qv;
            sk += kv * kv;
        }
        sq += __shfl_xor_sync(0xffffffffu, sq, 1);
        sk += __shfl_xor_sync(0xffffffffu, sk, 1);
        if ((tid & 1) == 0) {
            sRq[r] = scale / fmaxf(sqrtf(sq), 1e-12f);
            sRk[r] = 1.0f  / fmaxf(sqrtf(sk), 1e-12f);
        }
    }
    __syncthreads();

    const uint32_t qB = smem_u32(&sQ[0][0]);
    const uint32_t kB = smem_u32(&sK[0][0]);
    const uint32_t vB = smem_u32(&sV[0][0]);

    float accS[8][4];
#pragma unroll
    for (int j = 0; j < 8; j++)
#pragma unroll
        for (int k = 0; k < 4; k++) accS[j][k] = 0.f;

#pragma unroll
    for (int ks = 0; ks < 2; ks++) {
        uint32_t a[4], b[4][4];
        ldsm4(a, qB + (uint32_t)(((warp * 16 + lrow) * 40 + ks * 16 + lk * 8) * 2));
#pragma unroll
        for (int nt = 0; nt < 4; nt++)
            ldsm4(b[nt], kB + (uint32_t)(((nt * 16 + lrow) * 40 + ks * 16 + lk * 8) * 2));
#pragma unroll
        for (int n8 = 0; n8 < 8; n8++)
            mma16(accS[n8], a, b[n8 >> 1][n8 & 1], b[n8 >> 1][(n8 & 1) + 2]);
    }

    const int w = bw & 63;
    const float* cmbF = g_cmb + (((size_t)w * 16 + h) << 12);
    const int i0 = warp * 16 + gid;
    const float rq0 = sRq[i0], rq1 = sRq[i0 + 8];
#pragma unroll
    for (int n8 = 0; n8 < 8; n8++) {
        int j = n8 * 8 + tig * 2;
        float rk0 = sRk[j], rk1 = sRk[j + 1];
        float2 b0 = *(const float2*)(cmbF + i0 * 64 + j);
        float2 b1 = *(const float2*)(cmbF + (i0 + 8) * 64 + j);
        accS[n8][0] = accS[n8][0] * rq0 * rk0 + b0.x;
        accS[n8][1] = accS[n8][1] * rq0 * rk1 + b0.y;
        accS[n8][2] = accS[n8][2] * rq1 * rk0 + b1.x;
        accS[n8][3] = accS[n8][3] * rq1 * rk1 + b1.y;
    }

    float m0 = -1e30f, m1 = -1e30f;
#pragma unroll
    for (int n8 = 0; n8 < 8; n8++) {
        m0 = fmaxf(m0, fmaxf(accS[n8][0], accS[n8][1]));
        m1 = fmaxf(m1, fmaxf(accS[n8][2], accS[n8][3]));
    }
    m0 = fmaxf(m0, __shfl_xor_sync(0xffffffffu, m0, 1));
    m0 = fmaxf(m0, __shfl_xor_sync(0xffffffffu, m0, 2));
    m1 = fmaxf(m1, __shfl_xor_sync(0xffffffffu, m1, 1));
    m1 = fmaxf(m1, __shfl_xor_sync(0xffffffffu, m1, 2));
    float s0 = 0.f, s1 = 0.f;
#pragma unroll
    for (int n8 = 0; n8 < 8; n8++) {
        accS[n8][0] = __expf(accS[n8][0] - m0); s0 += accS[n8][0];
        accS[n8][1] = __expf(accS[n8][1] - m0); s0 += accS[n8][1];
        accS[n8][2] = __expf(accS[n8][2] - m1); s1 += accS[n8][2];
        accS[n8][3] = __expf(accS[n8][3] - m1); s1 += accS[n8][3];
    }
    s0 += __shfl_xor_sync(0xffffffffu, s0, 1);
    s0 += __shfl_xor_sync(0xffffffffu, s0, 2);
    s1 += __shfl_xor_sync(0xffffffffu, s1, 1);
    s1 += __shfl_xor_sync(0xffffffffu, s1, 2);
    float r0 = 1.0f / s0, r1 = 1.0f / s1;

    uint32_t pk0[8], pk1[8];
#pragma unroll
    for (int n8 = 0; n8 < 8; n8++) {
        pk0[n8] = packh2(accS[n8][0] * r0, accS[n8][1] * r0);
        pk1[n8] = packh2(accS[n8][2] * r1, accS[n8][3] * r1);
    }

    float accO[4][4];
#pragma unroll
    for (int j = 0; j < 4; j++)
#pragma unroll
        for (int k = 0; k < 4; k++) accO[j][k] = 0.f;

#pragma unroll
    for (int kb = 0; kb < 4; kb++) {
        uint32_t aP[4] = { pk0[2 * kb], pk1[2 * kb], pk0[2 * kb + 1], pk1[2 * kb + 1] };
#pragma unroll
        for (int dt = 0; dt < 2; dt++) {
            uint32_t vb[4];
            int vr = kb * 16 + ((lane >> 4) << 3) + (lane & 7);
            int vc = dt * 16 + ((lane >> 3) & 1) * 8;
            ldsm4t(vb, vB + (uint32_t)((vr * 40 + vc) * 2));
            mma16(accO[2 * dt],     aP, vb[0], vb[2]);
            mma16(accO[2 * dt + 1], aP, vb[1], vb[3]);
        }
    }

#pragma unroll
    for (int n8 = 0; n8 < 4; n8++) {
        int d = n8 * 8 + tig * 2;
        size_t o0 = (size_t)(bw * 64 + i0) * 512 + h * 32 + d;
        __half2 h0 = __floats2half2_rn(accO[n8][0], accO[n8][1]);
        __half2 h1 = __floats2half2_rn(accO[n8][2], accO[n8][3]);
        *(__half2*)(outp + o0)            = h0;
        *(__half2*)(outp + o0 + 8 * 512)  = h1;
    }
}

// ---------------- LayerNorm: warp-per-token ----------------
__global__ __launch_bounds__(256)
void ln1_kernel(const float4* __restrict__ proj, const float4* __restrict__ x,
                const float4* __restrict__ gma, const float4* __restrict__ bta,
                float4* __restrict__ x1o, uint2* __restrict__ x1h) {
    const int m = blockIdx.x * 8 + (threadIdx.x >> 5);
    const int lane = threadIdx.x & 31;
    const size_t pb = (size_t)m * 128 + lane;

    float4 v[4];
    float sum = 0.f;
#pragma unroll
    for (int j = 0; j < 4; j++) {
        v[j] = proj[pb + j * 32];
        sum += (v[j].x + v[j].y) + (v[j].z + v[j].w);
    }
#pragma unroll
    for (int o = 16; o; o >>= 1) sum += __shfl_xor_sync(0xffffffffu, sum, o);
    const float mean = sum * (1.0f / 512.0f);

    float vs = 0.f;
#pragma unroll
    for (int j = 0; j < 4; j++) {
        v[j].x -= mean; v[j].y -= mean; v[j].z -= mean; v[j].w -= mean;
        vs += (v[j].x * v[j].x + v[j].y * v[j].y) + (v[j].z * v[j].z + v[j].w * v[j].w);
    }
#pragma unroll
    for (int o = 16; o; o >>= 1) vs += __shfl_xor_sync(0xffffffffu, vs, o);
    const float inv = rsqrtf(vs * (1.0f / 512.0f) + 1e-5f);

    const int g = win2glob(m);
    const size_t gb = (size_t)g * 128 + lane;
#pragma unroll
    for (int j = 0; j < 4; j++) {
        float4 xm = x[gb + j * 32];
        float4 gm = gma[lane + j * 32];
        float4 bt = bta[lane + j * 32];
        float4 r;
        r.x = xm.x + v[j].x * inv * gm.x + bt.x;
        r.y = xm.y + v[j].y * inv * gm.y + bt.y;
        r.z = xm.z + v[j].z * inv * gm.z + bt.z;
        r.w = xm.w + v[j].w * inv * gm.w + bt.w;
        x1o[gb + j * 32] = r;
        uint2 u; u.x = packh2(r.x, r.y); u.y = packh2(r.z, r.w);
        x1h[gb + j * 32] = u;
    }
}

__global__ __launch_bounds__(256)
void ln2_kernel(const float4* __restrict__ mlp, const float4* __restrict__ x1,
                const float4* __restrict__ gma, const float4* __restrict__ bta,
                float4* __restrict__ outp) {
    const int m = blockIdx.x * 8 + (threadIdx.x >> 5);
    const int lane = threadIdx.x & 31;
    const size_t pb = (size_t)m * 128 + lane;

    float4 v[4];
    float sum = 0.f;
#pragma unroll
    for (int j = 0; j < 4; j++) {
        v[j] = mlp[pb + j * 32];
        sum += (v[j].x + v[j].y) + (v[j].z + v[j].w);
    }
#pragma unroll
    for (int o = 16; o; o >>= 1) sum += __shfl_xor_sync(0xffffffffu, sum, o);
    const float mean = sum * (1.0f / 512.0f);

    float vs = 0.f;
#pragma unroll
    for (int j = 0; j < 4; j++) {
        v[j].x -= mean; v[j].y -= mean; v[j].z -= mean; v[j].w -= mean;
        vs += (v[j].x * v[j].x + v[j].y * v[j].y) + (v[j].z * v[j].z + v[j].w * v[j].w);
    }
#pragma unroll
    for (int o = 16; o; o >>= 1) vs += __shfl_xor_sync(0xffffffffu, vs, o);
    const float inv = rsqrtf(vs * (1.0f / 512.0f) + 1e-5f);

#pragma unroll
    for (int j = 0; j < 4; j++) {
        float4 xm = x1[pb + j * 32];
        float4 gm = gma[lane + j * 32];
        float4 bt = bta[lane + j * 32];
        float4 r;
        r.x = xm.x + v[j].x * inv * gm.x + bt.x;
        r.y = xm.y + v[j].y * inv * gm.y + bt.y;
        r.z = xm.z + v[j].z * inv * gm.z + bt.z;
        r.w = xm.w + v[j].w * inv * gm.w + bt.w;
        outp[pb + j * 32] = r;
    }
}

// ---------------- host launcher ----------------
extern "C" void kernel_launch(void* const* d_in, const int* in_sizes, int n_in,
                              void* d_out, int out_size) {
    (void)in_sizes; (void)n_in; (void)out_size;
    const float* x      = (const float*)d_in[0];
    const float* qkv_w  = (const float*)d_in[1];
    const float* q_bias = (const float*)d_in[2];
    const float* v_bias = (const float*)d_in[3];
    const float* lscale = (const float*)d_in[4];
    const float* cpb_w1 = (const float*)d_in[5];
    const float* cpb_b1 = (const float*)d_in[6];
    const float* cpb_w2 = (const float*)d_in[7];
    const float* proj_w = (const float*)d_in[8];
    const float* proj_b = (const float*)d_in[9];
    const float* n1g    = (const float*)d_in[10];
    const float* n1b    = (const float*)d_in[11];
    const float* n2g    = (const float*)d_in[12];
    const float* n2b    = (const float*)d_in[13];
    const float* fc1_w  = (const float*)d_in[14];
    const float* fc1_b  = (const float*)d_in[15];
    const float* fc2_w  = (const float*)d_in[16];
    const float* fc2_b  = (const float*)d_in[17];
    const float* coords = (const float*)d_in[18];
    const float* amask  = (const float*)d_in[19];
    const int*   rpi    = (const int*)d_in[20];
    float*       out    = (float*)d_out;

    float  *p_proj, *p_x1, *p_mlp;
    __half *p_qkv, *p_xh, *p_attnh, *p_x1h, *p_hid, *p_wqkv, *p_wproj, *p_wfc1, *p_wfc2;
    cudaGetSymbolAddress((void**)&p_qkv,   g_qkvh);
    cudaGetSymbolAddress((void**)&p_proj,  g_proj);
    cudaGetSymbolAddress((void**)&p_x1,    g_x1);
    cudaGetSymbolAddress((void**)&p_mlp,   g_mlp);
    cudaGetSymbolAddress((void**)&p_xh,    g_xh);
    cudaGetSymbolAddress((void**)&p_attnh, g_attnh);
    cudaGetSymbolAddress((void**)&p_x1h,   g_x1h);
    cudaGetSymbolAddress((void**)&p_hid,   g_hid);
    cudaGetSymbolAddress((void**)&p_wqkv,  g_wqkv);
    cudaGetSymbolAddress((void**)&p_wproj, g_wproj);
    cudaGetSymbolAddress((void**)&p_wfc1,  g_wfc1);
    cudaGetSymbolAddress((void**)&p_wfc2,  g_wfc2);

    cudaFuncSetAttribute(gemm_ca<512,  EpiQKVh>, cudaFuncAttributeMaxDynamicSharedMemorySize, GSMEM);
    cudaFuncSetAttribute(gemm_ca<512,  EpiBias>, cudaFuncAttributeMaxDynamicSharedMemorySize, GSMEM);
    cudaFuncSetAttribute(gemm_ca<512,  EpiGelu>, cudaFuncAttributeMaxDynamicSharedMemorySize, GSMEM);
    cudaFuncSetAttribute(gemm_ca<2048, EpiBias>, cudaFuncAttributeMaxDynamicSharedMemorySize, GSMEM);

    // side streams + events (created once; reused every call — same work each call)
    static cudaStream_t sA = nullptr, sB = nullptr;
    static cudaEvent_t  ev0 = nullptr, evA = nullptr, evB = nullptr;
    if (!sA) {
        cudaStreamCreateWithFlags(&sA, cudaStreamNonBlocking);
        cudaStreamCreateWithFlags(&sB, cudaStreamNonBlocking);
        cudaEventCreateWithFlags(&ev0, cudaEventDisableTiming);
        cudaEventCreateWithFlags(&evA, cudaEventDisableTiming);
        cudaEventCreateWithFlags(&evB, cudaEventDisableTiming);
    }
    const cudaStream_t s0 = (cudaStream_t)0;

    // segment sizes (float4 counts)
    const int n4_x    = Tt * 512 / 4;
    const int n4_qkvw = 1536 * 512 / 4;
    const int n4_proj = 512 * 512 / 4;
    const int n4_fc1  = 2048 * 512 / 4;
    const int n4_fc2  = 512 * 2048 / 4;
    const int m0b = (n4_x + 255) / 256;
    const int m1b = m0b + (n4_qkvw + 255) / 256;
    const int w0b = (n4_proj + 255) / 256;
    const int w1b = w0b + (n4_fc1 + 255) / 256;
    const int w2b = w1b + (n4_fc2 + 255) / 256;

    // fork
    cudaEventRecord(ev0, s0);
    cudaStreamWaitEvent(sA, ev0, 0);
    cudaStreamWaitEvent(sB, ev0, 0);

    // side stream A: convert proj/fc1/fc2 weights (needed only after attention)
    cvt_batch3<<<w2b, 256, 0, sA>>>(
        CvtSeg{proj_w, p_wproj, n4_proj}, CvtSeg{fc1_w, p_wfc1, n4_fc1},
        CvtSeg{fc2_w, p_wfc2, n4_fc2}, w0b, w1b);
    cudaEventRecord(evA, sA);

    // side stream B: CPB table + combined bias/mask (needed by attention)
    cpb_kernel<<<225, 512, 0, sB>>>(coords, cpb_w1, cpb_b1, cpb_w2);
    cmb_kernel<<<1024, 256, 0, sB>>>(rpi, amask);
    cudaEventRecord(evB, sB);

    // main stream: x + qkv_w conversion, then QKV GEMM
    cvt_batch3<<<m1b, 256>>>(
        CvtSeg{x, p_xh, n4_x}, CvtSeg{qkv_w, p_wqkv, n4_qkvw},
        CvtSeg{nullptr, nullptr, 0}, m0b, m1b);
    gemm_ca<512><<<dim3(6, 512), 512, GSMEM>>>(p_xh, p_wqkv, EpiQKVh{p_qkv, q_bias, v_bias});

    // join B before attention
    cudaStreamWaitEvent(s0, evB, 0);
    attn_mma<<<dim3(1024, 16), 128>>>(p_qkv, lscale, p_attnh);

    // join A before proj GEMM
    cudaStreamWaitEvent(s0, evA, 0);
    gemm_ca<512><<<dim3(2, 512), 512, GSMEM>>>(p_attnh, p_wproj, EpiBias{p_proj, proj_b, 512});
    ln1_kernel<<<Tt / 8, 256>>>((const float4*)p_proj, (const float4*)x,
                                (const float4*)n1g, (const float4*)n1b,
                                (float4*)p_x1, (uint2*)p_x1h);
    gemm_ca<512><<<dim3(8, 512), 512, GSMEM>>>(p_x1h, p_wfc1, EpiGelu{p_hid, fc1_b});
    gemm_ca<2048><<<dim3(2, 512), 512, GSMEM>>>(p_hid, p_wfc2, EpiBias{p_mlp, fc2_b, 512});
    ln2_kernel<<<Tt / 8, 256>>>((const float4*)p_mlp, (const float4*)p_x1,
                                (const float4*)n2g, (const float4*)n2b,
                                (float4*)out);
}

// round 15
// speedup vs baseline: 1.1802x; 1.0753x over previous
#include <cuda_runtime.h>
#include <cuda_fp16.h>
#include <cstdint>
#include <math.h>

// ---------------- problem constants ----------------
#define BSZ   16
#define Hh    64
#define Ww    64
#define Cc    512
#define HEADS 16
#define WS    8
#define SHIFT 4
#define Ll    (Hh*Ww)
#define Tt    (BSZ*Ll)     // 65536 tokens
#define HID   2048

// ---------------- scratch (device globals) ----------------
__device__ __half g_qkvh [(size_t)Tt * 1536];
__device__ __half g_xh   [(size_t)Tt * Cc];
__device__ __half g_attnh[(size_t)Tt * Cc];
__device__ float  g_proj [(size_t)Tt * Cc];
__device__ float  g_x1   [(size_t)Tt * Cc];
__device__ __half g_x1h  [(size_t)Tt * Cc];
__device__ __half g_hid  [(size_t)Tt * HID];
__device__ float  g_mlp  [(size_t)Tt * Cc];
__device__ float  g_tbl  [225 * HEADS];
__device__ float  g_cmb  [64 * 16 * 4096];
__device__ __half g_wqkv [1536 * 512];
__device__ __half g_wproj[512 * 512];
__device__ __half g_wfc1 [2048 * 512];
__device__ __half g_wfc2 [512 * 2048];

// ---------------- helpers ----------------
__device__ __forceinline__ void mma16(float* d, const uint32_t* a, uint32_t b0, uint32_t b1) {
    asm volatile(
        "mma.sync.aligned.m16n8k16.row.col.f32.f16.f16.f32 "
        "{%0,%1,%2,%3}, {%4,%5,%6,%7}, {%8,%9}, {%0,%1,%2,%3};\n"
        : "+f"(d[0]), "+f"(d[1]), "+f"(d[2]), "+f"(d[3])
        : "r"(a[0]), "r"(a[1]), "r"(a[2]), "r"(a[3]), "r"(b0), "r"(b1));
}
__device__ __forceinline__ void ldsm4(uint32_t* r, uint32_t addr) {
    asm volatile("ldmatrix.sync.aligned.m8n8.x4.shared.b16 {%0,%1,%2,%3}, [%4];"
                 : "=r"(r[0]), "=r"(r[1]), "=r"(r[2]), "=r"(r[3]) : "r"(addr));
}
__device__ __forceinline__ void ldsm4t(uint32_t* r, uint32_t addr) {
    asm volatile("ldmatrix.sync.aligned.m8n8.x4.trans.shared.b16 {%0,%1,%2,%3}, [%4];"
                 : "=r"(r[0]), "=r"(r[1]), "=r"(r[2]), "=r"(r[3]) : "r"(addr));
}
__device__ __forceinline__ void cpasync16(uint32_t dst, const void* src) {
    asm volatile("cp.async.cg.shared.global [%0], [%1], 16;" :: "r"(dst), "l"(src) : "memory");
}
__device__ __forceinline__ uint32_t smem_u32(const void* p) {
    uint32_t a;
    asm("{ .reg .u64 t; cvta.to.shared.u64 t, %1; cvt.u32.u64 %0, t; }" : "=r"(a) : "l"(p));
    return a;
}
__device__ __forceinline__ uint32_t packh2(float a, float b) {
    __half2 h = __floats2half2_rn(a, b);
    return *(uint32_t*)&h;
}

__device__ __forceinline__ int win2glob(int m) {
    int bw = m >> 6, n = m & 63;
    int b = bw >> 6, w = bw & 63;
    int y = (((w >> 3) << 3) + (n >> 3) + SHIFT) & 63;
    int x = (((w & 7) << 3) + (n & 7) + SHIFT) & 63;
    return (b << 12) | (y << 6) | x;
}

// ---------------- epilogue functors ----------------
struct EpiQKVh {
    __half* out; const float* qb; const float* vb;
    __device__ __forceinline__ void operator()(int m, int c, float v0, float v1) const {
        if (c < 512)       { v0 += qb[c]; v1 += qb[c + 1]; }
        else if (c >= 1024){ v0 += vb[c - 1024]; v1 += vb[c - 1023]; }
        *(__half2*)(out + (size_t)m * 1536 + c) = __floats2half2_rn(v0, v1);
    }
};
struct EpiBias {
    float* out; const float* b; int ldc;
    __device__ __forceinline__ void operator()(int m, int c, float v0, float v1) const {
        float2 r; r.x = v0 + b[c]; r.y = v1 + b[c + 1];
        *(float2*)(out + (size_t)m * ldc + c) = r;
    }
};
struct EpiGelu {
    __half* out; const float* b;
    __device__ __forceinline__ void operator()(int m, int c, float v0, float v1) const {
        v0 += b[c];     v0 = 0.5f * v0 * (1.0f + erff(v0 * 0.70710678118654752f));
        v1 += b[c + 1]; v1 = 0.5f * v1 * (1.0f + erff(v1 * 0.70710678118654752f));
        *(__half2*)(out + (size_t)m * HID + c) = __floats2half2_rn(v0, v1);
    }
};

// ---------------- fp16 mma.sync GEMM: 128x256 tile, 1024 threads (32 warps, 8/SMSP),
// ---------------- warp tile 32x32, 3-stage cp.async ----------------
#define BKk     64
#define STG_A   (128 * BKk * 2)
#define STG_B   (256 * BKk * 2)
#define STG     (STG_A + STG_B)
#define GSMEM   (3 * STG)

template <int K, class Epi>
__global__ __launch_bounds__(1024, 1)
void gemm_ca(const __half* __restrict__ A, const __half* __restrict__ B, Epi epi) {
    extern __shared__ __align__(16) char sm[];
    const uint32_t smBase = smem_u32(sm);

    const int tid  = threadIdx.x;
    const int lane = tid & 31, warp = tid >> 5;      // 32 warps
    const int gid  = lane >> 2, tig = lane & 3;
    const int lrow = lane & 15, lk = lane >> 4;
    const int wm   = warp >> 3, wn = warp & 7;        // 4m x 8n, warp tile 32x32
    const int m0   = blockIdx.y << 7;                 // 128-row tile
    const int n0   = blockIdx.x << 8;                 // 256-col tile
    const int NT   = K / BKk;

    // cp.async: A 1024 units -> 1/thread; B 2048 units -> 2/thread
    uint32_t aOff, sDstA;
    {
        int r = tid >> 3, c = tid & 7;
        aOff  = (uint32_t)(m0 + r) * (uint32_t)K + (uint32_t)(c * 8);
        sDstA = (uint32_t)((r * 8 + (c ^ (r & 7))) * 16);
    }
    uint32_t bOff[2], sDstB[2];
#pragma unroll
    for (int i = 0; i < 2; i++) {
        int u = tid * 2 + i, r = u >> 3, c = u & 7;
        bOff[i]  = (uint32_t)(n0 + r) * (uint32_t)K + (uint32_t)(c * 8);
        sDstB[i] = (uint32_t)(STG_A + (r * 8 + (c ^ (r & 7))) * 16);
    }

    int aR8[2], aSW[2], bR8[2], bSW[2];
#pragma unroll
    for (int t = 0; t < 2; t++) {
        int ra = wm * 32 + t * 16 + lrow;
        aR8[t] = ra * 8; aSW[t] = ra & 7;
        int rb = wn * 32 + t * 16 + lrow;
        bR8[t] = rb * 8; bSW[t] = rb & 7;
    }

    float acc[2][4][4];
#pragma unroll
    for (int i = 0; i < 2; i++)
#pragma unroll
        for (int j = 0; j < 4; j++)
#pragma unroll
            for (int k = 0; k < 4; k++) acc[i][j][k] = 0.f;

    auto load_tile = [&](int s, int kt) {
        uint32_t base = smBase + s * STG;
        uint32_t ko = (uint32_t)(kt * BKk);
        cpasync16(base + sDstA, A + aOff + ko);
#pragma unroll
        for (int i = 0; i < 2; i++) cpasync16(base + sDstB[i], B + bOff[i] + ko);
    };

    load_tile(0, 0);
    asm volatile("cp.async.commit_group;" ::: "memory");
    load_tile(1, 1);
    asm volatile("cp.async.commit_group;" ::: "memory");

    for (int kt = 0; kt < NT; kt++) {
        const int s = kt % 3;
        asm volatile("cp.async.wait_group 1;" ::: "memory");
        __syncthreads();
        if (kt + 2 < NT) load_tile((kt + 2) % 3, kt + 2);
        asm volatile("cp.async.commit_group;" ::: "memory");

        uint32_t sA = smBase + s * STG;
        uint32_t sB = sA + STG_A;
#pragma unroll
        for (int ks = 0; ks < 4; ks++) {
            uint32_t a[2][4], b[2][4];
#pragma unroll
            for (int mt = 0; mt < 2; mt++)
                ldsm4(a[mt], sA + (uint32_t)((aR8[mt] + ((ks * 2 + lk) ^ aSW[mt])) * 16));
#pragma unroll
            for (int nt = 0; nt < 2; nt++)
                ldsm4(b[nt], sB + (uint32_t)((bR8[nt] + ((ks * 2 + lk) ^ bSW[nt])) * 16));
#pragma unroll
            for (int mt = 0; mt < 2; mt++)
#pragma unroll
                for (int n8 = 0; n8 < 4; n8++)
                    mma16(acc[mt][n8], a[mt], b[n8 >> 1][n8 & 1], b[n8 >> 1][(n8 & 1) + 2]);
        }
    }

    // epilogue
#pragma unroll
    for (int mt = 0; mt < 2; mt++)
#pragma unroll
        for (int n8 = 0; n8 < 4; n8++) {
            int r = m0 + wm * 32 + mt * 16 + gid;
            int c = n0 + wn * 32 + n8 * 8 + tig * 2;
            epi(r,     c, acc[mt][n8][0], acc[mt][n8][1]);
            epi(r + 8, c, acc[mt][n8][2], acc[mt][n8][3]);
        }
}

// ---------------- batched fp32 -> fp16 convert (3 segments) ----------------
struct CvtSeg { const float* src; __half* dst; int n4; };

__global__ __launch_bounds__(256)
void cvt_batch3(CvtSeg s0, CvtSeg s1, CvtSeg s2, int c0, int c1) {
    int blk = blockIdx.x;
    CvtSeg s;
    int base;
    if      (blk < c0) { s = s0; base = blk; }
    else if (blk < c1) { s = s1; base = blk - c0; }
    else               { s = s2; base = blk - c1; }
    int i = base * 256 + threadIdx.x;
    if (i < s.n4) {
        float4 v = ((const float4*)s.src)[i];
        uint2 u;
        u.x = packh2(v.x, v.y);
        u.y = packh2(v.z, v.w);
        ((uint2*)s.dst)[i] = u;
    }
}

// ---------------- CPB MLP ----------------
__global__ __launch_bounds__(512) void cpb_kernel(const float* __restrict__ ct,
                                                  const float* __restrict__ w1,
                                                  const float* __restrict__ b1,
                                                  const float* __restrict__ w2) {
    __shared__ float hid[512];
    int p = blockIdx.x;
    float c0 = ct[p * 2 + 0], c1 = ct[p * 2 + 1];
    int t = threadIdx.x;
    hid[t] = fmaxf(c0 * w1[t * 2 + 0] + c1 * w1[t * 2 + 1] + b1[t], 0.f);
    __syncthreads();
    int lane = t & 31, h = t >> 5;
    float s = 0.f;
    for (int k = lane; k < 512; k += 32) s += w2[h * 512 + k] * hid[k];
#pragma unroll
    for (int o = 16; o; o >>= 1) s += __shfl_xor_sync(0xffffffffu, s, o);
    if (lane == 0) g_tbl[p * 16 + h] = 16.0f / (1.0f + __expf(-s));
}

// ---------------- combined bias+mask table ----------------
__global__ __launch_bounds__(256)
void cmb_kernel(const int* __restrict__ rpi, const float* __restrict__ am) {
    int wh = blockIdx.x;
    int w = wh >> 4, h = wh & 15;
#pragma unroll
    for (int e = 0; e < 16; e++) {
        int ij = threadIdx.x + e * 256;
        g_cmb[((size_t)wh << 12) + ij] = g_tbl[rpi[ij] * 16 + h] + am[(size_t)w * 4096 + ij];
    }
}

// ---------------- attention ----------------
__global__ __launch_bounds__(128)
void attn_mma(const __half* __restrict__ qkv, const float* __restrict__ ls,
              __half* __restrict__ outp) {
    __shared__ __align__(16) __half sQ[64][40];
    __shared__ __align__(16) __half sK[64][40];
    __shared__ __align__(16) __half sV[64][40];
    __shared__ float sRq[64];
    __shared__ float sRk[64];

    const int bw = blockIdx.x, h = blockIdx.y;
    const int tid = threadIdx.x;
    const int lane = tid & 31, warp = tid >> 5;
    const int gid = lane >> 2, tig = lane & 3;
    const int lrow = lane & 15, lk = lane >> 4;

#pragma unroll
    for (int i = 0; i < 2; i++) {
        int u = tid * 2 + i;
        int r = u >> 2, c = u & 3;
        int g = win2glob(bw * 64 + r);
        const __half* src = qkv + (size_t)g * 1536 + h * 32 + c * 8;
        *(uint4*)&sQ[r][c * 8] = *(const uint4*)(src);
        *(uint4*)&sK[r][c * 8] = *(const uint4*)(src + 512);
        *(uint4*)&sV[r][c * 8] = *(const uint4*)(src + 1024);
    }
    __syncthreads();

    const float scale = __expf(fminf(ls[h], 4.6051701859880914f));

    {
        int r = tid >> 1, seg = (tid & 1) * 16;
        float sq = 0.f, sk = 0.f;
#pragma unroll
        for (int d = 0; d < 16; d++) {
            float qv = __half2float(sQ[r][seg + d]);
            float kv = __half2float(sK[r][seg + d]);
            sq += qv * qv;
            sk += kv * kv;
        }
        sq += __shfl_xor_sync(0xffffffffu, sq, 1);
        sk += __shfl_xor_sync(0xffffffffu, sk, 1);
        if ((tid & 1) == 0) {
            sRq[r] = scale / fmaxf(sqrtf(sq), 1e-12f);
            sRk[r] = 1.0f  / fmaxf(sqrtf(sk), 1e-12f);
        }
    }
    __syncthreads();

    const uint32_t qB = smem_u32(&sQ[0][0]);
    const uint32_t kB = smem_u32(&sK[0][0]);
    const uint32_t vB = smem_u32(&sV[0][0]);

    float accS[8][4];
#pragma unroll
    for (int j = 0; j < 8; j++)
#pragma unroll
        for (int k = 0; k < 4; k++) accS[j][k] = 0.f;

#pragma unroll
    for (int ks = 0; ks < 2; ks++) {
        uint32_t a[4], b[4][4];
        ldsm4(a, qB + (uint32_t)(((warp * 16 + lrow) * 40 + ks * 16 + lk * 8) * 2));
#pragma unroll
        for (int nt = 0; nt < 4; nt++)
            ldsm4(b[nt], kB + (uint32_t)(((nt * 16 + lrow) * 40 + ks * 16 + lk * 8) * 2));
#pragma unroll
        for (int n8 = 0; n8 < 8; n8++)
            mma16(accS[n8], a, b[n8 >> 1][n8 & 1], b[n8 >> 1][(n8 & 1) + 2]);
    }

    const int w = bw & 63;
    const float* cmbF = g_cmb + (((size_t)w * 16 + h) << 12);
    const int i0 = warp * 16 + gid;
    const float rq0 = sRq[i0], rq1 = sRq[i0 + 8];
#pragma unroll
    for (int n8 = 0; n8 < 8; n8++) {
        int j = n8 * 8 + tig * 2;
        float rk0 = sRk[j], rk1 = sRk[j + 1];
        float2 b0 = *(const float2*)(cmbF + i0 * 64 + j);
        float2 b1 = *(const float2*)(cmbF + (i0 + 8) * 64 + j);
        accS[n8][0] = accS[n8][0] * rq0 * rk0 + b0.x;
        accS[n8][1] = accS[n8][1] * rq0 * rk1 + b0.y;
        accS[n8][2] = accS[n8][2] * rq1 * rk0 + b1.x;
        accS[n8][3] = accS[n8][3] * rq1 * rk1 + b1.y;
    }

    float m0 = -1e30f, m1 = -1e30f;
#pragma unroll
    for (int n8 = 0; n8 < 8; n8++) {
        m0 = fmaxf(m0, fmaxf(accS[n8][0], accS[n8][1]));
        m1 = fmaxf(m1, fmaxf(accS[n8][2], accS[n8][3]));
    }
    m0 = fmaxf(m0, __shfl_xor_sync(0xffffffffu, m0, 1));
    m0 = fmaxf(m0, __shfl_xor_sync(0xffffffffu, m0, 2));
    m1 = fmaxf(m1, __shfl_xor_sync(0xffffffffu, m1, 1));
    m1 = fmaxf(m1, __shfl_xor_sync(0xffffffffu, m1, 2));
    float s0 = 0.f, s1 = 0.f;
#pragma unroll
    for (int n8 = 0; n8 < 8; n8++) {
        accS[n8][0] = __expf(accS[n8][0] - m0); s0 += accS[n8][0];
        accS[n8][1] = __expf(accS[n8][1] - m0); s0 += accS[n8][1];
        accS[n8][2] = __expf(accS[n8][2] - m1); s1 += accS[n8][2];
        accS[n8][3] = __expf(accS[n8][3] - m1); s1 += accS[n8][3];
    }
    s0 += __shfl_xor_sync(0xffffffffu, s0, 1);
    s0 += __shfl_xor_sync(0xffffffffu, s0, 2);
    s1 += __shfl_xor_sync(0xffffffffu, s1, 1);
    s1 += __shfl_xor_sync(0xffffffffu, s1, 2);
    float r0 = 1.0f / s0, r1 = 1.0f / s1;

    uint32_t pk0[8], pk1[8];
#pragma unroll
    for (int n8 = 0; n8 < 8; n8++) {
        pk0[n8] = packh2(accS[n8][0] * r0, accS[n8][1] * r0);
        pk1[n8] = packh2(accS[n8][2] * r1, accS[n8][3] * r1);
    }

    float accO[4][4];
#pragma unroll
    for (int j = 0; j < 4; j++)
#pragma unroll
        for (int k = 0; k < 4; k++) accO[j][k] = 0.f;

#pragma unroll
    for (int kb = 0; kb < 4; kb++) {
        uint32_t aP[4] = { pk0[2 * kb], pk1[2 * kb], pk0[2 * kb + 1], pk1[2 * kb + 1] };
#pragma unroll
        for (int dt = 0; dt < 2; dt++) {
            uint32_t vb[4];
            int vr = kb * 16 + ((lane >> 4) << 3) + (lane & 7);
            int vc = dt * 16 + ((lane >> 3) & 1) * 8;
            ldsm4t(vb, vB + (uint32_t)((vr * 40 + vc) * 2));
            mma16(accO[2 * dt],     aP, vb[0], vb[2]);
            mma16(accO[2 * dt + 1], aP, vb[1], vb[3]);
        }
    }

#pragma unroll
    for (int n8 = 0; n8 < 4; n8++) {
        int d = n8 * 8 + tig * 2;
        size_t o0 = (size_t)(bw * 64 + i0) * 512 + h * 32 + d;
        __half2 h0 = __floats2half2_rn(accO[n8][0], accO[n8][1]);
        __half2 h1 = __floats2half2_rn(accO[n8][2], accO[n8][3]);
        *(__half2*)(outp + o0)            = h0;
        *(__half2*)(outp + o0 + 8 * 512)  = h1;
    }
}

// ---------------- LayerNorm: warp-per-token ----------------
__global__ __launch_bounds__(256)
void ln1_kernel(const float4* __restrict__ proj, const float4* __restrict__ x,
                const float4* __restrict__ gma, const float4* __restrict__ bta,
                float4* __restrict__ x1o, uint2* __restrict__ x1h) {
    const int m = blockIdx.x * 8 + (threadIdx.x >> 5);
    const int lane = threadIdx.x & 31;
    const size_t pb = (size_t)m * 128 + lane;

    float4 v[4];
    float sum = 0.f;
#pragma unroll
    for (int j = 0; j < 4; j++) {
        v[j] = proj[pb + j * 32];
        sum += (v[j].x + v[j].y) + (v[j].z + v[j].w);
    }
#pragma unroll
    for (int o = 16; o; o >>= 1) sum += __shfl_xor_sync(0xffffffffu, sum, o);
    const float mean = sum * (1.0f / 512.0f);

    float vs = 0.f;
#pragma unroll
    for (int j = 0; j < 4; j++) {
        v[j].x -= mean; v[j].y -= mean; v[j].z -= mean; v[j].w -= mean;
        vs += (v[j].x * v[j].x + v[j].y * v[j].y) + (v[j].z * v[j].z + v[j].w * v[j].w);
    }
#pragma unroll
    for (int o = 16; o; o >>= 1) vs += __shfl_xor_sync(0xffffffffu, vs, o);
    const float inv = rsqrtf(vs * (1.0f / 512.0f) + 1e-5f);

    const int g = win2glob(m);
    const size_t gb = (size_t)g * 128 + lane;
#pragma unroll
    for (int j = 0; j < 4; j++) {
        float4 xm = x[gb + j * 32];
        float4 gm = gma[lane + j * 32];
        float4 bt = bta[lane + j * 32];
        float4 r;
        r.x = xm.x + v[j].x * inv * gm.x + bt.x;
        r.y = xm.y + v[j].y * inv * gm.y + bt.y;
        r.z = xm.z + v[j].z * inv * gm.z + bt.z;
        r.w = xm.w + v[j].w * inv * gm.w + bt.w;
        x1o[gb + j * 32] = r;
        uint2 u; u.x = packh2(r.x, r.y); u.y = packh2(r.z, r.w);
        x1h[gb + j * 32] = u;
    }
}

__global__ __launch_bounds__(256)
void ln2_kernel(const float4* __restrict__ mlp, const float4* __restrict__ x1,
                const float4* __restrict__ gma, const float4* __restrict__ bta,
                float4* __restrict__ outp) {
    const int m = blockIdx.x * 8 + (threadIdx.x >> 5);
    const int lane = threadIdx.x & 31;
    const size_t pb = (size_t)m * 128 + lane;

    float4 v[4];
    float sum = 0.f;
#pragma unroll
    for (int j = 0; j < 4; j++) {
        v[j] = mlp[pb + j * 32];
        sum += (v[j].x + v[j].y) + (v[j].z + v[j].w);
    }
#pragma unroll
    for (int o = 16; o; o >>= 1) sum += __shfl_xor_sync(0xffffffffu, sum, o);
    const float mean = sum * (1.0f / 512.0f);

    float vs = 0.f;
#pragma unroll
    for (int j = 0; j < 4; j++) {
        v[j].x -= mean; v[j].y -= mean; v[j].z -= mean; v[j].w -= mean;
        vs += (v[j].x * v[j].x + v[j].y * v[j].y) + (v[j].z * v[j].z + v[j].w * v[j].w);
    }
#pragma unroll
    for (int o = 16; o; o >>= 1) vs += __shfl_xor_sync(0xffffffffu, vs, o);
    const float inv = rsqrtf(vs * (1.0f / 512.0f) + 1e-5f);

#pragma unroll
    for (int j = 0; j < 4; j++) {
        float4 xm = x1[pb + j * 32];
        float4 gm = gma[lane + j * 32];
        float4 bt = bta[lane + j * 32];
        float4 r;
        r.x = xm.x + v[j].x * inv * gm.x + bt.x;
        r.y = xm.y + v[j].y * inv * gm.y + bt.y;
        r.z = xm.z + v[j].z * inv * gm.z + bt.z;
        r.w = xm.w + v[j].w * inv * gm.w + bt.w;
        outp[pb + j * 32] = r;
    }
}

// ---------------- host launcher ----------------
extern "C" void kernel_launch(void* const* d_in, const int* in_sizes, int n_in,
                              void* d_out, int out_size) {
    (void)in_sizes; (void)n_in; (void)out_size;
    const float* x      = (const float*)d_in[0];
    const float* qkv_w  = (const float*)d_in[1];
    const float* q_bias = (const float*)d_in[2];
    const float* v_bias = (const float*)d_in[3];
    const float* lscale = (const float*)d_in[4];
    const float* cpb_w1 = (const float*)d_in[5];
    const float* cpb_b1 = (const float*)d_in[6];
    const float* cpb_w2 = (const float*)d_in[7];
    const float* proj_w = (const float*)d_in[8];
    const float* proj_b = (const float*)d_in[9];
    const float* n1g    = (const float*)d_in[10];
    const float* n1b    = (const float*)d_in[11];
    const float* n2g    = (const float*)d_in[12];
    const float* n2b    = (const float*)d_in[13];
    const float* fc1_w  = (const float*)d_in[14];
    const float* fc1_b  = (const float*)d_in[15];
    const float* fc2_w  = (const float*)d_in[16];
    const float* fc2_b  = (const float*)d_in[17];
    const float* coords = (const float*)d_in[18];
    const float* amask  = (const float*)d_in[19];
    const int*   rpi    = (const int*)d_in[20];
    float*       out    = (float*)d_out;

    float  *p_proj, *p_x1, *p_mlp;
    __half *p_qkv, *p_xh, *p_attnh, *p_x1h, *p_hid, *p_wqkv, *p_wproj, *p_wfc1, *p_wfc2;
    cudaGetSymbolAddress((void**)&p_qkv,   g_qkvh);
    cudaGetSymbolAddress((void**)&p_proj,  g_proj);
    cudaGetSymbolAddress((void**)&p_x1,    g_x1);
    cudaGetSymbolAddress((void**)&p_mlp,   g_mlp);
    cudaGetSymbolAddress((void**)&p_xh,    g_xh);
    cudaGetSymbolAddress((void**)&p_attnh, g_attnh);
    cudaGetSymbolAddress((void**)&p_x1h,   g_x1h);
    cudaGetSymbolAddress((void**)&p_hid,   g_hid);
    cudaGetSymbolAddress((void**)&p_wqkv,  g_wqkv);
    cudaGetSymbolAddress((void**)&p_wproj, g_wproj);
    cudaGetSymbolAddress((void**)&p_wfc1,  g_wfc1);
    cudaGetSymbolAddress((void**)&p_wfc2,  g_wfc2);

    cudaFuncSetAttribute(gemm_ca<512,  EpiQKVh>, cudaFuncAttributeMaxDynamicSharedMemorySize, GSMEM);
    cudaFuncSetAttribute(gemm_ca<512,  EpiBias>, cudaFuncAttributeMaxDynamicSharedMemorySize, GSMEM);
    cudaFuncSetAttribute(gemm_ca<512,  EpiGelu>, cudaFuncAttributeMaxDynamicSharedMemorySize, GSMEM);
    cudaFuncSetAttribute(gemm_ca<2048, EpiBias>, cudaFuncAttributeMaxDynamicSharedMemorySize, GSMEM);

    static cudaStream_t sA = nullptr, sB = nullptr;
    static cudaEvent_t  ev0 = nullptr, evA = nullptr, evB = nullptr;
    if (!sA) {
        cudaStreamCreateWithFlags(&sA, cudaStreamNonBlocking);
        cudaStreamCreateWithFlags(&sB, cudaStreamNonBlocking);
        cudaEventCreateWithFlags(&ev0, cudaEventDisableTiming);
        cudaEventCreateWithFlags(&evA, cudaEventDisableTiming);
        cudaEventCreateWithFlags(&evB, cudaEventDisableTiming);
    }
    const cudaStream_t s0 = (cudaStream_t)0;

    const int n4_x    = Tt * 512 / 4;
    const int n4_qkvw = 1536 * 512 / 4;
    const int n4_proj = 512 * 512 / 4;
    const int n4_fc1  = 2048 * 512 / 4;
    const int n4_fc2  = 512 * 2048 / 4;
    const int m0b = (n4_x + 255) / 256;
    const int m1b = m0b + (n4_qkvw + 255) / 256;
    const int w0b = (n4_proj + 255) / 256;
    const int w1b = w0b + (n4_fc1 + 255) / 256;
    const int w2b = w1b + (n4_fc2 + 255) / 256;

    cudaEventRecord(ev0, s0);
    cudaStreamWaitEvent(sA, ev0, 0);
    cudaStreamWaitEvent(sB, ev0, 0);

    cvt_batch3<<<w2b, 256, 0, sA>>>(
        CvtSeg{proj_w, p_wproj, n4_proj}, CvtSeg{fc1_w, p_wfc1, n4_fc1},
        CvtSeg{fc2_w, p_wfc2, n4_fc2}, w0b, w1b);
    cudaEventRecord(evA, sA);

    cpb_kernel<<<225, 512, 0, sB>>>(coords, cpb_w1, cpb_b1, cpb_w2);
    cmb_kernel<<<1024, 256, 0, sB>>>(rpi, amask);
    cudaEventRecord(evB, sB);

    cvt_batch3<<<m1b, 256>>>(
        CvtSeg{x, p_xh, n4_x}, CvtSeg{qkv_w, p_wqkv, n4_qkvw},
        CvtSeg{nullptr, nullptr, 0}, m0b, m1b);
    gemm_ca<512><<<dim3(6, 512), 1024, GSMEM>>>(p_xh, p_wqkv, EpiQKVh{p_qkv, q_bias, v_bias});

    cudaStreamWaitEvent(s0, evB, 0);
    attn_mma<<<dim3(1024, 16), 128>>>(p_qkv, lscale, p_attnh);

    cudaStreamWaitEvent(s0, evA, 0);
    gemm_ca<512><<<dim3(2, 512), 1024, GSMEM>>>(p_attnh, p_wproj, EpiBias{p_proj, proj_b, 512});
    ln1_kernel<<<Tt / 8, 256>>>((const float4*)p_proj, (const float4*)x,
                                (const float4*)n1g, (const float4*)n1b,
                                (float4*)p_x1, (uint2*)p_x1h);
    gemm_ca<512><<<dim3(8, 512), 1024, GSMEM>>>(p_x1h, p_wfc1, EpiGelu{p_hid, fc1_b});
    gemm_ca<2048><<<dim3(2, 512), 1024, GSMEM>>>(p_hid, p_wfc2, EpiBias{p_mlp, fc2_b, 512});
    ln2_kernel<<<Tt / 8, 256>>>((const float4*)p_mlp, (const float4*)p_x1,
                                (const float4*)n2g, (const float4*)n2b,
                                (float4*)out);
}

// round 16
// speedup vs baseline: 1.2018x; 1.0183x over previous
#include <cuda_runtime.h>
#include <cuda_fp16.h>
#include <cstdint>
#include <math.h>

// ---------------- problem constants ----------------
#define BSZ   16
#define Hh    64
#define Ww    64
#define Cc    512
#define HEADS 16
#define WS    8
#define SHIFT 4
#define Ll    (Hh*Ww)
#define Tt    (BSZ*Ll)     // 65536 tokens
#define HID   2048

// ---------------- scratch (device globals) ----------------
__device__ __half g_qkvh [(size_t)Tt * 1536];
__device__ __half g_xh   [(size_t)Tt * Cc];
__device__ __half g_attnh[(size_t)Tt * Cc];
__device__ float  g_proj [(size_t)Tt * Cc];
__device__ float  g_x1   [(size_t)Tt * Cc];
__device__ __half g_x1h  [(size_t)Tt * Cc];
__device__ __half g_hid  [(size_t)Tt * HID];
__device__ float  g_mlp  [(size_t)Tt * Cc];
__device__ float  g_tbl  [225 * HEADS];
__device__ float  g_cmb  [64 * 16 * 4096];
__device__ __half g_wqkv [1536 * 512];
__device__ __half g_wproj[512 * 512];
__device__ __half g_wfc1 [2048 * 512];
__device__ __half g_wfc2 [512 * 2048];

// ---------------- helpers ----------------
__device__ __forceinline__ void mma16(float* d, const uint32_t* a, uint32_t b0, uint32_t b1) {
    asm volatile(
        "mma.sync.aligned.m16n8k16.row.col.f32.f16.f16.f32 "
        "{%0,%1,%2,%3}, {%4,%5,%6,%7}, {%8,%9}, {%0,%1,%2,%3};\n"
        : "+f"(d[0]), "+f"(d[1]), "+f"(d[2]), "+f"(d[3])
        : "r"(a[0]), "r"(a[1]), "r"(a[2]), "r"(a[3]), "r"(b0), "r"(b1));
}
__device__ __forceinline__ void ldsm4(uint32_t* r, uint32_t addr) {
    asm volatile("ldmatrix.sync.aligned.m8n8.x4.shared.b16 {%0,%1,%2,%3}, [%4];"
                 : "=r"(r[0]), "=r"(r[1]), "=r"(r[2]), "=r"(r[3]) : "r"(addr));
}
__device__ __forceinline__ void ldsm4t(uint32_t* r, uint32_t addr) {
    asm volatile("ldmatrix.sync.aligned.m8n8.x4.trans.shared.b16 {%0,%1,%2,%3}, [%4];"
                 : "=r"(r[0]), "=r"(r[1]), "=r"(r[2]), "=r"(r[3]) : "r"(addr));
}
__device__ __forceinline__ void cpasync16(uint32_t dst, const void* src) {
    asm volatile("cp.async.cg.shared.global [%0], [%1], 16;" :: "r"(dst), "l"(src) : "memory");
}
__device__ __forceinline__ uint32_t smem_u32(const void* p) {
    uint32_t a;
    asm("{ .reg .u64 t; cvta.to.shared.u64 t, %1; cvt.u32.u64 %0, t; }" : "=r"(a) : "l"(p));
    return a;
}
__device__ __forceinline__ uint32_t packh2(float a, float b) {
    __half2 h = __floats2half2_rn(a, b);
    return *(uint32_t*)&h;
}

__device__ __forceinline__ int win2glob(int m) {
    int bw = m >> 6, n = m & 63;
    int b = bw >> 6, w = bw & 63;
    int y = (((w >> 3) << 3) + (n >> 3) + SHIFT) & 63;
    int x = (((w & 7) << 3) + (n & 7) + SHIFT) & 63;
    return (b << 12) | (y << 6) | x;
}

// ---------------- epilogue functors ----------------
struct EpiQKVh {
    __half* out; const float* qb; const float* vb;
    __device__ __forceinline__ void operator()(int m, int c, float v0, float v1) const {
        if (c < 512)       { v0 += qb[c]; v1 += qb[c + 1]; }
        else if (c >= 1024){ v0 += vb[c - 1024]; v1 += vb[c - 1023]; }
        *(__half2*)(out + (size_t)m * 1536 + c) = __floats2half2_rn(v0, v1);
    }
};
struct EpiBias {
    float* out; const float* b; int ldc;
    __device__ __forceinline__ void operator()(int m, int c, float v0, float v1) const {
        float2 r; r.x = v0 + b[c]; r.y = v1 + b[c + 1];
        *(float2*)(out + (size_t)m * ldc + c) = r;
    }
};
struct EpiGelu {
    __half* out; const float* b;
    __device__ __forceinline__ void operator()(int m, int c, float v0, float v1) const {
        v0 += b[c];     v0 = 0.5f * v0 * (1.0f + erff(v0 * 0.70710678118654752f));
        v1 += b[c + 1]; v1 = 0.5f * v1 * (1.0f + erff(v1 * 0.70710678118654752f));
        *(__half2*)(out + (size_t)m * HID + c) = __floats2half2_rn(v0, v1);
    }
};

// ---------------- fp16 mma.sync GEMM: 128x128 tile, 512 threads (16 warps 4x4,
// ---------------- warp tile 32x32), 3-stage cp.async, 2 CTAs/SM (32 warps/SM) ----------------
#define BKk     64
#define STG_A   (128 * BKk * 2)            // 16384
#define STG     (2 * STG_A)                // 32768
#define GSMEM   (3 * STG)                  // 98304

template <int K, class Epi>
__global__ __launch_bounds__(512, 2)
void gemm_ca(const __half* __restrict__ A, const __half* __restrict__ B, Epi epi) {
    extern __shared__ __align__(16) char sm[];
    const uint32_t smBase = smem_u32(sm);

    const int tid  = threadIdx.x;
    const int lane = tid & 31, warp = tid >> 5;      // 16 warps
    const int gid  = lane >> 2, tig = lane & 3;
    const int lrow = lane & 15, lk = lane >> 4;
    const int wm   = warp >> 2, wn = warp & 3;        // 4m x 4n, warp tile 32x32
    const int m0   = blockIdx.y << 7;
    const int n0   = blockIdx.x << 7;
    const int NT   = K / BKk;

    // cp.async: A 1024 units -> 2/thread; B 1024 units -> 2/thread
    uint32_t aOff[2], sDstA[2], bOff[2], sDstB[2];
#pragma unroll
    for (int i = 0; i < 2; i++) {
        int u = tid * 2 + i, r = u >> 3, c = u & 7;
        aOff[i]  = (uint32_t)(m0 + r) * (uint32_t)K + (uint32_t)(c * 8);
        sDstA[i] = (uint32_t)((r * 8 + (c ^ (r & 7))) * 16);
        bOff[i]  = (uint32_t)(n0 + r) * (uint32_t)K + (uint32_t)(c * 8);
        sDstB[i] = (uint32_t)(STG_A + (r * 8 + (c ^ (r & 7))) * 16);
    }

    int aR8[2], aSW[2], bR8[2], bSW[2];
#pragma unroll
    for (int t = 0; t < 2; t++) {
        int ra = wm * 32 + t * 16 + lrow;
        aR8[t] = ra * 8; aSW[t] = ra & 7;
        int rb = wn * 32 + t * 16 + lrow;
        bR8[t] = rb * 8; bSW[t] = rb & 7;
    }

    float acc[2][4][4];
#pragma unroll
    for (int i = 0; i < 2; i++)
#pragma unroll
        for (int j = 0; j < 4; j++)
#pragma unroll
            for (int k = 0; k < 4; k++) acc[i][j][k] = 0.f;

    auto load_tile = [&](int s, int kt) {
        uint32_t base = smBase + s * STG;
        uint32_t ko = (uint32_t)(kt * BKk);
#pragma unroll
        for (int i = 0; i < 2; i++) {
            cpasync16(base + sDstA[i], A + aOff[i] + ko);
            cpasync16(base + sDstB[i], B + bOff[i] + ko);
        }
    };

    load_tile(0, 0);
    asm volatile("cp.async.commit_group;" ::: "memory");
    load_tile(1, 1);
    asm volatile("cp.async.commit_group;" ::: "memory");

    for (int kt = 0; kt < NT; kt++) {
        const int s = kt % 3;
        asm volatile("cp.async.wait_group 1;" ::: "memory");
        __syncthreads();
        if (kt + 2 < NT) load_tile((kt + 2) % 3, kt + 2);
        asm volatile("cp.async.commit_group;" ::: "memory");

        uint32_t sA = smBase + s * STG;
        uint32_t sB = sA + STG_A;
#pragma unroll
        for (int ks = 0; ks < 4; ks++) {
            uint32_t a[2][4], b[2][4];
#pragma unroll
            for (int mt = 0; mt < 2; mt++)
                ldsm4(a[mt], sA + (uint32_t)((aR8[mt] + ((ks * 2 + lk) ^ aSW[mt])) * 16));
#pragma unroll
            for (int nt = 0; nt < 2; nt++)
                ldsm4(b[nt], sB + (uint32_t)((bR8[nt] + ((ks * 2 + lk) ^ bSW[nt])) * 16));
#pragma unroll
            for (int mt = 0; mt < 2; mt++)
#pragma unroll
                for (int n8 = 0; n8 < 4; n8++)
                    mma16(acc[mt][n8], a[mt], b[n8 >> 1][n8 & 1], b[n8 >> 1][(n8 & 1) + 2]);
        }
    }

    // epilogue
#pragma unroll
    for (int mt = 0; mt < 2; mt++)
#pragma unroll
        for (int n8 = 0; n8 < 4; n8++) {
            int r = m0 + wm * 32 + mt * 16 + gid;
            int c = n0 + wn * 32 + n8 * 8 + tig * 2;
            epi(r,     c, acc[mt][n8][0], acc[mt][n8][1]);
            epi(r + 8, c, acc[mt][n8][2], acc[mt][n8][3]);
        }
}

// ---------------- batched fp32 -> fp16 convert (3 segments) ----------------
struct CvtSeg { const float* src; __half* dst; int n4; };

__global__ __launch_bounds__(256)
void cvt_batch3(CvtSeg s0, CvtSeg s1, CvtSeg s2, int c0, int c1) {
    int blk = blockIdx.x;
    CvtSeg s;
    int base;
    if      (blk < c0) { s = s0; base = blk; }
    else if (blk < c1) { s = s1; base = blk - c0; }
    else               { s = s2; base = blk - c1; }
    int i = base * 256 + threadIdx.x;
    if (i < s.n4) {
        float4 v = ((const float4*)s.src)[i];
        uint2 u;
        u.x = packh2(v.x, v.y);
        u.y = packh2(v.z, v.w);
        ((uint2*)s.dst)[i] = u;
    }
}

// ---------------- CPB MLP ----------------
__global__ __launch_bounds__(512) void cpb_kernel(const float* __restrict__ ct,
                                                  const float* __restrict__ w1,
                                                  const float* __restrict__ b1,
                                                  const float* __restrict__ w2) {
    __shared__ float hid[512];
    int p = blockIdx.x;
    float c0 = ct[p * 2 + 0], c1 = ct[p * 2 + 1];
    int t = threadIdx.x;
    hid[t] = fmaxf(c0 * w1[t * 2 + 0] + c1 * w1[t * 2 + 1] + b1[t], 0.f);
    __syncthreads();
    int lane = t & 31, h = t >> 5;
    float s = 0.f;
    for (int k = lane; k < 512; k += 32) s += w2[h * 512 + k] * hid[k];
#pragma unroll
    for (int o = 16; o; o >>= 1) s += __shfl_xor_sync(0xffffffffu, s, o);
    if (lane == 0) g_tbl[p * 16 + h] = 16.0f / (1.0f + __expf(-s));
}

// ---------------- combined bias+mask table ----------------
__global__ __launch_bounds__(256)
void cmb_kernel(const int* __restrict__ rpi, const float* __restrict__ am) {
    int wh = blockIdx.x;
    int w = wh >> 4, h = wh & 15;
#pragma unroll
    for (int e = 0; e < 16; e++) {
        int ij = threadIdx.x + e * 256;
        g_cmb[((size_t)wh << 12) + ij] = g_tbl[rpi[ij] * 16 + h] + am[(size_t)w * 4096 + ij];
    }
}

// ---------------- attention ----------------
__global__ __launch_bounds__(128)
void attn_mma(const __half* __restrict__ qkv, const float* __restrict__ ls,
              __half* __restrict__ outp) {
    __shared__ __align__(16) __half sQ[64][40];
    __shared__ __align__(16) __half sK[64][40];
    __shared__ __align__(16) __half sV[64][40];
    __shared__ float sRq[64];
    __shared__ float sRk[64];

    const int bw = blockIdx.x, h = blockIdx.y;
    const int tid = threadIdx.x;
    const int lane = tid & 31, warp = tid >> 5;
    const int gid = lane >> 2, tig = lane & 3;
    const int lrow = lane & 15, lk = lane >> 4;

#pragma unroll
    for (int i = 0; i < 2; i++) {
        int u = tid * 2 + i;
        int r = u >> 2, c = u & 3;
        int g = win2glob(bw * 64 + r);
        const __half* src = qkv + (size_t)g * 1536 + h * 32 + c * 8;
        *(uint4*)&sQ[r][c * 8] = *(const uint4*)(src);
        *(uint4*)&sK[r][c * 8] = *(const uint4*)(src + 512);
        *(uint4*)&sV[r][c * 8] = *(const uint4*)(src + 1024);
    }
    __syncthreads();

    const float scale = __expf(fminf(ls[h], 4.6051701859880914f));

    {
        int r = tid >> 1, seg = (tid & 1) * 16;
        float sq = 0.f, sk = 0.f;
#pragma unroll
        for (int d = 0; d < 16; d++) {
            float qv = __half2float(sQ[r][seg + d]);
            float kv = __half2float(sK[r][seg + d]);
            sq += qv * qv;
            sk += kv * kv;
        }
        sq += __shfl_xor_sync(0xffffffffu, sq, 1);
        sk += __shfl_xor_sync(0xffffffffu, sk, 1);
        if ((tid & 1) == 0) {
            sRq[r] = scale / fmaxf(sqrtf(sq), 1e-12f);
            sRk[r] = 1.0f  / fmaxf(sqrtf(sk), 1e-12f);
        }
    }
    __syncthreads();

    const uint32_t qB = smem_u32(&sQ[0][0]);
    const uint32_t kB = smem_u32(&sK[0][0]);
    const uint32_t vB = smem_u32(&sV[0][0]);

    float accS[8][4];
#pragma unroll
    for (int j = 0; j < 8; j++)
#pragma unroll
        for (int k = 0; k < 4; k++) accS[j][k] = 0.f;

#pragma unroll
    for (int ks = 0; ks < 2; ks++) {
        uint32_t a[4], b[4][4];
        ldsm4(a, qB + (uint32_t)(((warp * 16 + lrow) * 40 + ks * 16 + lk * 8) * 2));
#pragma unroll
        for (int nt = 0; nt < 4; nt++)
            ldsm4(b[nt], kB + (uint32_t)(((nt * 16 + lrow) * 40 + ks * 16 + lk * 8) * 2));
#pragma unroll
        for (int n8 = 0; n8 < 8; n8++)
            mma16(accS[n8], a, b[n8 >> 1][n8 & 1], b[n8 >> 1][(n8 & 1) + 2]);
    }

    const int w = bw & 63;
    const float* cmbF = g_cmb + (((size_t)w * 16 + h) << 12);
    const int i0 = warp * 16 + gid;
    const float rq0 = sRq[i0], rq1 = sRq[i0 + 8];
#pragma unroll
    for (int n8 = 0; n8 < 8; n8++) {
        int j = n8 * 8 + tig * 2;
        float rk0 = sRk[j], rk1 = sRk[j + 1];
        float2 b0 = *(const float2*)(cmbF + i0 * 64 + j);
        float2 b1 = *(const float2*)(cmbF + (i0 + 8) * 64 + j);
        accS[n8][0] = accS[n8][0] * rq0 * rk0 + b0.x;
        accS[n8][1] = accS[n8][1] * rq0 * rk1 + b0.y;
        accS[n8][2] = accS[n8][2] * rq1 * rk0 + b1.x;
        accS[n8][3] = accS[n8][3] * rq1 * rk1 + b1.y;
    }

    float m0 = -1e30f, m1 = -1e30f;
#pragma unroll
    for (int n8 = 0; n8 < 8; n8++) {
        m0 = fmaxf(m0, fmaxf(accS[n8][0], accS[n8][1]));
        m1 = fmaxf(m1, fmaxf(accS[n8][2], accS[n8][3]));
    }
    m0 = fmaxf(m0, __shfl_xor_sync(0xffffffffu, m0, 1));
    m0 = fmaxf(m0, __shfl_xor_sync(0xffffffffu, m0, 2));
    m1 = fmaxf(m1, __shfl_xor_sync(0xffffffffu, m1, 1));
    m1 = fmaxf(m1, __shfl_xor_sync(0xffffffffu, m1, 2));
    float s0 = 0.f, s1 = 0.f;
#pragma unroll
    for (int n8 = 0; n8 < 8; n8++) {
        accS[n8][0] = __expf(accS[n8][0] - m0); s0 += accS[n8][0];
        accS[n8][1] = __expf(accS[n8][1] - m0); s0 += accS[n8][1];
        accS[n8][2] = __expf(accS[n8][2] - m1); s1 += accS[n8][2];
        accS[n8][3] = __expf(accS[n8][3] - m1); s1 += accS[n8][3];
    }
    s0 += __shfl_xor_sync(0xffffffffu, s0, 1);
    s0 += __shfl_xor_sync(0xffffffffu, s0, 2);
    s1 += __shfl_xor_sync(0xffffffffu, s1, 1);
    s1 += __shfl_xor_sync(0xffffffffu, s1, 2);
    float r0 = 1.0f / s0, r1 = 1.0f / s1;

    uint32_t pk0[8], pk1[8];
#pragma unroll
    for (int n8 = 0; n8 < 8; n8++) {
        pk0[n8] = packh2(accS[n8][0] * r0, accS[n8][1] * r0);
        pk1[n8] = packh2(accS[n8][2] * r1, accS[n8][3] * r1);
    }

    float accO[4][4];
#pragma unroll
    for (int j = 0; j < 4; j++)
#pragma unroll
        for (int k = 0; k < 4; k++) accO[j][k] = 0.f;

#pragma unroll
    for (int kb = 0; kb < 4; kb++) {
        uint32_t aP[4] = { pk0[2 * kb], pk1[2 * kb], pk0[2 * kb + 1], pk1[2 * kb + 1] };
#pragma unroll
        for (int dt = 0; dt < 2; dt++) {
            uint32_t vb[4];
            int vr = kb * 16 + ((lane >> 4) << 3) + (lane & 7);
            int vc = dt * 16 + ((lane >> 3) & 1) * 8;
            ldsm4t(vb, vB + (uint32_t)((vr * 40 + vc) * 2));
            mma16(accO[2 * dt],     aP, vb[0], vb[2]);
            mma16(accO[2 * dt + 1], aP, vb[1], vb[3]);
        }
    }

#pragma unroll
    for (int n8 = 0; n8 < 4; n8++) {
        int d = n8 * 8 + tig * 2;
        size_t o0 = (size_t)(bw * 64 + i0) * 512 + h * 32 + d;
        __half2 h0 = __floats2half2_rn(accO[n8][0], accO[n8][1]);
        __half2 h1 = __floats2half2_rn(accO[n8][2], accO[n8][3]);
        *(__half2*)(outp + o0)            = h0;
        *(__half2*)(outp + o0 + 8 * 512)  = h1;
    }
}

// ---------------- LayerNorm: warp-per-token ----------------
__global__ __launch_bounds__(256)
void ln1_kernel(const float4* __restrict__ proj, const float4* __restrict__ x,
                const float4* __restrict__ gma, const float4* __restrict__ bta,
                float4* __restrict__ x1o, uint2* __restrict__ x1h) {
    const int m = blockIdx.x * 8 + (threadIdx.x >> 5);
    const int lane = threadIdx.x & 31;
    const size_t pb = (size_t)m * 128 + lane;

    float4 v[4];
    float sum = 0.f;
#pragma unroll
    for (int j = 0; j < 4; j++) {
        v[j] = proj[pb + j * 32];
        sum += (v[j].x + v[j].y) + (v[j].z + v[j].w);
    }
#pragma unroll
    for (int o = 16; o; o >>= 1) sum += __shfl_xor_sync(0xffffffffu, sum, o);
    const float mean = sum * (1.0f / 512.0f);

    float vs = 0.f;
#pragma unroll
    for (int j = 0; j < 4; j++) {
        v[j].x -= mean; v[j].y -= mean; v[j].z -= mean; v[j].w -= mean;
        vs += (v[j].x * v[j].x + v[j].y * v[j].y) + (v[j].z * v[j].z + v[j].w * v[j].w);
    }
#pragma unroll
    for (int o = 16; o; o >>= 1) vs += __shfl_xor_sync(0xffffffffu, vs, o);
    const float inv = rsqrtf(vs * (1.0f / 512.0f) + 1e-5f);

    const int g = win2glob(m);
    const size_t gb = (size_t)g * 128 + lane;
#pragma unroll
    for (int j = 0; j < 4; j++) {
        float4 xm = x[gb + j * 32];
        float4 gm = gma[lane + j * 32];
        float4 bt = bta[lane + j * 32];
        float4 r;
        r.x = xm.x + v[j].x * inv * gm.x + bt.x;
        r.y = xm.y + v[j].y * inv * gm.y + bt.y;
        r.z = xm.z + v[j].z * inv * gm.z + bt.z;
        r.w = xm.w + v[j].w * inv * gm.w + bt.w;
        x1o[gb + j * 32] = r;
        uint2 u; u.x = packh2(r.x, r.y); u.y = packh2(r.z, r.w);
        x1h[gb + j * 32] = u;
    }
}

__global__ __launch_bounds__(256)
void ln2_kernel(const float4* __restrict__ mlp, const float4* __restrict__ x1,
                const float4* __restrict__ gma, const float4* __restrict__ bta,
                float4* __restrict__ outp) {
    const int m = blockIdx.x * 8 + (threadIdx.x >> 5);
    const int lane = threadIdx.x & 31;
    const size_t pb = (size_t)m * 128 + lane;

    float4 v[4];
    float sum = 0.f;
#pragma unroll
    for (int j = 0; j < 4; j++) {
        v[j] = mlp[pb + j * 32];
        sum += (v[j].x + v[j].y) + (v[j].z + v[j].w);
    }
#pragma unroll
    for (int o = 16; o; o >>= 1) sum += __shfl_xor_sync(0xffffffffu, sum, o);
    const float mean = sum * (1.0f / 512.0f);

    float vs = 0.f;
#pragma unroll
    for (int j = 0; j < 4; j++) {
        v[j].x -= mean; v[j].y -= mean; v[j].z -= mean; v[j].w -= mean;
        vs += (v[j].x * v[j].x + v[j].y * v[j].y) + (v[j].z * v[j].z + v[j].w * v[j].w);
    }
#pragma unroll
    for (int o = 16; o; o >>= 1) vs += __shfl_xor_sync(0xffffffffu, vs, o);
    const float inv = rsqrtf(vs * (1.0f / 512.0f) + 1e-5f);

#pragma unroll
    for (int j = 0; j < 4; j++) {
        float4 xm = x1[pb + j * 32];
        float4 gm = gma[lane + j * 32];
        float4 bt = bta[lane + j * 32];
        float4 r;
        r.x = xm.x + v[j].x * inv * gm.x + bt.x;
        r.y = xm.y + v[j].y * inv * gm.y + bt.y;
        r.z = xm.z + v[j].z * inv * gm.z + bt.z;
        r.w = xm.w + v[j].w * inv * gm.w + bt.w;
        outp[pb + j * 32] = r;
    }
}

// ---------------- host launcher ----------------
extern "C" void kernel_launch(void* const* d_in, const int* in_sizes, int n_in,
                              void* d_out, int out_size) {
    (void)in_sizes; (void)n_in; (void)out_size;
    const float* x      = (const float*)d_in[0];
    const float* qkv_w  = (const float*)d_in[1];
    const float* q_bias = (const float*)d_in[2];
    const float* v_bias = (const float*)d_in[3];
    const float* lscale = (const float*)d_in[4];
    const float* cpb_w1 = (const float*)d_in[5];
    const float* cpb_b1 = (const float*)d_in[6];
    const float* cpb_w2 = (const float*)d_in[7];
    const float* proj_w = (const float*)d_in[8];
    const float* proj_b = (const float*)d_in[9];
    const float* n1g    = (const float*)d_in[10];
    const float* n1b    = (const float*)d_in[11];
    const float* n2g    = (const float*)d_in[12];
    const float* n2b    = (const float*)d_in[13];
    const float* fc1_w  = (const float*)d_in[14];
    const float* fc1_b  = (const float*)d_in[15];
    const float* fc2_w  = (const float*)d_in[16];
    const float* fc2_b  = (const float*)d_in[17];
    const float* coords = (const float*)d_in[18];
    const float* amask  = (const float*)d_in[19];
    const int*   rpi    = (const int*)d_in[20];
    float*       out    = (float*)d_out;

    float  *p_proj, *p_x1, *p_mlp;
    __half *p_qkv, *p_xh, *p_attnh, *p_x1h, *p_hid, *p_wqkv, *p_wproj, *p_wfc1, *p_wfc2;
    cudaGetSymbolAddress((void**)&p_qkv,   g_qkvh);
    cudaGetSymbolAddress((void**)&p_proj,  g_proj);
    cudaGetSymbolAddress((void**)&p_x1,    g_x1);
    cudaGetSymbolAddress((void**)&p_mlp,   g_mlp);
    cudaGetSymbolAddress((void**)&p_xh,    g_xh);
    cudaGetSymbolAddress((void**)&p_attnh, g_attnh);
    cudaGetSymbolAddress((void**)&p_x1h,   g_x1h);
    cudaGetSymbolAddress((void**)&p_hid,   g_hid);
    cudaGetSymbolAddress((void**)&p_wqkv,  g_wqkv);
    cudaGetSymbolAddress((void**)&p_wproj, g_wproj);
    cudaGetSymbolAddress((void**)&p_wfc1,  g_wfc1);
    cudaGetSymbolAddress((void**)&p_wfc2,  g_wfc2);

    cudaFuncSetAttribute(gemm_ca<512,  EpiQKVh>, cudaFuncAttributeMaxDynamicSharedMemorySize, GSMEM);
    cudaFuncSetAttribute(gemm_ca<512,  EpiBias>, cudaFuncAttributeMaxDynamicSharedMemorySize, GSMEM);
    cudaFuncSetAttribute(gemm_ca<512,  EpiGelu>, cudaFuncAttributeMaxDynamicSharedMemorySize, GSMEM);
    cudaFuncSetAttribute(gemm_ca<2048, EpiBias>, cudaFuncAttributeMaxDynamicSharedMemorySize, GSMEM);

    static cudaStream_t sA = nullptr, sB = nullptr;
    static cudaEvent_t  ev0 = nullptr, evA = nullptr, evB = nullptr;
    if (!sA) {
        cudaStreamCreateWithFlags(&sA, cudaStreamNonBlocking);
        cudaStreamCreateWithFlags(&sB, cudaStreamNonBlocking);
        cudaEventCreateWithFlags(&ev0, cudaEventDisableTiming);
        cudaEventCreateWithFlags(&evA, cudaEventDisableTiming);
        cudaEventCreateWithFlags(&evB, cudaEventDisableTiming);
    }
    const cudaStream_t s0 = (cudaStream_t)0;

    const int n4_x    = Tt * 512 / 4;
    const int n4_qkvw = 1536 * 512 / 4;
    const int n4_proj = 512 * 512 / 4;
    const int n4_fc1  = 2048 * 512 / 4;
    const int n4_fc2  = 512 * 2048 / 4;
    const int m0b = (n4_x + 255) / 256;
    const int m1b = m0b + (n4_qkvw + 255) / 256;
    const int w0b = (n4_proj + 255) / 256;
    const int w1b = w0b + (n4_fc1 + 255) / 256;
    const int w2b = w1b + (n4_fc2 + 255) / 256;

    cudaEventRecord(ev0, s0);
    cudaStreamWaitEvent(sA, ev0, 0);
    cudaStreamWaitEvent(sB, ev0, 0);

    cvt_batch3<<<w2b, 256, 0, sA>>>(
        CvtSeg{proj_w, p_wproj, n4_proj}, CvtSeg{fc1_w, p_wfc1, n4_fc1},
        CvtSeg{fc2_w, p_wfc2, n4_fc2}, w0b, w1b);
    cudaEventRecord(evA, sA);

    cpb_kernel<<<225, 512, 0, sB>>>(coords, cpb_w1, cpb_b1, cpb_w2);
    cmb_kernel<<<1024, 256, 0, sB>>>(rpi, amask);
    cudaEventRecord(evB, sB);

    cvt_batch3<<<m1b, 256>>>(
        CvtSeg{x, p_xh, n4_x}, CvtSeg{qkv_w, p_wqkv, n4_qkvw},
        CvtSeg{nullptr, nullptr, 0}, m0b, m1b);
    gemm_ca<512><<<dim3(12, 512), 512, GSMEM>>>(p_xh, p_wqkv, EpiQKVh{p_qkv, q_bias, v_bias});

    cudaStreamWaitEvent(s0, evB, 0);
    attn_mma<<<dim3(1024, 16), 128>>>(p_qkv, lscale, p_attnh);

    cudaStreamWaitEvent(s0, evA, 0);
    gemm_ca<512><<<dim3(4, 512), 512, GSMEM>>>(p_attnh, p_wproj, EpiBias{p_proj, proj_b, 512});
    ln1_kernel<<<Tt / 8, 256>>>((const float4*)p_proj, (const float4*)x,
                                (const float4*)n1g, (const float4*)n1b,
                                (float4*)p_x1, (uint2*)p_x1h);
    gemm_ca<512><<<dim3(16, 512), 512, GSMEM>>>(p_x1h, p_wfc1, EpiGelu{p_hid, fc1_b});
    gemm_ca<2048><<<dim3(4, 512), 512, GSMEM>>>(p_hid, p_wfc2, EpiBias{p_mlp, fc2_b, 512});
    ln2_kernel<<<Tt / 8, 256>>>((const float4*)p_mlp, (const float4*)p_x1,
                                (const float4*)n2g, (const float4*)n2b,
                                (float4*)out);
}

// round 17
// speedup vs baseline: 1.2060x; 1.0035x over previous
#include <cuda_runtime.h>
#include <cuda_fp16.h>
#include <cstdint>
#include <math.h>

// ---------------- problem constants ----------------
#define BSZ   16
#define Hh    64
#define Ww    64
#define Cc    512
#define HEADS 16
#define WS    8
#define SHIFT 4
#define Ll    (Hh*Ww)
#define Tt    (BSZ*Ll)     // 65536 tokens
#define HID   2048

// ---------------- scratch (device globals) ----------------
__device__ __half g_qkvh [(size_t)Tt * 1536]; // fp16, WINDOW order
__device__ __half g_xh   [(size_t)Tt * Cc];   // global order
__device__ __half g_attnh[(size_t)Tt * Cc];   // window order
__device__ __half g_projh[(size_t)Tt * Cc];   // window order (fp16)
__device__ float  g_x1   [(size_t)Tt * Cc];   // global order
__device__ __half g_x1h  [(size_t)Tt * Cc];
__device__ __half g_hid  [(size_t)Tt * HID];
__device__ float  g_mlp  [(size_t)Tt * Cc];
__device__ float  g_tbl  [225 * HEADS];
__device__ float  g_cmb  [64 * 16 * 4096];
__device__ __half g_wqkv [1536 * 512];
__device__ __half g_wproj[512 * 512];
__device__ __half g_wfc1 [2048 * 512];
__device__ __half g_wfc2 [512 * 2048];

// ---------------- helpers ----------------
__device__ __forceinline__ void mma16(float* d, const uint32_t* a, uint32_t b0, uint32_t b1) {
    asm volatile(
        "mma.sync.aligned.m16n8k16.row.col.f32.f16.f16.f32 "
        "{%0,%1,%2,%3}, {%4,%5,%6,%7}, {%8,%9}, {%0,%1,%2,%3};\n"
        : "+f"(d[0]), "+f"(d[1]), "+f"(d[2]), "+f"(d[3])
        : "r"(a[0]), "r"(a[1]), "r"(a[2]), "r"(a[3]), "r"(b0), "r"(b1));
}
__device__ __forceinline__ void ldsm4(uint32_t* r, uint32_t addr) {
    asm volatile("ldmatrix.sync.aligned.m8n8.x4.shared.b16 {%0,%1,%2,%3}, [%4];"
                 : "=r"(r[0]), "=r"(r[1]), "=r"(r[2]), "=r"(r[3]) : "r"(addr));
}
__device__ __forceinline__ void ldsm4t(uint32_t* r, uint32_t addr) {
    asm volatile("ldmatrix.sync.aligned.m8n8.x4.trans.shared.b16 {%0,%1,%2,%3}, [%4];"
                 : "=r"(r[0]), "=r"(r[1]), "=r"(r[2]), "=r"(r[3]) : "r"(addr));
}
__device__ __forceinline__ void cpasync16(uint32_t dst, const void* src) {
    asm volatile("cp.async.cg.shared.global [%0], [%1], 16;" :: "r"(dst), "l"(src) : "memory");
}
__device__ __forceinline__ uint32_t smem_u32(const void* p) {
    uint32_t a;
    asm("{ .reg .u64 t; cvta.to.shared.u64 t, %1; cvt.u32.u64 %0, t; }" : "=r"(a) : "l"(p));
    return a;
}
__device__ __forceinline__ uint32_t packh2(float a, float b) {
    __half2 h = __floats2half2_rn(a, b);
    return *(uint32_t*)&h;
}

__device__ __forceinline__ int win2glob(int m) {
    int bw = m >> 6, n = m & 63;
    int b = bw >> 6, w = bw & 63;
    int y = (((w >> 3) << 3) + (n >> 3) + SHIFT) & 63;
    int x = (((w & 7) << 3) + (n & 7) + SHIFT) & 63;
    return (b << 12) | (y << 6) | x;
}

// ---------------- epilogue functors ----------------
struct EpiQKVh {
    __half* out; const float* qb; const float* vb;
    __device__ __forceinline__ void operator()(int m, int c, float v0, float v1) const {
        if (c < 512)       { v0 += qb[c]; v1 += qb[c + 1]; }
        else if (c >= 1024){ v0 += vb[c - 1024]; v1 += vb[c - 1023]; }
        *(__half2*)(out + (size_t)m * 1536 + c) = __floats2half2_rn(v0, v1);
    }
};
struct EpiBias {
    float* out; const float* b; int ldc;
    __device__ __forceinline__ void operator()(int m, int c, float v0, float v1) const {
        float2 r; r.x = v0 + b[c]; r.y = v1 + b[c + 1];
        *(float2*)(out + (size_t)m * ldc + c) = r;
    }
};
struct EpiBiasH {
    __half* out; const float* b;
    __device__ __forceinline__ void operator()(int m, int c, float v0, float v1) const {
        *(__half2*)(out + (size_t)m * 512 + c) = __floats2half2_rn(v0 + b[c], v1 + b[c + 1]);
    }
};
struct EpiGelu {
    __half* out; const float* b;
    __device__ __forceinline__ void operator()(int m, int c, float v0, float v1) const {
        v0 += b[c];     v0 = 0.5f * v0 * (1.0f + erff(v0 * 0.70710678118654752f));
        v1 += b[c + 1]; v1 = 0.5f * v1 * (1.0f + erff(v1 * 0.70710678118654752f));
        *(__half2*)(out + (size_t)m * HID + c) = __floats2half2_rn(v0, v1);
    }
};

// ---------------- fp16 mma.sync GEMM: 128x128 tile, 512 threads (16 warps 4x4,
// ---------------- warp tile 32x32), 3-stage cp.async, 2 CTAs/SM ----------------
// MAPA: A rows gathered through win2glob (window-order output from global-order A)
#define BKk     64
#define STG_A   (128 * BKk * 2)            // 16384
#define STG     (2 * STG_A)                // 32768
#define GSMEM   (3 * STG)                  // 98304

template <int K, bool MAPA, class Epi>
__global__ __launch_bounds__(512, 2)
void gemm_ca(const __half* __restrict__ A, const __half* __restrict__ B, Epi epi) {
    extern __shared__ __align__(16) char sm[];
    const uint32_t smBase = smem_u32(sm);

    const int tid  = threadIdx.x;
    const int lane = tid & 31, warp = tid >> 5;      // 16 warps
    const int gid  = lane >> 2, tig = lane & 3;
    const int lrow = lane & 15, lk = lane >> 4;
    const int wm   = warp >> 2, wn = warp & 3;        // 4m x 4n, warp tile 32x32
    const int m0   = blockIdx.y << 7;
    const int n0   = blockIdx.x << 7;
    const int NT   = K / BKk;

    uint32_t aOff[2], sDstA[2], bOff[2], sDstB[2];
#pragma unroll
    for (int i = 0; i < 2; i++) {
        int u = tid * 2 + i, r = u >> 3, c = u & 7;
        int ar = MAPA ? win2glob(m0 + r) : (m0 + r);
        aOff[i]  = (uint32_t)ar * (uint32_t)K + (uint32_t)(c * 8);
        sDstA[i] = (uint32_t)((r * 8 + (c ^ (r & 7))) * 16);
        bOff[i]  = (uint32_t)(n0 + r) * (uint32_t)K + (uint32_t)(c * 8);
        sDstB[i] = (uint32_t)(STG_A + (r * 8 + (c ^ (r & 7))) * 16);
    }

    int aR8[2], aSW[2], bR8[2], bSW[2];
#pragma unroll
    for (int t = 0; t < 2; t++) {
        int ra = wm * 32 + t * 16 + lrow;
        aR8[t] = ra * 8; aSW[t] = ra & 7;
        int rb = wn * 32 + t * 16 + lrow;
        bR8[t] = rb * 8; bSW[t] = rb & 7;
    }

    float acc[2][4][4];
#pragma unroll
    for (int i = 0; i < 2; i++)
#pragma unroll
        for (int j = 0; j < 4; j++)
#pragma unroll
            for (int k = 0; k < 4; k++) acc[i][j][k] = 0.f;

    auto load_tile = [&](int s, int kt) {
        uint32_t base = smBase + s * STG;
        uint32_t ko = (uint32_t)(kt * BKk);
#pragma unroll
        for (int i = 0; i < 2; i++) {
            cpasync16(base + sDstA[i], A + aOff[i] + ko);
            cpasync16(base + sDstB[i], B + bOff[i] + ko);
        }
    };

    load_tile(0, 0);
    asm volatile("cp.async.commit_group;" ::: "memory");
    load_tile(1, 1);
    asm volatile("cp.async.commit_group;" ::: "memory");

    for (int kt = 0; kt < NT; kt++) {
        const int s = kt % 3;
        asm volatile("cp.async.wait_group 1;" ::: "memory");
        __syncthreads();
        if (kt + 2 < NT) load_tile((kt + 2) % 3, kt + 2);
        asm volatile("cp.async.commit_group;" ::: "memory");

        uint32_t sA = smBase + s * STG;
        uint32_t sB = sA + STG_A;
#pragma unroll
        for (int ks = 0; ks < 4; ks++) {
            uint32_t a[2][4], b[2][4];
#pragma unroll
            for (int mt = 0; mt < 2; mt++)
                ldsm4(a[mt], sA + (uint32_t)((aR8[mt] + ((ks * 2 + lk) ^ aSW[mt])) * 16));
#pragma unroll
            for (int nt = 0; nt < 2; nt++)
                ldsm4(b[nt], sB + (uint32_t)((bR8[nt] + ((ks * 2 + lk) ^ bSW[nt])) * 16));
#pragma unroll
            for (int mt = 0; mt < 2; mt++)
#pragma unroll
                for (int n8 = 0; n8 < 4; n8++)
                    mma16(acc[mt][n8], a[mt], b[n8 >> 1][n8 & 1], b[n8 >> 1][(n8 & 1) + 2]);
        }
    }

#pragma unroll
    for (int mt = 0; mt < 2; mt++)
#pragma unroll
        for (int n8 = 0; n8 < 4; n8++) {
            int r = m0 + wm * 32 + mt * 16 + gid;
            int c = n0 + wn * 32 + n8 * 8 + tig * 2;
            epi(r,     c, acc[mt][n8][0], acc[mt][n8][1]);
            epi(r + 8, c, acc[mt][n8][2], acc[mt][n8][3]);
        }
}

// ---------------- batched fp32 -> fp16 convert (3 segments) ----------------
struct CvtSeg { const float* src; __half* dst; int n4; };

__global__ __launch_bounds__(256)
void cvt_batch3(CvtSeg s0, CvtSeg s1, CvtSeg s2, int c0, int c1) {
    int blk = blockIdx.x;
    CvtSeg s;
    int base;
    if      (blk < c0) { s = s0; base = blk; }
    else if (blk < c1) { s = s1; base = blk - c0; }
    else               { s = s2; base = blk - c1; }
    int i = base * 256 + threadIdx.x;
    if (i < s.n4) {
        float4 v = ((const float4*)s.src)[i];
        uint2 u;
        u.x = packh2(v.x, v.y);
        u.y = packh2(v.z, v.w);
        ((uint2*)s.dst)[i] = u;
    }
}

// ---------------- CPB MLP ----------------
__global__ __launch_bounds__(512) void cpb_kernel(const float* __restrict__ ct,
                                                  const float* __restrict__ w1,
                                                  const float* __restrict__ b1,
                                                  const float* __restrict__ w2) {
    __shared__ float hid[512];
    int p = blockIdx.x;
    float c0 = ct[p * 2 + 0], c1 = ct[p * 2 + 1];
    int t = threadIdx.x;
    hid[t] = fmaxf(c0 * w1[t * 2 + 0] + c1 * w1[t * 2 + 1] + b1[t], 0.f);
    __syncthreads();
    int lane = t & 31, h = t >> 5;
    float s = 0.f;
    for (int k = lane; k < 512; k += 32) s += w2[h * 512 + k] * hid[k];
#pragma unroll
    for (int o = 16; o; o >>= 1) s += __shfl_xor_sync(0xffffffffu, s, o);
    if (lane == 0) g_tbl[p * 16 + h] = 16.0f / (1.0f + __expf(-s));
}

// ---------------- combined bias+mask table ----------------
__global__ __launch_bounds__(256)
void cmb_kernel(const int* __restrict__ rpi, const float* __restrict__ am) {
    int wh = blockIdx.x;
    int w = wh >> 4, h = wh & 15;
#pragma unroll
    for (int e = 0; e < 16; e++) {
        int ij = threadIdx.x + e * 256;
        g_cmb[((size_t)wh << 12) + ij] = g_tbl[rpi[ij] * 16 + h] + am[(size_t)w * 4096 + ij];
    }
}

// ---------------- attention: qkv now WINDOW order -> contiguous loads ----------------
__global__ __launch_bounds__(128)
void attn_mma(const __half* __restrict__ qkv, const float* __restrict__ ls,
              __half* __restrict__ outp) {
    __shared__ __align__(16) __half sQ[64][40];
    __shared__ __align__(16) __half sK[64][40];
    __shared__ __align__(16) __half sV[64][40];
    __shared__ float sRq[64];
    __shared__ float sRk[64];

    const int bw = blockIdx.x, h = blockIdx.y;
    const int tid = threadIdx.x;
    const int lane = tid & 31, warp = tid >> 5;
    const int gid = lane >> 2, tig = lane & 3;
    const int lrow = lane & 15, lk = lane >> 4;

#pragma unroll
    for (int i = 0; i < 2; i++) {
        int u = tid * 2 + i;
        int r = u >> 2, c = u & 3;
        const __half* src = qkv + (size_t)(bw * 64 + r) * 1536 + h * 32 + c * 8;
        *(uint4*)&sQ[r][c * 8] = *(const uint4*)(src);
        *(uint4*)&sK[r][c * 8] = *(const uint4*)(src + 512);
        *(uint4*)&sV[r][c * 8] = *(const uint4*)(src + 1024);
    }
    __syncthreads();

    const float scale = __expf(fminf(ls[h], 4.6051701859880914f));

    {
        int r = tid >> 1, seg = (tid & 1) * 16;
        float sq = 0.f, sk = 0.f;
#pragma unroll
        for (int d = 0; d < 16; d++) {
            float qv = __half2float(sQ[r][seg + d]);
            float kv = __half2float(sK[r][seg + d]);
            sq += qv * qv;
            sk += kv * kv;
        }
        sq += __shfl_xor_sync(0xffffffffu, sq, 1);
        sk += __shfl_xor_sync(0xffffffffu, sk, 1);
        if ((tid & 1) == 0) {
            sRq[r] = scale / fmaxf(sqrtf(sq), 1e-12f);
            sRk[r] = 1.0f  / fmaxf(sqrtf(sk), 1e-12f);
        }
    }
    __syncthreads();

    const uint32_t qB = smem_u32(&sQ[0][0]);
    const uint32_t kB = smem_u32(&sK[0][0]);
    const uint32_t vB = smem_u32(&sV[0][0]);

    float accS[8][4];
#pragma unroll
    for (int j = 0; j < 8; j++)
#pragma unroll
        for (int k = 0; k < 4; k++) accS[j][k] = 0.f;

#pragma unroll
    for (int ks = 0; ks < 2; ks++) {
        uint32_t a[4], b[4][4];
        ldsm4(a, qB + (uint32_t)(((warp * 16 + lrow) * 40 + ks * 16 + lk * 8) * 2));
#pragma unroll
        for (int nt = 0; nt < 4; nt++)
            ldsm4(b[nt], kB + (uint32_t)(((nt * 16 + lrow) * 40 + ks * 16 + lk * 8) * 2));
#pragma unroll
        for (int n8 = 0; n8 < 8; n8++)
            mma16(accS[n8], a, b[n8 >> 1][n8 & 1], b[n8 >> 1][(n8 & 1) + 2]);
    }

    const int w = bw & 63;
    const float* cmbF = g_cmb + (((size_t)w * 16 + h) << 12);
    const int i0 = warp * 16 + gid;
    const float rq0 = sRq[i0], rq1 = sRq[i0 + 8];
#pragma unroll
    for (int n8 = 0; n8 < 8; n8++) {
        int j = n8 * 8 + tig * 2;
        float rk0 = sRk[j], rk1 = sRk[j + 1];
        float2 b0 = *(const float2*)(cmbF + i0 * 64 + j);
        float2 b1 = *(const float2*)(cmbF + (i0 + 8) * 64 + j);
        accS[n8][0] = accS[n8][0] * rq0 * rk0 + b0.x;
        accS[n8][1] = accS[n8][1] * rq0 * rk1 + b0.y;
        accS[n8][2] = accS[n8][2] * rq1 * rk0 + b1.x;
        accS[n8][3] = accS[n8][3] * rq1 * rk1 + b1.y;
    }

    float m0 = -1e30f, m1 = -1e30f;
#pragma unroll
    for (int n8 = 0; n8 < 8; n8++) {
        m0 = fmaxf(m0, fmaxf(accS[n8][0], accS[n8][1]));
        m1 = fmaxf(m1, fmaxf(accS[n8][2], accS[n8][3]));
    }
    m0 = fmaxf(m0, __shfl_xor_sync(0xffffffffu, m0, 1));
    m0 = fmaxf(m0, __shfl_xor_sync(0xffffffffu, m0, 2));
    m1 = fmaxf(m1, __shfl_xor_sync(0xffffffffu, m1, 1));
    m1 = fmaxf(m1, __shfl_xor_sync(0xffffffffu, m1, 2));
    float s0 = 0.f, s1 = 0.f;
#pragma unroll
    for (int n8 = 0; n8 < 8; n8++) {
        accS[n8][0] = __expf(accS[n8][0] - m0); s0 += accS[n8][0];
        accS[n8][1] = __expf(accS[n8][1] - m0); s0 += accS[n8][1];
        accS[n8][2] = __expf(accS[n8][2] - m1); s1 += accS[n8][2];
        accS[n8][3] = __expf(accS[n8][3] - m1); s1 += accS[n8][3];
    }
    s0 += __shfl_xor_sync(0xffffffffu, s0, 1);
    s0 += __shfl_xor_sync(0xffffffffu, s0, 2);
    s1 += __shfl_xor_sync(0xffffffffu, s1, 1);
    s1 += __shfl_xor_sync(0xffffffffu, s1, 2);
    float r0 = 1.0f / s0, r1 = 1.0f / s1;

    uint32_t pk0[8], pk1[8];
#pragma unroll
    for (int n8 = 0; n8 < 8; n8++) {
        pk0[n8] = packh2(accS[n8][0] * r0, accS[n8][1] * r0);
        pk1[n8] = packh2(accS[n8][2] * r1, accS[n8][3] * r1);
    }

    float accO[4][4];
#pragma unroll
    for (int j = 0; j < 4; j++)
#pragma unroll
        for (int k = 0; k < 4; k++) accO[j][k] = 0.f;

#pragma unroll
    for (int kb = 0; kb < 4; kb++) {
        uint32_t aP[4] = { pk0[2 * kb], pk1[2 * kb], pk0[2 * kb + 1], pk1[2 * kb + 1] };
#pragma unroll
        for (int dt = 0; dt < 2; dt++) {
            uint32_t vb[4];
            int vr = kb * 16 + ((lane >> 4) << 3) + (lane & 7);
            int vc = dt * 16 + ((lane >> 3) & 1) * 8;
            ldsm4t(vb, vB + (uint32_t)((vr * 40 + vc) * 2));
            mma16(accO[2 * dt],     aP, vb[0], vb[2]);
            mma16(accO[2 * dt + 1], aP, vb[1], vb[3]);
        }
    }

#pragma unroll
    for (int n8 = 0; n8 < 4; n8++) {
        int d = n8 * 8 + tig * 2;
        size_t o0 = (size_t)(bw * 64 + i0) * 512 + h * 32 + d;
        __half2 h0 = __floats2half2_rn(accO[n8][0], accO[n8][1]);
        __half2 h1 = __floats2half2_rn(accO[n8][2], accO[n8][3]);
        *(__half2*)(outp + o0)            = h0;
        *(__half2*)(outp + o0 + 8 * 512)  = h1;
    }
}

// ---------------- LayerNorm: warp-per-token ----------------
// LN1: proj now fp16 (window order); x fp32 global order.
__global__ __launch_bounds__(256)
void ln1_kernel(const uint2* __restrict__ projh, const float4* __restrict__ x,
                const float4* __restrict__ gma, const float4* __restrict__ bta,
                float4* __restrict__ x1o, uint2* __restrict__ x1h) {
    const int m = blockIdx.x * 8 + (threadIdx.x >> 5);
    const int lane = threadIdx.x & 31;
    const size_t pb = (size_t)m * 128 + lane;   // uint2 units (4 halves each)

    float4 v[4];
    float sum = 0.f;
#pragma unroll
    for (int j = 0; j < 4; j++) {
        uint2 u = projh[pb + j * 32];
        __half2 h01 = *(__half2*)&u.x;
        __half2 h23 = *(__half2*)&u.y;
        v[j].x = __low2float(h01); v[j].y = __high2float(h01);
        v[j].z = __low2float(h23); v[j].w = __high2float(h23);
        sum += (v[j].x + v[j].y) + (v[j].z + v[j].w);
    }
#pragma unroll
    for (int o = 16; o; o >>= 1) sum += __shfl_xor_sync(0xffffffffu, sum, o);
    const float mean = sum * (1.0f / 512.0f);

    float vs = 0.f;
#pragma unroll
    for (int j = 0; j < 4; j++) {
        v[j].x -= mean; v[j].y -= mean; v[j].z -= mean; v[j].w -= mean;
        vs += (v[j].x * v[j].x + v[j].y * v[j].y) + (v[j].z * v[j].z + v[j].w * v[j].w);
    }
#pragma unroll
    for (int o = 16; o; o >>= 1) vs += __shfl_xor_sync(0xffffffffu, vs, o);
    const float inv = rsqrtf(vs * (1.0f / 512.0f) + 1e-5f);

    const int g = win2glob(m);
    const size_t gb = (size_t)g * 128 + lane;
#pragma unroll
    for (int j = 0; j < 4; j++) {
        float4 xm = x[gb + j * 32];
        float4 gm = gma[lane + j * 32];
        float4 bt = bta[lane + j * 32];
        float4 r;
        r.x = xm.x + v[j].x * inv * gm.x + bt.x;
        r.y = xm.y + v[j].y * inv * gm.y + bt.y;
        r.z = xm.z + v[j].z * inv * gm.z + bt.z;
        r.w = xm.w + v[j].w * inv * gm.w + bt.w;
        x1o[gb + j * 32] = r;
        uint2 u; u.x = packh2(r.x, r.y); u.y = packh2(r.z, r.w);
        x1h[gb + j * 32] = u;
    }
}

__global__ __launch_bounds__(256)
void ln2_kernel(const float4* __restrict__ mlp, const float4* __restrict__ x1,
                const float4* __restrict__ gma, const float4* __restrict__ bta,
                float4* __restrict__ outp) {
    const int m = blockIdx.x * 8 + (threadIdx.x >> 5);
    const int lane = threadIdx.x & 31;
    const size_t pb = (size_t)m * 128 + lane;

    float4 v[4];
    float sum = 0.f;
#pragma unroll
    for (int j = 0; j < 4; j++) {
        v[j] = mlp[pb + j * 32];
        sum += (v[j].x + v[j].y) + (v[j].z + v[j].w);
    }
#pragma unroll
    for (int o = 16; o; o >>= 1) sum += __shfl_xor_sync(0xffffffffu, sum, o);
    const float mean = sum * (1.0f / 512.0f);

    float vs = 0.f;
#pragma unroll
    for (int j = 0; j < 4; j++) {
        v[j].x -= mean; v[j].y -= mean; v[j].z -= mean; v[j].w -= mean;
        vs += (v[j].x * v[j].x + v[j].y * v[j].y) + (v[j].z * v[j].z + v[j].w * v[j].w);
    }
#pragma unroll
    for (int o = 16; o; o >>= 1) vs += __shfl_xor_sync(0xffffffffu, vs, o);
    const float inv = rsqrtf(vs * (1.0f / 512.0f) + 1e-5f);

#pragma unroll
    for (int j = 0; j < 4; j++) {
        float4 xm = x1[pb + j * 32];
        float4 gm = gma[lane + j * 32];
        float4 bt = bta[lane + j * 32];
        float4 r;
        r.x = xm.x + v[j].x * inv * gm.x + bt.x;
        r.y = xm.y + v[j].y * inv * gm.y + bt.y;
        r.z = xm.z + v[j].z * inv * gm.z + bt.z;
        r.w = xm.w + v[j].w * inv * gm.w + bt.w;
        outp[pb + j * 32] = r;
    }
}

// ---------------- host launcher ----------------
extern "C" void kernel_launch(void* const* d_in, const int* in_sizes, int n_in,
                              void* d_out, int out_size) {
    (void)in_sizes; (void)n_in; (void)out_size;
    const float* x      = (const float*)d_in[0];
    const float* qkv_w  = (const float*)d_in[1];
    const float* q_bias = (const float*)d_in[2];
    const float* v_bias = (const float*)d_in[3];
    const float* lscale = (const float*)d_in[4];
    const float* cpb_w1 = (const float*)d_in[5];
    const float* cpb_b1 = (const float*)d_in[6];
    const float* cpb_w2 = (const float*)d_in[7];
    const float* proj_w = (const float*)d_in[8];
    const float* proj_b = (const float*)d_in[9];
    const float* n1g    = (const float*)d_in[10];
    const float* n1b    = (const float*)d_in[11];
    const float* n2g    = (const float*)d_in[12];
    const float* n2b    = (const float*)d_in[13];
    const float* fc1_w  = (const float*)d_in[14];
    const float* fc1_b  = (const float*)d_in[15];
    const float* fc2_w  = (const float*)d_in[16];
    const float* fc2_b  = (const float*)d_in[17];
    const float* coords = (const float*)d_in[18];
    const float* amask  = (const float*)d_in[19];
    const int*   rpi    = (const int*)d_in[20];
    float*       out    = (float*)d_out;

    float  *p_x1, *p_mlp;
    __half *p_qkv, *p_xh, *p_attnh, *p_projh, *p_x1h, *p_hid, *p_wqkv, *p_wproj, *p_wfc1, *p_wfc2;
    cudaGetSymbolAddress((void**)&p_qkv,   g_qkvh);
    cudaGetSymbolAddress((void**)&p_projh, g_projh);
    cudaGetSymbolAddress((void**)&p_x1,    g_x1);
    cudaGetSymbolAddress((void**)&p_mlp,   g_mlp);
    cudaGetSymbolAddress((void**)&p_xh,    g_xh);
    cudaGetSymbolAddress((void**)&p_attnh, g_attnh);
    cudaGetSymbolAddress((void**)&p_x1h,   g_x1h);
    cudaGetSymbolAddress((void**)&p_hid,   g_hid);
    cudaGetSymbolAddress((void**)&p_wqkv,  g_wqkv);
    cudaGetSymbolAddress((void**)&p_wproj, g_wproj);
    cudaGetSymbolAddress((void**)&p_wfc1,  g_wfc1);
    cudaGetSymbolAddress((void**)&p_wfc2,  g_wfc2);

    cudaFuncSetAttribute((void*)gemm_ca<512,  true,  EpiQKVh>, cudaFuncAttributeMaxDynamicSharedMemorySize, GSMEM);
    cudaFuncSetAttribute((void*)gemm_ca<512,  false, EpiBiasH>, cudaFuncAttributeMaxDynamicSharedMemorySize, GSMEM);
    cudaFuncSetAttribute((void*)gemm_ca<512,  false, EpiGelu>, cudaFuncAttributeMaxDynamicSharedMemorySize, GSMEM);
    cudaFuncSetAttribute((void*)gemm_ca<2048, false, EpiBias>, cudaFuncAttributeMaxDynamicSharedMemorySize, GSMEM);

    static cudaStream_t sA = nullptr, sB = nullptr;
    static cudaEvent_t  ev0 = nullptr, evA = nullptr, evB = nullptr;
    if (!sA) {
        cudaStreamCreateWithFlags(&sA, cudaStreamNonBlocking);
        cudaStreamCreateWithFlags(&sB, cudaStreamNonBlocking);
        cudaEventCreateWithFlags(&ev0, cudaEventDisableTiming);
        cudaEventCreateWithFlags(&evA, cudaEventDisableTiming);
        cudaEventCreateWithFlags(&evB, cudaEventDisableTiming);
    }
    const cudaStream_t s0 = (cudaStream_t)0;

    const int n4_x    = Tt * 512 / 4;
    const int n4_qkvw = 1536 * 512 / 4;
    const int n4_proj = 512 * 512 / 4;
    const int n4_fc1  = 2048 * 512 / 4;
    const int n4_fc2  = 512 * 2048 / 4;
    const int m0b = (n4_x + 255) / 256;
    const int m1b = m0b + (n4_qkvw + 255) / 256;
    const int w0b = (n4_proj + 255) / 256;
    const int w1b = w0b + (n4_fc1 + 255) / 256;
    const int w2b = w1b + (n4_fc2 + 255) / 256;

    cudaEventRecord(ev0, s0);
    cudaStreamWaitEvent(sA, ev0, 0);
    cudaStreamWaitEvent(sB, ev0, 0);

    cvt_batch3<<<w2b, 256, 0, sA>>>(
        CvtSeg{proj_w, p_wproj, n4_proj}, CvtSeg{fc1_w, p_wfc1, n4_fc1},
        CvtSeg{fc2_w, p_wfc2, n4_fc2}, w0b, w1b);
    cudaEventRecord(evA, sA);

    cpb_kernel<<<225, 512, 0, sB>>>(coords, cpb_w1, cpb_b1, cpb_w2);
    cmb_kernel<<<1024, 256, 0, sB>>>(rpi, amask);
    cudaEventRecord(evB, sB);

    cvt_batch3<<<m1b, 256>>>(
        CvtSeg{x, p_xh, n4_x}, CvtSeg{qkv_w, p_wqkv, n4_qkvw},
        CvtSeg{nullptr, nullptr, 0}, m0b, m1b);
    // QKV GEMM with window gather on A rows -> window-order qkv
    gemm_ca<512, true><<<dim3(12, 512), 512, GSMEM>>>(p_xh, p_wqkv, EpiQKVh{p_qkv, q_bias, v_bias});

    cudaStreamWaitEvent(s0, evB, 0);
    attn_mma<<<dim3(1024, 16), 128>>>(p_qkv, lscale, p_attnh);

    cudaStreamWaitEvent(s0, evA, 0);
    gemm_ca<512, false><<<dim3(4, 512), 512, GSMEM>>>(p_attnh, p_wproj, EpiBiasH{p_projh, proj_b});
    ln1_kernel<<<Tt / 8, 256>>>((const uint2*)p_projh, (const float4*)x,
                                (const float4*)n1g, (const float4*)n1b,
                                (float4*)p_x1, (uint2*)p_x1h);
    gemm_ca<512, false><<<dim3(16, 512), 512, GSMEM>>>(p_x1h, p_wfc1, EpiGelu{p_hid, fc1_b});
    gemm_ca<2048, false><<<dim3(4, 512), 512, GSMEM>>>(p_hid, p_wfc2, EpiBias{p_mlp, fc2_b, 512});
    ln2_kernel<<<Tt / 8, 256>>>((const float4*)p_mlp, (const float4*)p_x1,
                                (const float4*)n2g, (const float4*)n2b,
                                (float4*)out);
}